// round 5
// baseline (speedup 1.0000x reference)
#include <cuda_runtime.h>
#include <cuda_bf16.h>
#include <cstdint>

using bf16 = __nv_bfloat16;

#define Bb  2
#define Ss  2048
#define Dd  2048
#define Hh  16
#define HDd 128
#define Ff  8192
#define LCc 512
#define EPSf 1e-6f

// ---------------------------------------------------------------------------
// Scratch (__device__ globals; allocation-free rule)
// ---------------------------------------------------------------------------
__device__ float g_em [Bb * 6 * Dd];
__device__ float g_qkv [(size_t)Bb * Ss * 3 * Dd];
__device__ float g_y   [(size_t)Bb * Ss * Dd];
__device__ float g_sc  [(size_t)Bb * Hh * Ss * Ss];

#define DECL2(nm, n) __device__ __align__(128) bf16 nm##h[(size_t)(n)]; __device__ __align__(128) bf16 nm##l[(size_t)(n)];
DECL2(g_tx, (size_t)Bb*Ss*Dd)
DECL2(g_cx, (size_t)Bb*LCc*Dd)
DECL2(g_q,  (size_t)Bb*Ss*Dd)
DECL2(g_k,  (size_t)Bb*Ss*Dd)
DECL2(g_vt, (size_t)Bb*Ss*Dd)
DECL2(g_p,  (size_t)Bb*Hh*Ss*Ss)
DECL2(g_f,  (size_t)Bb*Ss*Ff)
DECL2(g_wqkv, (size_t)3*Dd*Dd)
DECL2(g_wckv, (size_t)2*Dd*Dd)
DECL2(g_wo,   (size_t)Dd*Dd)
DECL2(g_wcq,  (size_t)Dd*Dd)
DECL2(g_wco,  (size_t)Dd*Dd)
DECL2(g_wf1,  (size_t)Ff*Dd)
DECL2(g_wf2,  (size_t)Dd*Ff)

// ---------------------------------------------------------------------------
// helpers
// ---------------------------------------------------------------------------
__device__ __forceinline__ uint32_t smem_u32(const void* p) {
    uint32_t a;
    asm("{ .reg .u64 t; cvta.to.shared.u64 t, %1; cvt.u32.u64 %0, t; }" : "=r"(a) : "l"(p));
    return a;
}
#define CP_COMMIT() asm volatile("cp.async.commit_group;" ::: "memory")

#define LDSM4(d, a) \
  asm volatile("ldmatrix.sync.aligned.m8n8.x4.shared.b16 {%0,%1,%2,%3}, [%4];" \
    : "=r"((d)[0]), "=r"((d)[1]), "=r"((d)[2]), "=r"((d)[3]) : "r"(a))

#define MMA16816(c, a, b0, b1) \
  asm volatile("mma.sync.aligned.m16n8k16.row.col.f32.bf16.bf16.f32 " \
    "{%0,%1,%2,%3}, {%4,%5,%6,%7}, {%8,%9}, {%0,%1,%2,%3};" \
    : "+f"((c)[0]), "+f"((c)[1]), "+f"((c)[2]), "+f"((c)[3]) \
    : "r"((a)[0]), "r"((a)[1]), "r"((a)[2]), "r"((a)[3]), "r"(b0), "r"(b1))

__device__ __forceinline__ float gelu_t(float x) {
    float x3 = x * x * x;
    return 0.5f * x * (1.f + tanhf(0.7978845608028654f * (x + 0.044715f * x3)));
}
__device__ __forceinline__ void split2(float v, bf16& h, bf16& l) {
    h = __float2bfloat16(v);
    l = __float2bfloat16(v - __bfloat162float(h));
}
__device__ __forceinline__ __nv_bfloat162 mkbf2(bf16 a, bf16 b) {
    __nv_bfloat162 r; r.x = a; r.y = b; return r;
}
// segmented bias: segments of 2048 columns (b1/b2 null -> single segment b0)
__device__ __forceinline__ float bget(const float* b0, const float* b1,
                                      const float* b2, int c) {
    if (b1 == nullptr) return b0 ? b0[c] : 0.f;
    int seg = c >> 11, off = c & 2047;
    const float* bp = (seg == 0) ? b0 : ((seg == 1) ? b1 : b2);
    return bp[off];
}

// stage: Ah(10240) Al(10240) Bh(10240) Bl(10240); 80B row pitch, 128 rows, 32 bf16 cols
#define STAGE_BYTES 40960u
#define SMEM_TOTAL_G (4 * 40960)

// ---------------------------------------------------------------------------
// HMMA (mma.sync) GEMM: C(MxN) = A(MxK) @ B^T, B stored [N x K], bf16 hi/lo
// 3-term bf16x3 into fp32 acc. EPI: 0 fp32(+bias); 1 gelu->bf16 h/l(+bias);
// 2 xo += (acc+bias)*gate  (gateRow<0: plain add)
// ---------------------------------------------------------------------------
template <int EPI>
__global__ __launch_bounds__(256, 1)
void mma_gemm(const bf16* __restrict__ Ah, const bf16* __restrict__ Al,
              const bf16* __restrict__ Bh, const bf16* __restrict__ Bl,
              int K, int lda, int ldb,
              float* C, bf16* Ch, bf16* Cl, int ldc,
              const float* __restrict__ bias0, const float* __restrict__ bias1,
              const float* __restrict__ bias2,
              const float* __restrict__ em, int gateRow,
              int Hdiv,
              long long sAb, long long sAh_, long long sBb, long long sBh_,
              long long sCb, long long sCh_)
{
    extern __shared__ __align__(128) char smem[];
    const uint32_t sbase = smem_u32(smem);
    const int tid = threadIdx.x;
    const int w = tid >> 5, l = tid & 31;
    const int wm = w >> 2, wn = w & 3;          // 2 x 4 warp grid, warp tile 64x32

    const int z = blockIdx.z;
    const int zb = z / Hdiv, zh = z - zb * Hdiv;
    Ah += zb * sAb + zh * sAh_;  Al += zb * sAb + zh * sAh_;
    Bh += zb * sBb + zh * sBh_;  Bl += zb * sBb + zh * sBh_;
    const long long coff = zb * sCb + zh * sCh_;
    const int m0 = blockIdx.y * 128, n0 = blockIdx.x * 128;

    float acc[4][4][4];
#pragma unroll
    for (int i = 0; i < 4; i++)
#pragma unroll
        for (int j = 0; j < 4; j++)
#pragma unroll
            for (int r = 0; r < 4; r++) acc[i][j][r] = 0.f;

    auto load_chunk = [&](int kc, int stg) {
        const uint32_t sb = sbase + (uint32_t)stg * STAGE_BYTES;
        auto one = [&](const bf16* p, int r0, int ld, uint32_t off) {
#pragma unroll
            for (int it = 0; it < 2; it++) {
                int c = tid + it * 256;             // 0..511
                int r = c >> 2, c16 = c & 3;
                const char* g = (const char*)(p + (long long)(r0 + r) * ld + kc * 32) + c16 * 16;
                asm volatile("cp.async.cg.shared.global [%0], [%1], 16;"
                             :: "r"(sb + off + (uint32_t)(r * 80 + c16 * 16)), "l"(g));
            }
        };
        one(Ah, m0, lda, 0u);      one(Al, m0, lda, 10240u);
        one(Bh, n0, ldb, 20480u);  one(Bl, n0, ldb, 30720u);
        CP_COMMIT();
    };

    const uint32_t lrow  = (uint32_t)(l & 15) * 80u;
    const uint32_t lhalf = (uint32_t)(l >> 4) * 16u;

    auto compute = [&](int stg) {
        const uint32_t sb = sbase + (uint32_t)stg * STAGE_BYTES;
#pragma unroll
        for (int ks = 0; ks < 2; ks++) {
            const uint32_t kb = (uint32_t)ks * 32u + lhalf;
            uint32_t aH[4][4], aL[4][4], bH[2][4], bL[2][4];
#pragma unroll
            for (int mt = 0; mt < 4; mt++) {
                uint32_t ra = sb + (uint32_t)((wm * 64 + mt * 16) * 80) + lrow + kb;
                LDSM4(aH[mt], ra);
                LDSM4(aL[mt], ra + 10240u);
            }
#pragma unroll
            for (int bt = 0; bt < 2; bt++) {
                uint32_t rb = sb + 20480u + (uint32_t)((wn * 32 + bt * 16) * 80) + lrow + kb;
                LDSM4(bH[bt], rb);
                LDSM4(bL[bt], rb + 10240u);
            }
#pragma unroll
            for (int mt = 0; mt < 4; mt++)
#pragma unroll
                for (int nt = 0; nt < 4; nt++) {
                    const int bt = nt >> 1, hi = nt & 1;
                    MMA16816(acc[mt][nt], aH[mt], bH[bt][hi], bH[bt][hi + 2]);
                }
#pragma unroll
            for (int mt = 0; mt < 4; mt++)
#pragma unroll
                for (int nt = 0; nt < 4; nt++) {
                    const int bt = nt >> 1, hi = nt & 1;
                    MMA16816(acc[mt][nt], aL[mt], bH[bt][hi], bH[bt][hi + 2]);
                }
#pragma unroll
            for (int mt = 0; mt < 4; mt++)
#pragma unroll
                for (int nt = 0; nt < 4; nt++) {
                    const int bt = nt >> 1, hi = nt & 1;
                    MMA16816(acc[mt][nt], aH[mt], bL[bt][hi], bL[bt][hi + 2]);
                }
        }
    };

    const int nk = K / 32;
    const int npre = (nk < 3) ? nk : 3;
    for (int i = 0; i < npre; i++) load_chunk(i, i);
    for (int i = 0; i < nk; i++) {
        int out = nk - 1 - i; if (out > 2) out = 2;
        if (out == 2)      asm volatile("cp.async.wait_group 2;" ::: "memory");
        else if (out == 1) asm volatile("cp.async.wait_group 1;" ::: "memory");
        else               asm volatile("cp.async.wait_group 0;" ::: "memory");
        __syncthreads();
        if (i + 3 < nk) load_chunk(i + 3, (i + 3) & 3);
        compute(i & 3);
    }

    // ---------------- epilogue ----------------
    const int r0f = l >> 2, c0f = (l & 3) * 2;
#pragma unroll
    for (int mt = 0; mt < 4; mt++) {
        const int gr = m0 + wm * 64 + mt * 16 + r0f;
#pragma unroll
        for (int nt = 0; nt < 4; nt++) {
            const int gc = n0 + wn * 32 + nt * 8 + c0f;
            float a0 = acc[mt][nt][0], a1 = acc[mt][nt][1];
            float a2 = acc[mt][nt][2], a3 = acc[mt][nt][3];
            if (EPI == 0) {
                float bx = bget(bias0, bias1, bias2, gc);
                float by = bget(bias0, bias1, bias2, gc + 1);
                float2 u0; u0.x = a0 + bx; u0.y = a1 + by;
                float2 u1; u1.x = a2 + bx; u1.y = a3 + by;
                *(float2*)(C + coff + (long long)gr * ldc + gc) = u0;
                *(float2*)(C + coff + (long long)(gr + 8) * ldc + gc) = u1;
            } else if (EPI == 1) {
                float bx = bias0[gc], by = bias0[gc + 1];
                float v0 = gelu_t(a0 + bx), v1 = gelu_t(a1 + by);
                float v2 = gelu_t(a2 + bx), v3 = gelu_t(a3 + by);
                bf16 h0, l0, h1, l1;
                split2(v0, h0, l0); split2(v1, h1, l1);
                *(__nv_bfloat162*)(Ch + coff + (long long)gr * ldc + gc) = mkbf2(h0, h1);
                *(__nv_bfloat162*)(Cl + coff + (long long)gr * ldc + gc) = mkbf2(l0, l1);
                split2(v2, h0, l0); split2(v3, h1, l1);
                *(__nv_bfloat162*)(Ch + coff + (long long)(gr + 8) * ldc + gc) = mkbf2(h0, h1);
                *(__nv_bfloat162*)(Cl + coff + (long long)(gr + 8) * ldc + gc) = mkbf2(l0, l1);
            } else {
                float bx = bias0[gc], by = bias0[gc + 1];
#pragma unroll
                for (int hh = 0; hh < 2; hh++) {
                    const int row = gr + hh * 8;
                    float va = (hh ? a2 : a0) + bx;
                    float vb = (hh ? a3 : a1) + by;
                    if (gateRow >= 0) {
                        const int b = row / Ss;
                        const float* gp = em + ((long long)b * 6 + gateRow) * Dd;
                        va *= gp[gc]; vb *= gp[gc + 1];
                    }
                    float2 o = *(float2*)(C + coff + (long long)row * ldc + gc);
                    o.x += va; o.y += vb;
                    *(float2*)(C + coff + (long long)row * ldc + gc) = o;
                }
            }
        }
    }
}

// ---------------------------------------------------------------------------
// Elementwise kernels
// ---------------------------------------------------------------------------
__global__ void k_copy(const float* __restrict__ a, float* __restrict__ o, long long n) {
    long long i = (long long)blockIdx.x * 256 + threadIdx.x;
    if (i < n) o[i] = a[i];
}
__global__ void k_emadd(const float* __restrict__ e, const float* __restrict__ mod,
                        float* __restrict__ em) {
    int i = blockIdx.x * 256 + threadIdx.x;
    if (i < Bb * 6 * Dd) em[i] = e[i] + mod[i % (6 * Dd)];
}
__global__ void k_split4(const float* __restrict__ in, bf16* __restrict__ oh,
                         bf16* __restrict__ ol, long long n) {
    long long i = ((long long)blockIdx.x * 256 + threadIdx.x) * 4;
    if (i >= n) return;
    float4 v = *(const float4*)(in + i);
    bf16 h0, l0, h1, l1;
    split2(v.x, h0, l0); split2(v.y, h1, l1);
    *(__nv_bfloat162*)(oh + i) = mkbf2(h0, h1);
    *(__nv_bfloat162*)(ol + i) = mkbf2(l0, l1);
    split2(v.z, h0, l0); split2(v.w, h1, l1);
    *(__nv_bfloat162*)(oh + i + 2) = mkbf2(h0, h1);
    *(__nv_bfloat162*)(ol + i + 2) = mkbf2(l0, l1);
}
// transpose+split: W[K x N] -> T[N x K] bf16 h/l  (vectorized bf162 stores)
__global__ void k_tsplit(const float* __restrict__ W, bf16* __restrict__ Th,
                         bf16* __restrict__ Tl, int Kd, int Nd) {
    __shared__ float t[32][33];
    int n0 = blockIdx.x * 32, k0 = blockIdx.y * 32;
    int tx = threadIdx.x;
    for (int j = threadIdx.y; j < 32; j += 8)
        t[j][tx] = W[(long long)(k0 + j) * Nd + n0 + tx];        // t[k][n]
    __syncthreads();
    for (int j = threadIdx.y; j < 16; j += 8) {
        int n  = j * 2 + (tx >> 4);       // 0..31
        int kk = (tx & 15) * 2;           // 0..30
        float v0 = t[kk][n], v1 = t[kk + 1][n];
        long long o = (long long)(n0 + n) * Kd + k0 + kk;
        bf16 h0, l0, h1, l1;
        split2(v0, h0, l0); split2(v1, h1, l1);
        *(__nv_bfloat162*)(Th + o) = mkbf2(h0, h1);
        *(__nv_bfloat162*)(Tl + o) = mkbf2(l0, l1);
    }
}
__global__ void k_ln_mod_split(const float* __restrict__ x, const float* __restrict__ em,
                               bf16* __restrict__ oh, bf16* __restrict__ ol,
                               int scaleRow, int shiftRow) {
    int row = blockIdx.x, b = row / Ss, t = threadIdx.x;
    const float* xr = x + (long long)row * Dd;
    const float* es = em + ((long long)b * 6 + scaleRow) * Dd;
    const float* eh = em + ((long long)b * 6 + shiftRow) * Dd;
    float v[8];
    float4 a0 = *(const float4*)(xr + t * 8);
    float4 a1 = *(const float4*)(xr + t * 8 + 4);
    v[0]=a0.x; v[1]=a0.y; v[2]=a0.z; v[3]=a0.w; v[4]=a1.x; v[5]=a1.y; v[6]=a1.z; v[7]=a1.w;
    float s = 0.f, s2 = 0.f;
#pragma unroll
    for (int i = 0; i < 8; i++) { s += v[i]; s2 += v[i] * v[i]; }
    __shared__ float sh[512];
    sh[t] = s; sh[256 + t] = s2;
    __syncthreads();
    for (int o = 128; o > 0; o >>= 1) {
        if (t < o) { sh[t] += sh[t + o]; sh[256 + t] += sh[256 + t + o]; }
        __syncthreads();
    }
    float m = sh[0] * (1.f / Dd);
    float var = sh[256] * (1.f / Dd) - m * m;
    float r = rsqrtf(var + EPSf);
    bf16 hh[8], ll[8];
#pragma unroll
    for (int i = 0; i < 8; i++) {
        int dI = t * 8 + i;
        float u = (v[i] - m) * r * (1.f + es[dI]) + eh[dI];
        split2(u, hh[i], ll[i]);
    }
    long long ob = (long long)row * Dd + t * 8;
#pragma unroll
    for (int i = 0; i < 8; i += 2) {
        *(__nv_bfloat162*)(oh + ob + i) = mkbf2(hh[i], hh[i + 1]);
        *(__nv_bfloat162*)(ol + ob + i) = mkbf2(ll[i], ll[i + 1]);
    }
}
__global__ void k_rms_rope_split(const float* __restrict__ in, int ldin, int off,
                                 const float* __restrict__ w, const float* __restrict__ freqs,
                                 bf16* __restrict__ oh, bf16* __restrict__ ol, int Sv) {
    int row = blockIdx.x, b = row / Sv, s = row % Sv, t = threadIdx.x;
    const float* xr = in + (long long)row * ldin + off;
    float v[8];
    float4 a0 = *(const float4*)(xr + t * 8);
    float4 a1 = *(const float4*)(xr + t * 8 + 4);
    v[0]=a0.x; v[1]=a0.y; v[2]=a0.z; v[3]=a0.w; v[4]=a1.x; v[5]=a1.y; v[6]=a1.z; v[7]=a1.w;
    float s2 = 0.f;
#pragma unroll
    for (int i = 0; i < 8; i++) s2 += v[i] * v[i];
    __shared__ float sh[256];
    sh[t] = s2;
    __syncthreads();
    for (int o = 128; o > 0; o >>= 1) {
        if (t < o) sh[t] += sh[t + o];
        __syncthreads();
    }
    float r = rsqrtf(sh[0] * (1.f / Dd) + EPSf);
    int dbase = t * 8, h = dbase >> 7, dd = dbase & 127;
    float u[8];
#pragma unroll
    for (int i = 0; i < 8; i++) u[i] = v[i] * r * w[dbase + i];
    if (freqs) {
#pragma unroll
        for (int pr = 0; pr < 4; pr++) {
            float sn, cs;
            __sincosf(freqs[s * 64 + (dd >> 1) + pr], &sn, &cs);
            float xr_ = u[2 * pr], xi = u[2 * pr + 1];
            u[2 * pr]     = xr_ * cs - xi * sn;
            u[2 * pr + 1] = xr_ * sn + xi * cs;
        }
    }
    long long ob = ((long long)(b * Hh + h) * Sv + s) * 128 + dd;
    bf16 hh[8], ll[8];
#pragma unroll
    for (int i = 0; i < 8; i++) split2(u[i], hh[i], ll[i]);
#pragma unroll
    for (int i = 0; i < 8; i += 2) {
        *(__nv_bfloat162*)(oh + ob + i) = mkbf2(hh[i], hh[i + 1]);
        *(__nv_bfloat162*)(ol + ob + i) = mkbf2(ll[i], ll[i + 1]);
    }
}
// V transpose+split: in[b, s, off + h*128 + d] -> out[((b*H+h)*128+d)*Sv + s]
__global__ void k_vt_split(const float* __restrict__ in, int ldin, int off,
                           bf16* __restrict__ oh, bf16* __restrict__ ol, int Sv) {
    __shared__ float t[32][33];
    int bh = blockIdx.z, b = bh >> 4, h = bh & 15;
    int s0 = blockIdx.x * 32, d0 = blockIdx.y * 32;
    int tx = threadIdx.x;
    for (int j = threadIdx.y; j < 32; j += 8)
        t[j][tx] = in[(long long)(b * Sv + s0 + j) * ldin + off + h * 128 + d0 + tx]; // t[s][d]
    __syncthreads();
    for (int j = threadIdx.y; j < 16; j += 8) {
        int d  = j * 2 + (tx >> 4);
        int ss = (tx & 15) * 2;
        float v0 = t[ss][d], v1 = t[ss + 1][d];
        long long o = (long long)(bh * 128 + d0 + d) * Sv + s0 + ss;
        bf16 h0, l0, h1, l1;
        split2(v0, h0, l0); split2(v1, h1, l1);
        *(__nv_bfloat162*)(oh + o) = mkbf2(h0, h1);
        *(__nv_bfloat162*)(ol + o) = mkbf2(l0, l1);
    }
}
__global__ void k_softmax_split(const float* __restrict__ S, bf16* __restrict__ oh,
                                bf16* __restrict__ ol, int ncols, float scale) {
    long long row = blockIdx.x;
    const float* p = S + row * ncols;
    bf16* Hp = oh + row * ncols;
    bf16* Lp = ol + row * ncols;
    int t = threadIdx.x, nc = ncols >> 8;     // 8 (self) or 2 (cross), contiguous per thread
    const int base = t * nc;
    float vv[8];
    float lm = -3.4e38f;
    for (int k = 0; k < nc; k += 2) {
        float2 f = *(const float2*)(p + base + k);
        vv[k] = f.x; vv[k + 1] = f.y;
        lm = fmaxf(lm, fmaxf(f.x, f.y));
    }
    __shared__ float sh[256];
    sh[t] = lm; __syncthreads();
    for (int o = 128; o > 0; o >>= 1) { if (t < o) sh[t] = fmaxf(sh[t], sh[t + o]); __syncthreads(); }
    float m = sh[0] * scale;
    __syncthreads();
    float ls = 0.f;
    for (int k = 0; k < nc; k++) { float e = __expf(vv[k] * scale - m); vv[k] = e; ls += e; }
    sh[t] = ls; __syncthreads();
    for (int o = 128; o > 0; o >>= 1) { if (t < o) sh[t] += sh[t + o]; __syncthreads(); }
    float inv = 1.f / sh[0];
    for (int k = 0; k < nc; k += 2) {
        bf16 h0, l0, h1, l1;
        split2(vv[k] * inv, h0, l0);
        split2(vv[k + 1] * inv, h1, l1);
        *(__nv_bfloat162*)(Hp + base + k) = mkbf2(h0, h1);
        *(__nv_bfloat162*)(Lp + base + k) = mkbf2(l0, l1);
    }
}

// ---------------------------------------------------------------------------
// Host orchestration
// ---------------------------------------------------------------------------
static void gemm(int epi, const bf16* Ah, const bf16* Al, const bf16* Bh, const bf16* Bl,
                 int M, int N, int K, int lda, int ldb,
                 float* C, bf16* Ch, bf16* Cl, int ldc,
                 const float* b0, const float* b1, const float* b2,
                 const float* em, int gateRow,
                 int batch, int Hdiv,
                 long long sAb, long long sAh, long long sBb, long long sBh,
                 long long sCb, long long sCh)
{
    dim3 g(N / 128, M / 128, batch), bl(256);
    size_t sm = SMEM_TOTAL_G;
    if (epi == 0)
        mma_gemm<0><<<g, bl, sm>>>(Ah, Al, Bh, Bl, K, lda, ldb, C, Ch, Cl, ldc,
                                   b0, b1, b2, em, gateRow, Hdiv, sAb, sAh, sBb, sBh, sCb, sCh);
    else if (epi == 1)
        mma_gemm<1><<<g, bl, sm>>>(Ah, Al, Bh, Bl, K, lda, ldb, C, Ch, Cl, ldc,
                                   b0, b1, b2, em, gateRow, Hdiv, sAb, sAh, sBb, sBh, sCb, sCh);
    else
        mma_gemm<2><<<g, bl, sm>>>(Ah, Al, Bh, Bl, K, lda, ldb, C, Ch, Cl, ldc,
                                   b0, b1, b2, em, gateRow, Hdiv, sAb, sAh, sBb, sBh, sCb, sCh);
}

#define SYM(p, s) cudaGetSymbolAddress((void**)&p, s)

extern "C" void kernel_launch(void* const* d_in, const int* in_sizes, int n_in,
                              void* d_out, int out_size)
{
    bool sig = (in_sizes[13] == Dd);
    int I_snq, I_snk, I_cq_w, I_cq_b, I_ck_w, I_ck_b, I_cv_w, I_cv_b;
    int I_co_w, I_co_b, I_cnq, I_cnk, I_f1_w, I_f1_b, I_f2_w, I_f2_b;
    if (sig) {
        I_snq=13; I_snk=14; I_cq_w=15; I_cq_b=16; I_ck_w=17; I_ck_b=18;
        I_cv_w=19; I_cv_b=20; I_co_w=21; I_co_b=22; I_cnq=23; I_cnk=24;
        I_f1_w=25; I_f1_b=26; I_f2_w=27; I_f2_b=28;
    } else {
        I_cq_w=13; I_cq_b=14; I_ck_w=15; I_ck_b=16; I_cv_w=17; I_cv_b=18;
        I_co_w=19; I_co_b=20; I_f1_w=21; I_f1_b=22; I_f2_w=23; I_f2_b=24;
        I_snq=25; I_snk=26; I_cnq=27; I_cnk=28;
    }
    const float* x    = (const float*)d_in[0];
    const float* e    = (const float*)d_in[1];
    const float* ctx  = (const float*)d_in[2];
    const float* fr   = (const float*)d_in[3];
    const float* mod  = (const float*)d_in[4];
    const float* sq_w = (const float*)d_in[5];  const float* sq_b = (const float*)d_in[6];
    const float* sk_w = (const float*)d_in[7];  const float* sk_b = (const float*)d_in[8];
    const float* sv_w = (const float*)d_in[9];  const float* sv_b = (const float*)d_in[10];
    const float* so_w = (const float*)d_in[11]; const float* so_b = (const float*)d_in[12];
    const float* snq  = (const float*)d_in[I_snq];  const float* snk  = (const float*)d_in[I_snk];
    const float* cq_w = (const float*)d_in[I_cq_w]; const float* cq_b = (const float*)d_in[I_cq_b];
    const float* ck_w = (const float*)d_in[I_ck_w]; const float* ck_b = (const float*)d_in[I_ck_b];
    const float* cv_w = (const float*)d_in[I_cv_w]; const float* cv_b = (const float*)d_in[I_cv_b];
    const float* co_w = (const float*)d_in[I_co_w]; const float* co_b = (const float*)d_in[I_co_b];
    const float* cnq  = (const float*)d_in[I_cnq];  const float* cnk  = (const float*)d_in[I_cnk];
    const float* f1_w = (const float*)d_in[I_f1_w]; const float* f1_b = (const float*)d_in[I_f1_b];
    const float* f2_w = (const float*)d_in[I_f2_w]; const float* f2_b = (const float*)d_in[I_f2_b];

    cudaFuncSetAttribute(mma_gemm<0>, cudaFuncAttributeMaxDynamicSharedMemorySize, SMEM_TOTAL_G);
    cudaFuncSetAttribute(mma_gemm<1>, cudaFuncAttributeMaxDynamicSharedMemorySize, SMEM_TOTAL_G);
    cudaFuncSetAttribute(mma_gemm<2>, cudaFuncAttributeMaxDynamicSharedMemorySize, SMEM_TOTAL_G);

    float *em_, *qkv, *y, *sc;
    SYM(em_, g_em); SYM(qkv, g_qkv); SYM(y, g_y); SYM(sc, g_sc);
    bf16 *txh, *txl, *cxh, *cxl, *qh, *ql, *kh, *kl, *vth, *vtl, *ph_, *pl_, *fh, *fl;
    SYM(txh, g_txh); SYM(txl, g_txl); SYM(cxh, g_cxh); SYM(cxl, g_cxl);
    SYM(qh, g_qh); SYM(ql, g_ql); SYM(kh, g_kh); SYM(kl, g_kl);
    SYM(vth, g_vth); SYM(vtl, g_vtl); SYM(ph_, g_ph); SYM(pl_, g_pl);
    SYM(fh, g_fh); SYM(fl, g_fl);
    bf16 *wqkvh, *wqkvl, *wckvh, *wckvl, *woh, *wol, *wcqh, *wcql, *wcoh, *wcol, *wf1h, *wf1l, *wf2h, *wf2l;
    SYM(wqkvh, g_wqkvh); SYM(wqkvl, g_wqkvl); SYM(wckvh, g_wckvh); SYM(wckvl, g_wckvl);
    SYM(woh, g_woh); SYM(wol, g_wol); SYM(wcqh, g_wcqh); SYM(wcql, g_wcql);
    SYM(wcoh, g_wcoh); SYM(wcol, g_wcol); SYM(wf1h, g_wf1h); SYM(wf1l, g_wf1l);
    SYM(wf2h, g_wf2h); SYM(wf2l, g_wf2l);

    float* xo = (float*)d_out;
    const long long NX = (long long)Bb * Ss * Dd;
    const long long DD = (long long)Dd * Dd;
    const long long SD = (long long)Ss * Dd;
    const long long SS2 = (long long)Ss * Ss;
    const long long SL = (long long)Ss * LCc;
    const float SCALE = 0.08838834764831845f;
    dim3 tb(32, 8);

    // ---- prep ordered so launch #6 is the big QKV GEMM (ncu -s 5 -c 1) ----
    k_emadd<<<(Bb * 6 * Dd + 255) / 256, 256>>>(e, mod, em_);                     // 1
    k_ln_mod_split<<<Bb * Ss, 256>>>(x, em_, txh, txl, 1, 0);                     // 2
    k_tsplit<<<dim3(Dd/32, Dd/32), tb>>>(sq_w, wqkvh,          wqkvl,          Dd, Dd); // 3
    k_tsplit<<<dim3(Dd/32, Dd/32), tb>>>(sk_w, wqkvh + DD,     wqkvl + DD,     Dd, Dd); // 4
    k_tsplit<<<dim3(Dd/32, Dd/32), tb>>>(sv_w, wqkvh + 2 * DD, wqkvl + 2 * DD, Dd, Dd); // 5
    gemm(0, txh, txl, wqkvh, wqkvl, Bb*Ss, 3*Dd, Dd, Dd, Dd,                      // 6 <- profiled
         qkv, nullptr, nullptr, 3*Dd, sq_b, sk_b, sv_b, nullptr, -1, 1, 1, 0,0,0,0,0,0);

    k_copy<<<(int)((NX + 255) / 256), 256>>>(x, xo, NX);
    k_tsplit<<<dim3(Dd/32, Dd/32), tb>>>(so_w, woh,  wol,  Dd, Dd);
    k_tsplit<<<dim3(Dd/32, Dd/32), tb>>>(cq_w, wcqh, wcql, Dd, Dd);
    k_tsplit<<<dim3(Dd/32, Dd/32), tb>>>(ck_w, wckvh,      wckvl,      Dd, Dd);
    k_tsplit<<<dim3(Dd/32, Dd/32), tb>>>(cv_w, wckvh + DD, wckvl + DD, Dd, Dd);
    k_tsplit<<<dim3(Dd/32, Dd/32), tb>>>(co_w, wcoh, wcol, Dd, Dd);
    k_tsplit<<<dim3(Ff/32, Dd/32), tb>>>(f1_w, wf1h, wf1l, Dd, Ff);
    k_tsplit<<<dim3(Dd/32, Ff/32), tb>>>(f2_w, wf2h, wf2l, Ff, Dd);

    // ===================== self attention =====================
    k_rms_rope_split<<<Bb * Ss, 256>>>(qkv, 3*Dd, 0,  snq, fr, qh, ql, Ss);
    k_rms_rope_split<<<Bb * Ss, 256>>>(qkv, 3*Dd, Dd, snk, fr, kh, kl, Ss);
    k_vt_split<<<dim3(Ss/32, 4, Bb*Hh), tb>>>(qkv, 3*Dd, 2*Dd, vth, vtl, Ss);
    gemm(0, qh, ql, kh, kl, Ss, Ss, HDd, HDd, HDd,
         sc, nullptr, nullptr, Ss, nullptr, nullptr, nullptr, nullptr, -1, Bb*Hh, 1,
         (long long)Ss*HDd, 0, (long long)Ss*HDd, 0, SS2, 0);
    k_softmax_split<<<Bb * Hh * Ss, 256>>>(sc, ph_, pl_, Ss, SCALE);
    gemm(0, ph_, pl_, vth, vtl, Ss, HDd, Ss, Ss, Ss,
         y, nullptr, nullptr, Dd, nullptr, nullptr, nullptr, nullptr, -1, Bb*Hh, Hh,
         (long long)Hh*SS2, SS2, (long long)Hh*HDd*Ss, (long long)HDd*Ss, SD, HDd);
    k_split4<<<(int)(NX / 1024), 256>>>(y, txh, txl, NX);
    gemm(2, txh, txl, woh, wol, Bb*Ss, Dd, Dd, Dd, Dd,
         xo, nullptr, nullptr, Dd, so_b, nullptr, nullptr, em_, 2, 1, 1, 0,0,0,0,0,0);

    // ===================== cross attention =====================
    k_split4<<<(int)(NX / 1024), 256>>>(xo, txh, txl, NX);
    gemm(0, txh, txl, wcqh, wcql, Bb*Ss, Dd, Dd, Dd, Dd,
         qkv, nullptr, nullptr, Dd, cq_b, nullptr, nullptr, nullptr, -1, 1, 1, 0,0,0,0,0,0);
    k_rms_rope_split<<<Bb * Ss, 256>>>(qkv, Dd, 0, cnq, nullptr, qh, ql, Ss);
    k_split4<<<(int)((long long)Bb*LCc*Dd / 1024), 256>>>(ctx, cxh, cxl, (long long)Bb*LCc*Dd);
    gemm(0, cxh, cxl, wckvh, wckvl, Bb*LCc, 2*Dd, Dd, Dd, Dd,
         qkv, nullptr, nullptr, 2*Dd, ck_b, cv_b, nullptr, nullptr, -1, 1, 1, 0,0,0,0,0,0);
    k_rms_rope_split<<<Bb * LCc, 256>>>(qkv, 2*Dd, 0, cnk, nullptr, kh, kl, LCc);
    k_vt_split<<<dim3(LCc/32, 4, Bb*Hh), tb>>>(qkv, 2*Dd, Dd, vth, vtl, LCc);
    gemm(0, qh, ql, kh, kl, Ss, LCc, HDd, HDd, HDd,
         sc, nullptr, nullptr, LCc, nullptr, nullptr, nullptr, nullptr, -1, Bb*Hh, 1,
         (long long)Ss*HDd, 0, (long long)LCc*HDd, 0, SL, 0);
    k_softmax_split<<<Bb * Hh * Ss, 256>>>(sc, ph_, pl_, LCc, SCALE);
    gemm(0, ph_, pl_, vth, vtl, Ss, HDd, LCc, LCc, LCc,
         y, nullptr, nullptr, Dd, nullptr, nullptr, nullptr, nullptr, -1, Bb*Hh, Hh,
         (long long)Hh*SL, SL, (long long)Hh*HDd*LCc, (long long)HDd*LCc, SD, HDd);
    k_split4<<<(int)(NX / 1024), 256>>>(y, txh, txl, NX);
    gemm(2, txh, txl, wcoh, wcol, Bb*Ss, Dd, Dd, Dd, Dd,
         xo, nullptr, nullptr, Dd, co_b, nullptr, nullptr, em_, -1, 1, 1, 0,0,0,0,0,0);

    // ===================== FFN =====================
    k_ln_mod_split<<<Bb * Ss, 256>>>(xo, em_, txh, txl, 4, 3);
    gemm(1, txh, txl, wf1h, wf1l, Bb*Ss, Ff, Dd, Dd, Dd,
         nullptr, fh, fl, Ff, f1_b, nullptr, nullptr, nullptr, -1, 1, 1, 0,0,0,0,0,0);
    gemm(2, fh, fl, wf2h, wf2l, Bb*Ss, Dd, Ff, Ff, Ff,
         xo, nullptr, nullptr, Dd, f2_b, nullptr, nullptr, em_, 5, 1, 1, 0,0,0,0,0,0);
}

// round 6
// speedup vs baseline: 1.5146x; 1.5146x over previous
#include <cuda_runtime.h>
#include <cuda_bf16.h>
#include <cstdint>

using bf16 = __nv_bfloat16;

#define Bb  2
#define Ss  2048
#define Dd  2048
#define Hh  16
#define HDd 128
#define Ff  8192
#define LCc 512
#define EPSf 1e-6f

// ---------------------------------------------------------------------------
// Scratch (__device__ globals; allocation-free rule)
// ---------------------------------------------------------------------------
__device__ float g_em [Bb * 6 * Dd];
__device__ float g_qkv [(size_t)Bb * Ss * 3 * Dd];
__device__ float g_y   [(size_t)Bb * Ss * Dd];
__device__ float g_sc  [(size_t)Bb * Hh * Ss * Ss];

#define DECL2(nm, n) __device__ __align__(128) bf16 nm##h[(size_t)(n)]; __device__ __align__(128) bf16 nm##l[(size_t)(n)];
DECL2(g_tx, (size_t)Bb*Ss*Dd)
DECL2(g_cx, (size_t)Bb*LCc*Dd)
DECL2(g_q,  (size_t)Bb*Ss*Dd)
DECL2(g_k,  (size_t)Bb*Ss*Dd)
DECL2(g_vt, (size_t)Bb*Ss*Dd)
DECL2(g_p,  (size_t)Bb*Hh*Ss*Ss)
DECL2(g_f,  (size_t)Bb*Ss*Ff)
DECL2(g_wqkv, (size_t)3*Dd*Dd)
DECL2(g_wckv, (size_t)2*Dd*Dd)
DECL2(g_wo,   (size_t)Dd*Dd)
DECL2(g_wcq,  (size_t)Dd*Dd)
DECL2(g_wco,  (size_t)Dd*Dd)
DECL2(g_wf1,  (size_t)Ff*Dd)
DECL2(g_wf2,  (size_t)Dd*Ff)

// ---------------------------------------------------------------------------
// helpers
// ---------------------------------------------------------------------------
__device__ __forceinline__ uint32_t smem_u32(const void* p) {
    uint32_t a;
    asm("{ .reg .u64 t; cvta.to.shared.u64 t, %1; cvt.u32.u64 %0, t; }" : "=r"(a) : "l"(p));
    return a;
}
#define CP_COMMIT() asm volatile("cp.async.commit_group;" ::: "memory")

#define LDSM4(d, a) \
  asm volatile("ldmatrix.sync.aligned.m8n8.x4.shared.b16 {%0,%1,%2,%3}, [%4];" \
    : "=r"((d)[0]), "=r"((d)[1]), "=r"((d)[2]), "=r"((d)[3]) : "r"(a))

#define MMA16816(c, a, b0, b1) \
  asm volatile("mma.sync.aligned.m16n8k16.row.col.f32.bf16.bf16.f32 " \
    "{%0,%1,%2,%3}, {%4,%5,%6,%7}, {%8,%9}, {%0,%1,%2,%3};" \
    : "+f"((c)[0]), "+f"((c)[1]), "+f"((c)[2]), "+f"((c)[3]) \
    : "r"((a)[0]), "r"((a)[1]), "r"((a)[2]), "r"((a)[3]), "r"(b0), "r"(b1))

__device__ __forceinline__ float gelu_t(float x) {
    float x3 = x * x * x;
    return 0.5f * x * (1.f + tanhf(0.7978845608028654f * (x + 0.044715f * x3)));
}
__device__ __forceinline__ void split2(float v, bf16& h, bf16& l) {
    h = __float2bfloat16(v);
    l = __float2bfloat16(v - __bfloat162float(h));
}
__device__ __forceinline__ __nv_bfloat162 mkbf2(bf16 a, bf16 b) {
    __nv_bfloat162 r; r.x = a; r.y = b; return r;
}
// segmented bias: segments of 2048 columns (b1 null -> single segment b0)
__device__ __forceinline__ float bget(const float* b0, const float* b1,
                                      const float* b2, int c) {
    if (b1 == nullptr) return b0 ? b0[c] : 0.f;
    int seg = c >> 11, off = c & 2047;
    const float* bp = (seg == 0) ? b0 : ((seg == 1) ? b1 : b2);
    return bp[off];
}

// stage: Ah(10240) Al(10240) Bh(10240) Bl(10240); 80B row pitch, 128 rows, 32 bf16 cols
#define STAGE_BYTES 40960u
#define SMEM_TOTAL_G (4 * 40960)

// ---------------------------------------------------------------------------
// HMMA (mma.sync) GEMM: C(MxN) = A(MxK) @ B^T, B stored [N x K], bf16 hi/lo
// 3-term bf16x3 into fp32 acc. EPI: 0 fp32(+bias); 1 gelu->bf16 h/l(+bias);
// 2 xo += (acc+bias)*gate  (gateRow<0: plain add)
// Mainloop = Round-4-measured version (prefetch depth 2), do not touch.
// ---------------------------------------------------------------------------
template <int EPI>
__global__ __launch_bounds__(256, 1)
void mma_gemm(const bf16* __restrict__ Ah, const bf16* __restrict__ Al,
              const bf16* __restrict__ Bh, const bf16* __restrict__ Bl,
              int K, int lda, int ldb,
              float* C, bf16* Ch, bf16* Cl, int ldc,
              const float* __restrict__ bias0, const float* __restrict__ bias1,
              const float* __restrict__ bias2,
              const float* __restrict__ em, int gateRow,
              int Hdiv,
              long long sAb, long long sAh_, long long sBb, long long sBh_,
              long long sCb, long long sCh_)
{
    extern __shared__ __align__(128) char smem[];
    const uint32_t sbase = smem_u32(smem);
    const int tid = threadIdx.x;
    const int w = tid >> 5, l = tid & 31;
    const int wm = w >> 2, wn = w & 3;          // 2 x 4 warp grid, warp tile 64x32

    const int z = blockIdx.z;
    const int zb = z / Hdiv, zh = z - zb * Hdiv;
    Ah += zb * sAb + zh * sAh_;  Al += zb * sAb + zh * sAh_;
    Bh += zb * sBb + zh * sBh_;  Bl += zb * sBb + zh * sBh_;
    const long long coff = zb * sCb + zh * sCh_;
    const int m0 = blockIdx.y * 128, n0 = blockIdx.x * 128;

    float acc[4][4][4];
#pragma unroll
    for (int i = 0; i < 4; i++)
#pragma unroll
        for (int j = 0; j < 4; j++)
#pragma unroll
            for (int r = 0; r < 4; r++) acc[i][j][r] = 0.f;

    auto load_chunk = [&](int kc, int stg) {
        const uint32_t sb = sbase + (uint32_t)stg * STAGE_BYTES;
        auto one = [&](const bf16* p, int r0, int ld, uint32_t off) {
#pragma unroll
            for (int it = 0; it < 2; it++) {
                int c = tid + it * 256;             // 0..511
                int r = c >> 2, c16 = c & 3;
                const char* g = (const char*)(p + (long long)(r0 + r) * ld + kc * 32) + c16 * 16;
                asm volatile("cp.async.cg.shared.global [%0], [%1], 16;"
                             :: "r"(sb + off + (uint32_t)(r * 80 + c16 * 16)), "l"(g));
            }
        };
        one(Ah, m0, lda, 0u);      one(Al, m0, lda, 10240u);
        one(Bh, n0, ldb, 20480u);  one(Bl, n0, ldb, 30720u);
        CP_COMMIT();
    };

    const uint32_t lrow  = (uint32_t)(l & 15) * 80u;
    const uint32_t lhalf = (uint32_t)(l >> 4) * 16u;

    auto compute = [&](int stg) {
        const uint32_t sb = sbase + (uint32_t)stg * STAGE_BYTES;
#pragma unroll
        for (int ks = 0; ks < 2; ks++) {
            const uint32_t kb = (uint32_t)ks * 32u + lhalf;
            uint32_t aH[4][4], aL[4][4], bH[2][4], bL[2][4];
#pragma unroll
            for (int mt = 0; mt < 4; mt++) {
                uint32_t ra = sb + (uint32_t)((wm * 64 + mt * 16) * 80) + lrow + kb;
                LDSM4(aH[mt], ra);
                LDSM4(aL[mt], ra + 10240u);
            }
#pragma unroll
            for (int bt = 0; bt < 2; bt++) {
                uint32_t rb = sb + 20480u + (uint32_t)((wn * 32 + bt * 16) * 80) + lrow + kb;
                LDSM4(bH[bt], rb);
                LDSM4(bL[bt], rb + 10240u);
            }
#pragma unroll
            for (int mt = 0; mt < 4; mt++)
#pragma unroll
                for (int nt = 0; nt < 4; nt++) {
                    const int bt = nt >> 1, hi = nt & 1;
                    MMA16816(acc[mt][nt], aH[mt], bH[bt][hi], bH[bt][hi + 2]);
                }
#pragma unroll
            for (int mt = 0; mt < 4; mt++)
#pragma unroll
                for (int nt = 0; nt < 4; nt++) {
                    const int bt = nt >> 1, hi = nt & 1;
                    MMA16816(acc[mt][nt], aL[mt], bH[bt][hi], bH[bt][hi + 2]);
                }
#pragma unroll
            for (int mt = 0; mt < 4; mt++)
#pragma unroll
                for (int nt = 0; nt < 4; nt++) {
                    const int bt = nt >> 1, hi = nt & 1;
                    MMA16816(acc[mt][nt], aH[mt], bL[bt][hi], bL[bt][hi + 2]);
                }
        }
    };

    const int nk = K / 32;
    load_chunk(0, 0);
    if (nk > 1) load_chunk(1, 1);
    for (int i = 0; i < nk; i++) {
        if (i + 1 < nk) asm volatile("cp.async.wait_group 1;" ::: "memory");
        else            asm volatile("cp.async.wait_group 0;" ::: "memory");
        __syncthreads();
        if (i + 2 < nk) load_chunk(i + 2, (i + 2) & 3);
        compute(i & 3);
    }

    // ---------------- epilogue ----------------
    const int r0f = l >> 2, c0f = (l & 3) * 2;
#pragma unroll
    for (int mt = 0; mt < 4; mt++) {
        const int gr = m0 + wm * 64 + mt * 16 + r0f;
#pragma unroll
        for (int nt = 0; nt < 4; nt++) {
            const int gc = n0 + wn * 32 + nt * 8 + c0f;
            float a0 = acc[mt][nt][0], a1 = acc[mt][nt][1];
            float a2 = acc[mt][nt][2], a3 = acc[mt][nt][3];
            if (EPI == 0) {
                float bx = bget(bias0, bias1, bias2, gc);
                float by = bget(bias0, bias1, bias2, gc + 1);
                float2 u0; u0.x = a0 + bx; u0.y = a1 + by;
                float2 u1; u1.x = a2 + bx; u1.y = a3 + by;
                *(float2*)(C + coff + (long long)gr * ldc + gc) = u0;
                *(float2*)(C + coff + (long long)(gr + 8) * ldc + gc) = u1;
            } else if (EPI == 1) {
                float bx = bias0[gc], by = bias0[gc + 1];
                float v0 = gelu_t(a0 + bx), v1 = gelu_t(a1 + by);
                float v2 = gelu_t(a2 + bx), v3 = gelu_t(a3 + by);
                bf16 h0, l0, h1, l1;
                split2(v0, h0, l0); split2(v1, h1, l1);
                *(__nv_bfloat162*)(Ch + coff + (long long)gr * ldc + gc) = mkbf2(h0, h1);
                *(__nv_bfloat162*)(Cl + coff + (long long)gr * ldc + gc) = mkbf2(l0, l1);
                split2(v2, h0, l0); split2(v3, h1, l1);
                *(__nv_bfloat162*)(Ch + coff + (long long)(gr + 8) * ldc + gc) = mkbf2(h0, h1);
                *(__nv_bfloat162*)(Cl + coff + (long long)(gr + 8) * ldc + gc) = mkbf2(l0, l1);
            } else {
                float bx = bias0[gc], by = bias0[gc + 1];
#pragma unroll
                for (int hh = 0; hh < 2; hh++) {
                    const int row = gr + hh * 8;
                    float va = (hh ? a2 : a0) + bx;
                    float vb = (hh ? a3 : a1) + by;
                    if (gateRow >= 0) {
                        const int b = row / Ss;
                        const float* gp = em + ((long long)b * 6 + gateRow) * Dd;
                        va *= gp[gc]; vb *= gp[gc + 1];
                    }
                    float2 o = *(float2*)(C + coff + (long long)row * ldc + gc);
                    o.x += va; o.y += vb;
                    *(float2*)(C + coff + (long long)row * ldc + gc) = o;
                }
            }
        }
    }
}

// ---------------------------------------------------------------------------
// Elementwise kernels
// ---------------------------------------------------------------------------
__global__ void k_copy(const float* __restrict__ a, float* __restrict__ o, long long n) {
    long long i = (long long)blockIdx.x * 256 + threadIdx.x;
    if (i < n) o[i] = a[i];
}
__global__ void k_emadd(const float* __restrict__ e, const float* __restrict__ mod,
                        float* __restrict__ em) {
    int i = blockIdx.x * 256 + threadIdx.x;
    if (i < Bb * 6 * Dd) em[i] = e[i] + mod[i % (6 * Dd)];
}
__global__ void k_split4(const float* __restrict__ in, bf16* __restrict__ oh,
                         bf16* __restrict__ ol, long long n) {
    long long i = ((long long)blockIdx.x * 256 + threadIdx.x) * 4;
    if (i >= n) return;
    float4 v = *(const float4*)(in + i);
    bf16 h0, l0, h1, l1;
    split2(v.x, h0, l0); split2(v.y, h1, l1);
    *(__nv_bfloat162*)(oh + i) = mkbf2(h0, h1);
    *(__nv_bfloat162*)(ol + i) = mkbf2(l0, l1);
    split2(v.z, h0, l0); split2(v.w, h1, l1);
    *(__nv_bfloat162*)(oh + i + 2) = mkbf2(h0, h1);
    *(__nv_bfloat162*)(ol + i + 2) = mkbf2(l0, l1);
}
// transpose+split: W[K x N] -> T[N x K] bf16 h/l
__global__ void k_tsplit(const float* __restrict__ W, bf16* __restrict__ Th,
                         bf16* __restrict__ Tl, int Kd, int Nd) {
    __shared__ float t[32][33];
    int n0 = blockIdx.x * 32, k0 = blockIdx.y * 32;
    int tx = threadIdx.x;
    for (int j = threadIdx.y; j < 32; j += 8)
        t[j][tx] = W[(long long)(k0 + j) * Nd + n0 + tx];        // t[k][n]
    __syncthreads();
    for (int j = threadIdx.y; j < 16; j += 8) {
        int n  = j * 2 + (tx >> 4);       // 0..31
        int kk = (tx & 15) * 2;           // 0..30
        float v0 = t[kk][n], v1 = t[kk + 1][n];
        long long o = (long long)(n0 + n) * Kd + k0 + kk;
        bf16 h0, l0, h1, l1;
        split2(v0, h0, l0); split2(v1, h1, l1);
        *(__nv_bfloat162*)(Th + o) = mkbf2(h0, h1);
        *(__nv_bfloat162*)(Tl + o) = mkbf2(l0, l1);
    }
}
__global__ void k_ln_mod_split(const float* __restrict__ x, const float* __restrict__ em,
                               bf16* __restrict__ oh, bf16* __restrict__ ol,
                               int scaleRow, int shiftRow) {
    int row = blockIdx.x, b = row / Ss, t = threadIdx.x;
    const float* xr = x + (long long)row * Dd;
    const float* es = em + ((long long)b * 6 + scaleRow) * Dd;
    const float* eh = em + ((long long)b * 6 + shiftRow) * Dd;
    float v[8];
    float4 a0 = *(const float4*)(xr + t * 8);
    float4 a1 = *(const float4*)(xr + t * 8 + 4);
    v[0]=a0.x; v[1]=a0.y; v[2]=a0.z; v[3]=a0.w; v[4]=a1.x; v[5]=a1.y; v[6]=a1.z; v[7]=a1.w;
    float s = 0.f, s2 = 0.f;
#pragma unroll
    for (int i = 0; i < 8; i++) { s += v[i]; s2 += v[i] * v[i]; }
    __shared__ float sh[512];
    sh[t] = s; sh[256 + t] = s2;
    __syncthreads();
    for (int o = 128; o > 0; o >>= 1) {
        if (t < o) { sh[t] += sh[t + o]; sh[256 + t] += sh[256 + t + o]; }
        __syncthreads();
    }
    float m = sh[0] * (1.f / Dd);
    float var = sh[256] * (1.f / Dd) - m * m;
    float r = rsqrtf(var + EPSf);
    bf16 hh[8], ll[8];
#pragma unroll
    for (int i = 0; i < 8; i++) {
        int dI = t * 8 + i;
        float u = (v[i] - m) * r * (1.f + es[dI]) + eh[dI];
        split2(u, hh[i], ll[i]);
    }
    long long ob = (long long)row * Dd + t * 8;
#pragma unroll
    for (int i = 0; i < 8; i += 2) {
        *(__nv_bfloat162*)(oh + ob + i) = mkbf2(hh[i], hh[i + 1]);
        *(__nv_bfloat162*)(ol + ob + i) = mkbf2(ll[i], ll[i + 1]);
    }
}
__global__ void k_rms_rope_split(const float* __restrict__ in, int ldin, int off,
                                 const float* __restrict__ w, const float* __restrict__ freqs,
                                 bf16* __restrict__ oh, bf16* __restrict__ ol, int Sv) {
    int row = blockIdx.x, b = row / Sv, s = row % Sv, t = threadIdx.x;
    const float* xr = in + (long long)row * ldin + off;
    float v[8];
    float4 a0 = *(const float4*)(xr + t * 8);
    float4 a1 = *(const float4*)(xr + t * 8 + 4);
    v[0]=a0.x; v[1]=a0.y; v[2]=a0.z; v[3]=a0.w; v[4]=a1.x; v[5]=a1.y; v[6]=a1.z; v[7]=a1.w;
    float s2 = 0.f;
#pragma unroll
    for (int i = 0; i < 8; i++) s2 += v[i] * v[i];
    __shared__ float sh[256];
    sh[t] = s2;
    __syncthreads();
    for (int o = 128; o > 0; o >>= 1) {
        if (t < o) sh[t] += sh[t + o];
        __syncthreads();
    }
    float r = rsqrtf(sh[0] * (1.f / Dd) + EPSf);
    int dbase = t * 8, h = dbase >> 7, dd = dbase & 127;
    float u[8];
#pragma unroll
    for (int i = 0; i < 8; i++) u[i] = v[i] * r * w[dbase + i];
    if (freqs) {
#pragma unroll
        for (int pr = 0; pr < 4; pr++) {
            float sn, cs;
            __sincosf(freqs[s * 64 + (dd >> 1) + pr], &sn, &cs);
            float xr_ = u[2 * pr], xi = u[2 * pr + 1];
            u[2 * pr]     = xr_ * cs - xi * sn;
            u[2 * pr + 1] = xr_ * sn + xi * cs;
        }
    }
    long long ob = ((long long)(b * Hh + h) * Sv + s) * 128 + dd;
    bf16 hh[8], ll[8];
#pragma unroll
    for (int i = 0; i < 8; i++) split2(u[i], hh[i], ll[i]);
#pragma unroll
    for (int i = 0; i < 8; i += 2) {
        *(__nv_bfloat162*)(oh + ob + i) = mkbf2(hh[i], hh[i + 1]);
        *(__nv_bfloat162*)(ol + ob + i) = mkbf2(ll[i], ll[i + 1]);
    }
}
// V transpose+split: in[b, s, off + h*128 + d] -> out[((b*H+h)*128+d)*Sv + s]
__global__ void k_vt_split(const float* __restrict__ in, int ldin, int off,
                           bf16* __restrict__ oh, bf16* __restrict__ ol, int Sv) {
    __shared__ float t[32][33];
    int bh = blockIdx.z, b = bh >> 4, h = bh & 15;
    int s0 = blockIdx.x * 32, d0 = blockIdx.y * 32;
    int tx = threadIdx.x;
    for (int j = threadIdx.y; j < 32; j += 8)
        t[j][tx] = in[(long long)(b * Sv + s0 + j) * ldin + off + h * 128 + d0 + tx]; // t[s][d]
    __syncthreads();
    for (int j = threadIdx.y; j < 16; j += 8) {
        int d  = j * 2 + (tx >> 4);
        int ss = (tx & 15) * 2;
        float v0 = t[ss][d], v1 = t[ss + 1][d];
        long long o = (long long)(bh * 128 + d0 + d) * Sv + s0 + ss;
        bf16 h0, l0, h1, l1;
        split2(v0, h0, l0); split2(v1, h1, l1);
        *(__nv_bfloat162*)(oh + o) = mkbf2(h0, h1);
        *(__nv_bfloat162*)(ol + o) = mkbf2(l0, l1);
    }
}
// softmax: coalesced AND vectorized — thread t owns elements {2t, 2t+1} + k*512
__global__ void k_softmax_split(const float* __restrict__ S, bf16* __restrict__ oh,
                                bf16* __restrict__ ol, int ncols, float scale) {
    long long row = blockIdx.x;
    const float* p = S + row * ncols;
    bf16* Hp = oh + row * ncols;
    bf16* Lp = ol + row * ncols;
    int t = threadIdx.x;
    int np = ncols >> 9;                 // float2 per thread: 4 (self) / 1 (cross)
    float2 vv[4];
    float lm = -3.4e38f;
    for (int k = 0; k < np; k++) {
        vv[k] = *(const float2*)(p + (k << 9) + 2 * t);
        lm = fmaxf(lm, fmaxf(vv[k].x, vv[k].y));
    }
    __shared__ float sh[256];
    sh[t] = lm; __syncthreads();
    for (int o = 128; o > 0; o >>= 1) { if (t < o) sh[t] = fmaxf(sh[t], sh[t + o]); __syncthreads(); }
    float m = sh[0] * scale;
    __syncthreads();
    float ls = 0.f;
    for (int k = 0; k < np; k++) {
        float e0 = __expf(vv[k].x * scale - m);
        float e1 = __expf(vv[k].y * scale - m);
        vv[k].x = e0; vv[k].y = e1; ls += e0 + e1;
    }
    sh[t] = ls; __syncthreads();
    for (int o = 128; o > 0; o >>= 1) { if (t < o) sh[t] += sh[t + o]; __syncthreads(); }
    float inv = 1.f / sh[0];
    for (int k = 0; k < np; k++) {
        bf16 h0, l0, h1, l1;
        split2(vv[k].x * inv, h0, l0);
        split2(vv[k].y * inv, h1, l1);
        *(__nv_bfloat162*)(Hp + (k << 9) + 2 * t) = mkbf2(h0, h1);
        *(__nv_bfloat162*)(Lp + (k << 9) + 2 * t) = mkbf2(l0, l1);
    }
}

// ---------------------------------------------------------------------------
// Host orchestration
// ---------------------------------------------------------------------------
static void gemm(int epi, const bf16* Ah, const bf16* Al, const bf16* Bh, const bf16* Bl,
                 int M, int N, int K, int lda, int ldb,
                 float* C, bf16* Ch, bf16* Cl, int ldc,
                 const float* b0, const float* b1, const float* b2,
                 const float* em, int gateRow,
                 int batch, int Hdiv,
                 long long sAb, long long sAh, long long sBb, long long sBh,
                 long long sCb, long long sCh)
{
    dim3 g(N / 128, M / 128, batch), bl(256);
    size_t sm = SMEM_TOTAL_G;
    if (epi == 0)
        mma_gemm<0><<<g, bl, sm>>>(Ah, Al, Bh, Bl, K, lda, ldb, C, Ch, Cl, ldc,
                                   b0, b1, b2, em, gateRow, Hdiv, sAb, sAh, sBb, sBh, sCb, sCh);
    else if (epi == 1)
        mma_gemm<1><<<g, bl, sm>>>(Ah, Al, Bh, Bl, K, lda, ldb, C, Ch, Cl, ldc,
                                   b0, b1, b2, em, gateRow, Hdiv, sAb, sAh, sBb, sBh, sCb, sCh);
    else
        mma_gemm<2><<<g, bl, sm>>>(Ah, Al, Bh, Bl, K, lda, ldb, C, Ch, Cl, ldc,
                                   b0, b1, b2, em, gateRow, Hdiv, sAb, sAh, sBb, sBh, sCb, sCh);
}

#define SYM(p, s) cudaGetSymbolAddress((void**)&p, s)

extern "C" void kernel_launch(void* const* d_in, const int* in_sizes, int n_in,
                              void* d_out, int out_size)
{
    bool sig = (in_sizes[13] == Dd);
    int I_snq, I_snk, I_cq_w, I_cq_b, I_ck_w, I_ck_b, I_cv_w, I_cv_b;
    int I_co_w, I_co_b, I_cnq, I_cnk, I_f1_w, I_f1_b, I_f2_w, I_f2_b;
    if (sig) {
        I_snq=13; I_snk=14; I_cq_w=15; I_cq_b=16; I_ck_w=17; I_ck_b=18;
        I_cv_w=19; I_cv_b=20; I_co_w=21; I_co_b=22; I_cnq=23; I_cnk=24;
        I_f1_w=25; I_f1_b=26; I_f2_w=27; I_f2_b=28;
    } else {
        I_cq_w=13; I_cq_b=14; I_ck_w=15; I_ck_b=16; I_cv_w=17; I_cv_b=18;
        I_co_w=19; I_co_b=20; I_f1_w=21; I_f1_b=22; I_f2_w=23; I_f2_b=24;
        I_snq=25; I_snk=26; I_cnq=27; I_cnk=28;
    }
    const float* x    = (const float*)d_in[0];
    const float* e    = (const float*)d_in[1];
    const float* ctx  = (const float*)d_in[2];
    const float* fr   = (const float*)d_in[3];
    const float* mod  = (const float*)d_in[4];
    const float* sq_w = (const float*)d_in[5];  const float* sq_b = (const float*)d_in[6];
    const float* sk_w = (const float*)d_in[7];  const float* sk_b = (const float*)d_in[8];
    const float* sv_w = (const float*)d_in[9];  const float* sv_b = (const float*)d_in[10];
    const float* so_w = (const float*)d_in[11]; const float* so_b = (const float*)d_in[12];
    const float* snq  = (const float*)d_in[I_snq];  const float* snk  = (const float*)d_in[I_snk];
    const float* cq_w = (const float*)d_in[I_cq_w]; const float* cq_b = (const float*)d_in[I_cq_b];
    const float* ck_w = (const float*)d_in[I_ck_w]; const float* ck_b = (const float*)d_in[I_ck_b];
    const float* cv_w = (const float*)d_in[I_cv_w]; const float* cv_b = (const float*)d_in[I_cv_b];
    const float* co_w = (const float*)d_in[I_co_w]; const float* co_b = (const float*)d_in[I_co_b];
    const float* cnq  = (const float*)d_in[I_cnq];  const float* cnk  = (const float*)d_in[I_cnk];
    const float* f1_w = (const float*)d_in[I_f1_w]; const float* f1_b = (const float*)d_in[I_f1_b];
    const float* f2_w = (const float*)d_in[I_f2_w]; const float* f2_b = (const float*)d_in[I_f2_b];

    cudaFuncSetAttribute(mma_gemm<0>, cudaFuncAttributeMaxDynamicSharedMemorySize, SMEM_TOTAL_G);
    cudaFuncSetAttribute(mma_gemm<1>, cudaFuncAttributeMaxDynamicSharedMemorySize, SMEM_TOTAL_G);
    cudaFuncSetAttribute(mma_gemm<2>, cudaFuncAttributeMaxDynamicSharedMemorySize, SMEM_TOTAL_G);

    float *em_, *qkv, *y, *sc;
    SYM(em_, g_em); SYM(qkv, g_qkv); SYM(y, g_y); SYM(sc, g_sc);
    bf16 *txh, *txl, *cxh, *cxl, *qh, *ql, *kh, *kl, *vth, *vtl, *ph_, *pl_, *fh, *fl;
    SYM(txh, g_txh); SYM(txl, g_txl); SYM(cxh, g_cxh); SYM(cxl, g_cxl);
    SYM(qh, g_qh); SYM(ql, g_ql); SYM(kh, g_kh); SYM(kl, g_kl);
    SYM(vth, g_vth); SYM(vtl, g_vtl); SYM(ph_, g_ph); SYM(pl_, g_pl);
    SYM(fh, g_fh); SYM(fl, g_fl);
    bf16 *wqkvh, *wqkvl, *wckvh, *wckvl, *woh, *wol, *wcqh, *wcql, *wcoh, *wcol, *wf1h, *wf1l, *wf2h, *wf2l;
    SYM(wqkvh, g_wqkvh); SYM(wqkvl, g_wqkvl); SYM(wckvh, g_wckvh); SYM(wckvl, g_wckvl);
    SYM(woh, g_woh); SYM(wol, g_wol); SYM(wcqh, g_wcqh); SYM(wcql, g_wcql);
    SYM(wcoh, g_wcoh); SYM(wcol, g_wcol); SYM(wf1h, g_wf1h); SYM(wf1l, g_wf1l);
    SYM(wf2h, g_wf2h); SYM(wf2l, g_wf2l);

    float* xo = (float*)d_out;
    const long long NX = (long long)Bb * Ss * Dd;
    const long long DD = (long long)Dd * Dd;
    const long long SD = (long long)Ss * Dd;
    const long long SS2 = (long long)Ss * Ss;
    const long long SL = (long long)Ss * LCc;
    const float SCALE = 0.08838834764831845f;
    dim3 tb(32, 8);

    // ---- launches 1-5 arranged so the ncu capture slot (my #4/#5) is the Q GEMM
    k_emadd<<<(Bb * 6 * Dd + 255) / 256, 256>>>(e, mod, em_);                           // 1
    k_ln_mod_split<<<Bb * Ss, 256>>>(x, em_, txh, txl, 1, 0);                           // 2
    k_tsplit<<<dim3(Dd/32, Dd/32), tb>>>(sq_w, wqkvh, wqkvl, Dd, Dd);                   // 3
    gemm(0, txh, txl, wqkvh, wqkvl, Bb*Ss, Dd, Dd, Dd, Dd,                              // 4 <- capture
         qkv, nullptr, nullptr, 3*Dd, sq_b, nullptr, nullptr, nullptr, -1, 1, 1, 0,0,0,0,0,0);
    gemm(0, txh, txl, wqkvh, wqkvl, Bb*Ss, Dd, Dd, Dd, Dd,                              // 5 <- capture (idempotent dup)
         qkv, nullptr, nullptr, 3*Dd, sq_b, nullptr, nullptr, nullptr, -1, 1, 1, 0,0,0,0,0,0);
    k_tsplit<<<dim3(Dd/32, Dd/32), tb>>>(sk_w, wqkvh + DD,     wqkvl + DD,     Dd, Dd); // 6
    k_tsplit<<<dim3(Dd/32, Dd/32), tb>>>(sv_w, wqkvh + 2 * DD, wqkvl + 2 * DD, Dd, Dd);
    gemm(0, txh, txl, wqkvh + DD, wqkvl + DD, Bb*Ss, 2*Dd, Dd, Dd, Dd,                  // K,V fused
         qkv + Dd, nullptr, nullptr, 3*Dd, sk_b, sv_b, nullptr, nullptr, -1, 1, 1, 0,0,0,0,0,0);

    k_copy<<<(int)((NX + 255) / 256), 256>>>(x, xo, NX);
    k_tsplit<<<dim3(Dd/32, Dd/32), tb>>>(so_w, woh,  wol,  Dd, Dd);
    k_tsplit<<<dim3(Dd/32, Dd/32), tb>>>(cq_w, wcqh, wcql, Dd, Dd);
    k_tsplit<<<dim3(Dd/32, Dd/32), tb>>>(ck_w, wckvh,      wckvl,      Dd, Dd);
    k_tsplit<<<dim3(Dd/32, Dd/32), tb>>>(cv_w, wckvh + DD, wckvl + DD, Dd, Dd);
    k_tsplit<<<dim3(Dd/32, Dd/32), tb>>>(co_w, wcoh, wcol, Dd, Dd);
    k_tsplit<<<dim3(Ff/32, Dd/32), tb>>>(f1_w, wf1h, wf1l, Dd, Ff);
    k_tsplit<<<dim3(Dd/32, Ff/32), tb>>>(f2_w, wf2h, wf2l, Ff, Dd);

    // ===================== self attention =====================
    k_rms_rope_split<<<Bb * Ss, 256>>>(qkv, 3*Dd, 0,  snq, fr, qh, ql, Ss);
    k_rms_rope_split<<<Bb * Ss, 256>>>(qkv, 3*Dd, Dd, snk, fr, kh, kl, Ss);
    k_vt_split<<<dim3(Ss/32, 4, Bb*Hh), tb>>>(qkv, 3*Dd, 2*Dd, vth, vtl, Ss);
    gemm(0, qh, ql, kh, kl, Ss, Ss, HDd, HDd, HDd,
         sc, nullptr, nullptr, Ss, nullptr, nullptr, nullptr, nullptr, -1, Bb*Hh, 1,
         (long long)Ss*HDd, 0, (long long)Ss*HDd, 0, SS2, 0);
    k_softmax_split<<<Bb * Hh * Ss, 256>>>(sc, ph_, pl_, Ss, SCALE);
    gemm(0, ph_, pl_, vth, vtl, Ss, HDd, Ss, Ss, Ss,
         y, nullptr, nullptr, Dd, nullptr, nullptr, nullptr, nullptr, -1, Bb*Hh, Hh,
         (long long)Hh*SS2, SS2, (long long)Hh*HDd*Ss, (long long)HDd*Ss, SD, HDd);
    k_split4<<<(int)(NX / 1024), 256>>>(y, txh, txl, NX);
    gemm(2, txh, txl, woh, wol, Bb*Ss, Dd, Dd, Dd, Dd,
         xo, nullptr, nullptr, Dd, so_b, nullptr, nullptr, em_, 2, 1, 1, 0,0,0,0,0,0);

    // ===================== cross attention =====================
    k_split4<<<(int)(NX / 1024), 256>>>(xo, txh, txl, NX);
    gemm(0, txh, txl, wcqh, wcql, Bb*Ss, Dd, Dd, Dd, Dd,
         qkv, nullptr, nullptr, Dd, cq_b, nullptr, nullptr, nullptr, -1, 1, 1, 0,0,0,0,0,0);
    k_rms_rope_split<<<Bb * Ss, 256>>>(qkv, Dd, 0, cnq, nullptr, qh, ql, Ss);
    k_split4<<<(int)((long long)Bb*LCc*Dd / 1024), 256>>>(ctx, cxh, cxl, (long long)Bb*LCc*Dd);
    gemm(0, cxh, cxl, wckvh, wckvl, Bb*LCc, 2*Dd, Dd, Dd, Dd,
         qkv, nullptr, nullptr, 2*Dd, ck_b, cv_b, nullptr, nullptr, -1, 1, 1, 0,0,0,0,0,0);
    k_rms_rope_split<<<Bb * LCc, 256>>>(qkv, 2*Dd, 0, cnk, nullptr, kh, kl, LCc);
    k_vt_split<<<dim3(LCc/32, 4, Bb*Hh), tb>>>(qkv, 2*Dd, Dd, vth, vtl, LCc);
    gemm(0, qh, ql, kh, kl, Ss, LCc, HDd, HDd, HDd,
         sc, nullptr, nullptr, LCc, nullptr, nullptr, nullptr, nullptr, -1, Bb*Hh, 1,
         (long long)Ss*HDd, 0, (long long)LCc*HDd, 0, SL, 0);
    k_softmax_split<<<Bb * Hh * Ss, 256>>>(sc, ph_, pl_, LCc, SCALE);
    gemm(0, ph_, pl_, vth, vtl, Ss, HDd, LCc, LCc, LCc,
         y, nullptr, nullptr, Dd, nullptr, nullptr, nullptr, nullptr, -1, Bb*Hh, Hh,
         (long long)Hh*SL, SL, (long long)Hh*HDd*LCc, (long long)HDd*LCc, SD, HDd);
    k_split4<<<(int)(NX / 1024), 256>>>(y, txh, txl, NX);
    gemm(2, txh, txl, wcoh, wcol, Bb*Ss, Dd, Dd, Dd, Dd,
         xo, nullptr, nullptr, Dd, co_b, nullptr, nullptr, em_, -1, 1, 1, 0,0,0,0,0,0);

    // ===================== FFN =====================
    k_ln_mod_split<<<Bb * Ss, 256>>>(xo, em_, txh, txl, 4, 3);
    gemm(1, txh, txl, wf1h, wf1l, Bb*Ss, Ff, Dd, Dd, Dd,
         nullptr, fh, fl, Ff, f1_b, nullptr, nullptr, nullptr, -1, 1, 1, 0,0,0,0,0,0);
    gemm(2, fh, fl, wf2h, wf2l, Bb*Ss, Dd, Ff, Ff, Ff,
         xo, nullptr, nullptr, Dd, f2_b, nullptr, nullptr, em_, 5, 1, 1, 0,0,0,0,0,0);
}

// round 7
// speedup vs baseline: 1.7762x; 1.1727x over previous
#include <cuda_runtime.h>
#include <cuda_bf16.h>
#include <cstdint>

using bf16 = __nv_bfloat16;

#define Bb  2
#define Ss  2048
#define Dd  2048
#define Hh  16
#define HDd 128
#define Ff  8192
#define LCc 512
#define EPSf 1e-6f

// ---------------------------------------------------------------------------
// Scratch (__device__ globals; allocation-free rule)
// ---------------------------------------------------------------------------
__device__ float g_em [Bb * 6 * Dd];
__device__ float g_qkv [(size_t)Bb * Ss * 3 * Dd];
__device__ float g_y   [(size_t)Bb * Ss * Dd];
__device__ float g_sc  [(size_t)Bb * Hh * Ss * Ss];

#define DECL2(nm, n) __device__ __align__(128) bf16 nm##h[(size_t)(n)]; __device__ __align__(128) bf16 nm##l[(size_t)(n)];
DECL2(g_tx, (size_t)Bb*Ss*Dd)
DECL2(g_cx, (size_t)Bb*LCc*Dd)
DECL2(g_q,  (size_t)Bb*Ss*Dd)
DECL2(g_k,  (size_t)Bb*Ss*Dd)
DECL2(g_vt, (size_t)Bb*Ss*Dd)
DECL2(g_p,  (size_t)Bb*Hh*Ss*Ss)
DECL2(g_f,  (size_t)Bb*Ss*Ff)
DECL2(g_wqkv, (size_t)3*Dd*Dd)
DECL2(g_wckv, (size_t)2*Dd*Dd)
DECL2(g_wo,   (size_t)Dd*Dd)
DECL2(g_wcq,  (size_t)Dd*Dd)
DECL2(g_wco,  (size_t)Dd*Dd)
DECL2(g_wf1,  (size_t)Ff*Dd)
DECL2(g_wf2,  (size_t)Dd*Ff)

// ---------------------------------------------------------------------------
// helpers
// ---------------------------------------------------------------------------
__device__ __forceinline__ uint32_t smem_u32(const void* p) {
    uint32_t a;
    asm("{ .reg .u64 t; cvta.to.shared.u64 t, %1; cvt.u32.u64 %0, t; }" : "=r"(a) : "l"(p));
    return a;
}
#define CP_COMMIT() asm volatile("cp.async.commit_group;" ::: "memory")

#define LDSM4(d, a) \
  asm volatile("ldmatrix.sync.aligned.m8n8.x4.shared.b16 {%0,%1,%2,%3}, [%4];" \
    : "=r"((d)[0]), "=r"((d)[1]), "=r"((d)[2]), "=r"((d)[3]) : "r"(a))

#define MMA16816(c, a, b0, b1) \
  asm volatile("mma.sync.aligned.m16n8k16.row.col.f32.bf16.bf16.f32 " \
    "{%0,%1,%2,%3}, {%4,%5,%6,%7}, {%8,%9}, {%0,%1,%2,%3};" \
    : "+f"((c)[0]), "+f"((c)[1]), "+f"((c)[2]), "+f"((c)[3]) \
    : "r"((a)[0]), "r"((a)[1]), "r"((a)[2]), "r"((a)[3]), "r"(b0), "r"(b1))

__device__ __forceinline__ float gelu_t(float x) {
    float x3 = x * x * x;
    return 0.5f * x * (1.f + tanhf(0.7978845608028654f * (x + 0.044715f * x3)));
}
__device__ __forceinline__ void split2(float v, bf16& h, bf16& l) {
    h = __float2bfloat16(v);
    l = __float2bfloat16(v - __bfloat162float(h));
}
__device__ __forceinline__ __nv_bfloat162 mkbf2(bf16 a, bf16 b) {
    __nv_bfloat162 r; r.x = a; r.y = b; return r;
}
// segmented bias: segments of 2048 columns (b1 null -> single segment b0)
__device__ __forceinline__ float bget(const float* b0, const float* b1,
                                      const float* b2, int c) {
    if (b1 == nullptr) return b0 ? b0[c] : 0.f;
    int seg = c >> 11, off = c & 2047;
    const float* bp = (seg == 0) ? b0 : ((seg == 1) ? b1 : b2);
    return bp[off];
}

// stage: Ah(10240) Al(10240) Bh(10240) Bl(10240); 80B row pitch, 128 rows, 32 bf16 cols
#define STAGE_BYTES 40960u
#define SMEM_TOTAL_G (2 * 40960)

// ---------------------------------------------------------------------------
// HMMA (mma.sync) GEMM: C(MxN) = A(MxK) @ B^T, B stored [N x K], bf16 hi/lo
// 3-term bf16x3 into fp32 acc. 2-stage pipeline, 2 CTAs/SM (the R6 profile
// showed 1 CTA/SM -> tensor pipe 40% with issue 23%; cross-CTA overlap is
// the fix). EPI: 0 fp32(+bias); 1 gelu->bf16 h/l(+bias); 2 xo += (acc+bias)*gate
// ---------------------------------------------------------------------------
template <int EPI>
__global__ __launch_bounds__(256, 2)
void mma_gemm(const bf16* __restrict__ Ah, const bf16* __restrict__ Al,
              const bf16* __restrict__ Bh, const bf16* __restrict__ Bl,
              int K, int lda, int ldb,
              float* C, bf16* Ch, bf16* Cl, int ldc,
              const float* __restrict__ bias0, const float* __restrict__ bias1,
              const float* __restrict__ bias2,
              const float* __restrict__ em, int gateRow,
              int Hdiv,
              long long sAb, long long sAh_, long long sBb, long long sBh_,
              long long sCb, long long sCh_)
{
    extern __shared__ __align__(128) char smem[];
    const uint32_t sbase = smem_u32(smem);
    const int tid = threadIdx.x;
    const int w = tid >> 5, l = tid & 31;
    const int wm = w >> 2, wn = w & 3;          // 2 x 4 warp grid, warp tile 64x32

    const int z = blockIdx.z;
    const int zb = z / Hdiv, zh = z - zb * Hdiv;
    Ah += zb * sAb + zh * sAh_;  Al += zb * sAb + zh * sAh_;
    Bh += zb * sBb + zh * sBh_;  Bl += zb * sBb + zh * sBh_;
    const long long coff = zb * sCb + zh * sCh_;
    const int m0 = blockIdx.y * 128, n0 = blockIdx.x * 128;

    float acc[4][4][4];
#pragma unroll
    for (int i = 0; i < 4; i++)
#pragma unroll
        for (int j = 0; j < 4; j++)
#pragma unroll
            for (int r = 0; r < 4; r++) acc[i][j][r] = 0.f;

    auto load_chunk = [&](int kc, int stg) {
        const uint32_t sb = sbase + (uint32_t)stg * STAGE_BYTES;
        auto one = [&](const bf16* p, int r0, int ld, uint32_t off) {
#pragma unroll
            for (int it = 0; it < 2; it++) {
                int c = tid + it * 256;             // 0..511
                int r = c >> 2, c16 = c & 3;
                const char* g = (const char*)(p + (long long)(r0 + r) * ld + kc * 32) + c16 * 16;
                asm volatile("cp.async.cg.shared.global [%0], [%1], 16;"
                             :: "r"(sb + off + (uint32_t)(r * 80 + c16 * 16)), "l"(g));
            }
        };
        one(Ah, m0, lda, 0u);      one(Al, m0, lda, 10240u);
        one(Bh, n0, ldb, 20480u);  one(Bl, n0, ldb, 30720u);
        CP_COMMIT();
    };

    const uint32_t lrow  = (uint32_t)(l & 15) * 80u;
    const uint32_t lhalf = (uint32_t)(l >> 4) * 16u;

    // register-lean term sequencing: aH,bH -> t1; aL -> t2; bL -> t3
    auto compute = [&](int stg) {
        const uint32_t sb = sbase + (uint32_t)stg * STAGE_BYTES;
#pragma unroll
        for (int ks = 0; ks < 2; ks++) {
            const uint32_t kb = (uint32_t)ks * 32u + lhalf;
            uint32_t aH[4][4], bH[2][4], tmp[4][4];
            uint32_t ra[4], rb[2];
#pragma unroll
            for (int mt = 0; mt < 4; mt++) {
                ra[mt] = sb + (uint32_t)((wm * 64 + mt * 16) * 80) + lrow + kb;
                LDSM4(aH[mt], ra[mt]);
            }
#pragma unroll
            for (int bt = 0; bt < 2; bt++) {
                rb[bt] = sb + 20480u + (uint32_t)((wn * 32 + bt * 16) * 80) + lrow + kb;
                LDSM4(bH[bt], rb[bt]);
            }
#pragma unroll
            for (int mt = 0; mt < 4; mt++)
#pragma unroll
                for (int nt = 0; nt < 4; nt++) {
                    const int bt = nt >> 1, hi = nt & 1;
                    MMA16816(acc[mt][nt], aH[mt], bH[bt][hi], bH[bt][hi + 2]);
                }
#pragma unroll
            for (int mt = 0; mt < 4; mt++) LDSM4(tmp[mt], ra[mt] + 10240u);   // aL
#pragma unroll
            for (int mt = 0; mt < 4; mt++)
#pragma unroll
                for (int nt = 0; nt < 4; nt++) {
                    const int bt = nt >> 1, hi = nt & 1;
                    MMA16816(acc[mt][nt], tmp[mt], bH[bt][hi], bH[bt][hi + 2]);
                }
#pragma unroll
            for (int bt = 0; bt < 2; bt++) LDSM4(tmp[bt], rb[bt] + 10240u);   // bL
#pragma unroll
            for (int mt = 0; mt < 4; mt++)
#pragma unroll
                for (int nt = 0; nt < 4; nt++) {
                    const int bt = nt >> 1, hi = nt & 1;
                    MMA16816(acc[mt][nt], aH[mt], tmp[bt][hi], tmp[bt][hi + 2]);
                }
        }
    };

    const int nk = K / 32;
    load_chunk(0, 0);
    for (int i = 0; i < nk; i++) {
        if (i + 1 < nk) {
            load_chunk(i + 1, (i + 1) & 1);
            asm volatile("cp.async.wait_group 1;" ::: "memory");
        } else {
            asm volatile("cp.async.wait_group 0;" ::: "memory");
        }
        __syncthreads();
        compute(i & 1);
        __syncthreads();
    }

    // ---------------- epilogue ----------------
    const int r0f = l >> 2, c0f = (l & 3) * 2;
#pragma unroll
    for (int mt = 0; mt < 4; mt++) {
        const int gr = m0 + wm * 64 + mt * 16 + r0f;
#pragma unroll
        for (int nt = 0; nt < 4; nt++) {
            const int gc = n0 + wn * 32 + nt * 8 + c0f;
            float a0 = acc[mt][nt][0], a1 = acc[mt][nt][1];
            float a2 = acc[mt][nt][2], a3 = acc[mt][nt][3];
            if (EPI == 0) {
                float bx = bget(bias0, bias1, bias2, gc);
                float by = bget(bias0, bias1, bias2, gc + 1);
                float2 u0; u0.x = a0 + bx; u0.y = a1 + by;
                float2 u1; u1.x = a2 + bx; u1.y = a3 + by;
                *(float2*)(C + coff + (long long)gr * ldc + gc) = u0;
                *(float2*)(C + coff + (long long)(gr + 8) * ldc + gc) = u1;
            } else if (EPI == 1) {
                float bx = bias0[gc], by = bias0[gc + 1];
                float v0 = gelu_t(a0 + bx), v1 = gelu_t(a1 + by);
                float v2 = gelu_t(a2 + bx), v3 = gelu_t(a3 + by);
                bf16 h0, l0, h1, l1;
                split2(v0, h0, l0); split2(v1, h1, l1);
                *(__nv_bfloat162*)(Ch + coff + (long long)gr * ldc + gc) = mkbf2(h0, h1);
                *(__nv_bfloat162*)(Cl + coff + (long long)gr * ldc + gc) = mkbf2(l0, l1);
                split2(v2, h0, l0); split2(v3, h1, l1);
                *(__nv_bfloat162*)(Ch + coff + (long long)(gr + 8) * ldc + gc) = mkbf2(h0, h1);
                *(__nv_bfloat162*)(Cl + coff + (long long)(gr + 8) * ldc + gc) = mkbf2(l0, l1);
            } else {
                float bx = bias0[gc], by = bias0[gc + 1];
#pragma unroll
                for (int hh = 0; hh < 2; hh++) {
                    const int row = gr + hh * 8;
                    float va = (hh ? a2 : a0) + bx;
                    float vb = (hh ? a3 : a1) + by;
                    if (gateRow >= 0) {
                        const int b = row / Ss;
                        const float* gp = em + ((long long)b * 6 + gateRow) * Dd;
                        va *= gp[gc]; vb *= gp[gc + 1];
                    }
                    float2 o = *(float2*)(C + coff + (long long)row * ldc + gc);
                    o.x += va; o.y += vb;
                    *(float2*)(C + coff + (long long)row * ldc + gc) = o;
                }
            }
        }
    }
}

// ---------------------------------------------------------------------------
// Elementwise kernels
// ---------------------------------------------------------------------------
__global__ void k_copy(const float* __restrict__ a, float* __restrict__ o, long long n) {
    long long i = (long long)blockIdx.x * 256 + threadIdx.x;
    if (i < n) o[i] = a[i];
}
__global__ void k_emadd(const float* __restrict__ e, const float* __restrict__ mod,
                        float* __restrict__ em) {
    int i = blockIdx.x * 256 + threadIdx.x;
    if (i < Bb * 6 * Dd) em[i] = e[i] + mod[i % (6 * Dd)];
}
__global__ void k_split4(const float* __restrict__ in, bf16* __restrict__ oh,
                         bf16* __restrict__ ol, long long n) {
    long long i = ((long long)blockIdx.x * 256 + threadIdx.x) * 4;
    if (i >= n) return;
    float4 v = *(const float4*)(in + i);
    bf16 h0, l0, h1, l1;
    split2(v.x, h0, l0); split2(v.y, h1, l1);
    *(__nv_bfloat162*)(oh + i) = mkbf2(h0, h1);
    *(__nv_bfloat162*)(ol + i) = mkbf2(l0, l1);
    split2(v.z, h0, l0); split2(v.w, h1, l1);
    *(__nv_bfloat162*)(oh + i + 2) = mkbf2(h0, h1);
    *(__nv_bfloat162*)(ol + i + 2) = mkbf2(l0, l1);
}
// transpose+split: W[K x N] -> T[N x K] bf16 h/l
__global__ void k_tsplit(const float* __restrict__ W, bf16* __restrict__ Th,
                         bf16* __restrict__ Tl, int Kd, int Nd) {
    __shared__ float t[32][33];
    int n0 = blockIdx.x * 32, k0 = blockIdx.y * 32;
    int tx = threadIdx.x;
    for (int j = threadIdx.y; j < 32; j += 8)
        t[j][tx] = W[(long long)(k0 + j) * Nd + n0 + tx];        // t[k][n]
    __syncthreads();
    for (int j = threadIdx.y; j < 16; j += 8) {
        int n  = j * 2 + (tx >> 4);       // 0..31
        int kk = (tx & 15) * 2;           // 0..30
        float v0 = t[kk][n], v1 = t[kk + 1][n];
        long long o = (long long)(n0 + n) * Kd + k0 + kk;
        bf16 h0, l0, h1, l1;
        split2(v0, h0, l0); split2(v1, h1, l1);
        *(__nv_bfloat162*)(Th + o) = mkbf2(h0, h1);
        *(__nv_bfloat162*)(Tl + o) = mkbf2(l0, l1);
    }
}
__global__ void k_ln_mod_split(const float* __restrict__ x, const float* __restrict__ em,
                               bf16* __restrict__ oh, bf16* __restrict__ ol,
                               int scaleRow, int shiftRow) {
    int row = blockIdx.x, b = row / Ss, t = threadIdx.x;
    const float* xr = x + (long long)row * Dd;
    const float* es = em + ((long long)b * 6 + scaleRow) * Dd;
    const float* eh = em + ((long long)b * 6 + shiftRow) * Dd;
    float v[8];
    float4 a0 = *(const float4*)(xr + t * 8);
    float4 a1 = *(const float4*)(xr + t * 8 + 4);
    v[0]=a0.x; v[1]=a0.y; v[2]=a0.z; v[3]=a0.w; v[4]=a1.x; v[5]=a1.y; v[6]=a1.z; v[7]=a1.w;
    float s = 0.f, s2 = 0.f;
#pragma unroll
    for (int i = 0; i < 8; i++) { s += v[i]; s2 += v[i] * v[i]; }
    __shared__ float sh[512];
    sh[t] = s; sh[256 + t] = s2;
    __syncthreads();
    for (int o = 128; o > 0; o >>= 1) {
        if (t < o) { sh[t] += sh[t + o]; sh[256 + t] += sh[256 + t + o]; }
        __syncthreads();
    }
    float m = sh[0] * (1.f / Dd);
    float var = sh[256] * (1.f / Dd) - m * m;
    float r = rsqrtf(var + EPSf);
    bf16 hh[8], ll[8];
#pragma unroll
    for (int i = 0; i < 8; i++) {
        int dI = t * 8 + i;
        float u = (v[i] - m) * r * (1.f + es[dI]) + eh[dI];
        split2(u, hh[i], ll[i]);
    }
    long long ob = (long long)row * Dd + t * 8;
#pragma unroll
    for (int i = 0; i < 8; i += 2) {
        *(__nv_bfloat162*)(oh + ob + i) = mkbf2(hh[i], hh[i + 1]);
        *(__nv_bfloat162*)(ol + ob + i) = mkbf2(ll[i], ll[i + 1]);
    }
}
__global__ void k_rms_rope_split(const float* __restrict__ in, int ldin, int off,
                                 const float* __restrict__ w, const float* __restrict__ freqs,
                                 bf16* __restrict__ oh, bf16* __restrict__ ol, int Sv) {
    int row = blockIdx.x, b = row / Sv, s = row % Sv, t = threadIdx.x;
    const float* xr = in + (long long)row * ldin + off;
    float v[8];
    float4 a0 = *(const float4*)(xr + t * 8);
    float4 a1 = *(const float4*)(xr + t * 8 + 4);
    v[0]=a0.x; v[1]=a0.y; v[2]=a0.z; v[3]=a0.w; v[4]=a1.x; v[5]=a1.y; v[6]=a1.z; v[7]=a1.w;
    float s2 = 0.f;
#pragma unroll
    for (int i = 0; i < 8; i++) s2 += v[i] * v[i];
    __shared__ float sh[256];
    sh[t] = s2;
    __syncthreads();
    for (int o = 128; o > 0; o >>= 1) {
        if (t < o) sh[t] += sh[t + o];
        __syncthreads();
    }
    float r = rsqrtf(sh[0] * (1.f / Dd) + EPSf);
    int dbase = t * 8, h = dbase >> 7, dd = dbase & 127;
    float u[8];
#pragma unroll
    for (int i = 0; i < 8; i++) u[i] = v[i] * r * w[dbase + i];
    if (freqs) {
#pragma unroll
        for (int pr = 0; pr < 4; pr++) {
            float sn, cs;
            __sincosf(freqs[s * 64 + (dd >> 1) + pr], &sn, &cs);
            float xr_ = u[2 * pr], xi = u[2 * pr + 1];
            u[2 * pr]     = xr_ * cs - xi * sn;
            u[2 * pr + 1] = xr_ * sn + xi * cs;
        }
    }
    long long ob = ((long long)(b * Hh + h) * Sv + s) * 128 + dd;
    bf16 hh[8], ll[8];
#pragma unroll
    for (int i = 0; i < 8; i++) split2(u[i], hh[i], ll[i]);
#pragma unroll
    for (int i = 0; i < 8; i += 2) {
        *(__nv_bfloat162*)(oh + ob + i) = mkbf2(hh[i], hh[i + 1]);
        *(__nv_bfloat162*)(ol + ob + i) = mkbf2(ll[i], ll[i + 1]);
    }
}
// V transpose+split: in[b, s, off + h*128 + d] -> out[((b*H+h)*128+d)*Sv + s]
__global__ void k_vt_split(const float* __restrict__ in, int ldin, int off,
                           bf16* __restrict__ oh, bf16* __restrict__ ol, int Sv) {
    __shared__ float t[32][33];
    int bh = blockIdx.z, b = bh >> 4, h = bh & 15;
    int s0 = blockIdx.x * 32, d0 = blockIdx.y * 32;
    int tx = threadIdx.x;
    for (int j = threadIdx.y; j < 32; j += 8)
        t[j][tx] = in[(long long)(b * Sv + s0 + j) * ldin + off + h * 128 + d0 + tx]; // t[s][d]
    __syncthreads();
    for (int j = threadIdx.y; j < 16; j += 8) {
        int d  = j * 2 + (tx >> 4);
        int ss = (tx & 15) * 2;
        float v0 = t[ss][d], v1 = t[ss + 1][d];
        long long o = (long long)(bh * 128 + d0 + d) * Sv + s0 + ss;
        bf16 h0, l0, h1, l1;
        split2(v0, h0, l0); split2(v1, h1, l1);
        *(__nv_bfloat162*)(oh + o) = mkbf2(h0, h1);
        *(__nv_bfloat162*)(ol + o) = mkbf2(l0, l1);
    }
}
// softmax: coalesced AND vectorized — thread t owns elements {2t, 2t+1} + k*512
__global__ void k_softmax_split(const float* __restrict__ S, bf16* __restrict__ oh,
                                bf16* __restrict__ ol, int ncols, float scale) {
    long long row = blockIdx.x;
    const float* p = S + row * ncols;
    bf16* Hp = oh + row * ncols;
    bf16* Lp = ol + row * ncols;
    int t = threadIdx.x;
    int np = ncols >> 9;                 // float2 per thread: 4 (self) / 1 (cross)
    float2 vv[4];
    float lm = -3.4e38f;
    for (int k = 0; k < np; k++) {
        vv[k] = *(const float2*)(p + (k << 9) + 2 * t);
        lm = fmaxf(lm, fmaxf(vv[k].x, vv[k].y));
    }
    __shared__ float sh[256];
    sh[t] = lm; __syncthreads();
    for (int o = 128; o > 0; o >>= 1) { if (t < o) sh[t] = fmaxf(sh[t], sh[t + o]); __syncthreads(); }
    float m = sh[0] * scale;
    __syncthreads();
    float ls = 0.f;
    for (int k = 0; k < np; k++) {
        float e0 = __expf(vv[k].x * scale - m);
        float e1 = __expf(vv[k].y * scale - m);
        vv[k].x = e0; vv[k].y = e1; ls += e0 + e1;
    }
    sh[t] = ls; __syncthreads();
    for (int o = 128; o > 0; o >>= 1) { if (t < o) sh[t] += sh[t + o]; __syncthreads(); }
    float inv = 1.f / sh[0];
    for (int k = 0; k < np; k++) {
        bf16 h0, l0, h1, l1;
        split2(vv[k].x * inv, h0, l0);
        split2(vv[k].y * inv, h1, l1);
        *(__nv_bfloat162*)(Hp + (k << 9) + 2 * t) = mkbf2(h0, h1);
        *(__nv_bfloat162*)(Lp + (k << 9) + 2 * t) = mkbf2(l0, l1);
    }
}

// ---------------------------------------------------------------------------
// Host orchestration
// ---------------------------------------------------------------------------
static void gemm(int epi, const bf16* Ah, const bf16* Al, const bf16* Bh, const bf16* Bl,
                 int M, int N, int K, int lda, int ldb,
                 float* C, bf16* Ch, bf16* Cl, int ldc,
                 const float* b0, const float* b1, const float* b2,
                 const float* em, int gateRow,
                 int batch, int Hdiv,
                 long long sAb, long long sAh, long long sBb, long long sBh,
                 long long sCb, long long sCh)
{
    dim3 g(N / 128, M / 128, batch), bl(256);
    size_t sm = SMEM_TOTAL_G;
    if (epi == 0)
        mma_gemm<0><<<g, bl, sm>>>(Ah, Al, Bh, Bl, K, lda, ldb, C, Ch, Cl, ldc,
                                   b0, b1, b2, em, gateRow, Hdiv, sAb, sAh, sBb, sBh, sCb, sCh);
    else if (epi == 1)
        mma_gemm<1><<<g, bl, sm>>>(Ah, Al, Bh, Bl, K, lda, ldb, C, Ch, Cl, ldc,
                                   b0, b1, b2, em, gateRow, Hdiv, sAb, sAh, sBb, sBh, sCb, sCh);
    else
        mma_gemm<2><<<g, bl, sm>>>(Ah, Al, Bh, Bl, K, lda, ldb, C, Ch, Cl, ldc,
                                   b0, b1, b2, em, gateRow, Hdiv, sAb, sAh, sBb, sBh, sCb, sCh);
}

#define SYM(p, s) cudaGetSymbolAddress((void**)&p, s)

extern "C" void kernel_launch(void* const* d_in, const int* in_sizes, int n_in,
                              void* d_out, int out_size)
{
    bool sig = (in_sizes[13] == Dd);
    int I_snq, I_snk, I_cq_w, I_cq_b, I_ck_w, I_ck_b, I_cv_w, I_cv_b;
    int I_co_w, I_co_b, I_cnq, I_cnk, I_f1_w, I_f1_b, I_f2_w, I_f2_b;
    if (sig) {
        I_snq=13; I_snk=14; I_cq_w=15; I_cq_b=16; I_ck_w=17; I_ck_b=18;
        I_cv_w=19; I_cv_b=20; I_co_w=21; I_co_b=22; I_cnq=23; I_cnk=24;
        I_f1_w=25; I_f1_b=26; I_f2_w=27; I_f2_b=28;
    } else {
        I_cq_w=13; I_cq_b=14; I_ck_w=15; I_ck_b=16; I_cv_w=17; I_cv_b=18;
        I_co_w=19; I_co_b=20; I_f1_w=21; I_f1_b=22; I_f2_w=23; I_f2_b=24;
        I_snq=25; I_snk=26; I_cnq=27; I_cnk=28;
    }
    const float* x    = (const float*)d_in[0];
    const float* e    = (const float*)d_in[1];
    const float* ctx  = (const float*)d_in[2];
    const float* fr   = (const float*)d_in[3];
    const float* mod  = (const float*)d_in[4];
    const float* sq_w = (const float*)d_in[5];  const float* sq_b = (const float*)d_in[6];
    const float* sk_w = (const float*)d_in[7];  const float* sk_b = (const float*)d_in[8];
    const float* sv_w = (const float*)d_in[9];  const float* sv_b = (const float*)d_in[10];
    const float* so_w = (const float*)d_in[11]; const float* so_b = (const float*)d_in[12];
    const float* snq  = (const float*)d_in[I_snq];  const float* snk  = (const float*)d_in[I_snk];
    const float* cq_w = (const float*)d_in[I_cq_w]; const float* cq_b = (const float*)d_in[I_cq_b];
    const float* ck_w = (const float*)d_in[I_ck_w]; const float* ck_b = (const float*)d_in[I_ck_b];
    const float* cv_w = (const float*)d_in[I_cv_w]; const float* cv_b = (const float*)d_in[I_cv_b];
    const float* co_w = (const float*)d_in[I_co_w]; const float* co_b = (const float*)d_in[I_co_b];
    const float* cnq  = (const float*)d_in[I_cnq];  const float* cnk  = (const float*)d_in[I_cnk];
    const float* f1_w = (const float*)d_in[I_f1_w]; const float* f1_b = (const float*)d_in[I_f1_b];
    const float* f2_w = (const float*)d_in[I_f2_w]; const float* f2_b = (const float*)d_in[I_f2_b];

    cudaFuncSetAttribute(mma_gemm<0>, cudaFuncAttributeMaxDynamicSharedMemorySize, SMEM_TOTAL_G);
    cudaFuncSetAttribute(mma_gemm<1>, cudaFuncAttributeMaxDynamicSharedMemorySize, SMEM_TOTAL_G);
    cudaFuncSetAttribute(mma_gemm<2>, cudaFuncAttributeMaxDynamicSharedMemorySize, SMEM_TOTAL_G);

    float *em_, *qkv, *y, *sc;
    SYM(em_, g_em); SYM(qkv, g_qkv); SYM(y, g_y); SYM(sc, g_sc);
    bf16 *txh, *txl, *cxh, *cxl, *qh, *ql, *kh, *kl, *vth, *vtl, *ph_, *pl_, *fh, *fl;
    SYM(txh, g_txh); SYM(txl, g_txl); SYM(cxh, g_cxh); SYM(cxl, g_cxl);
    SYM(qh, g_qh); SYM(ql, g_ql); SYM(kh, g_kh); SYM(kl, g_kl);
    SYM(vth, g_vth); SYM(vtl, g_vtl); SYM(ph_, g_ph); SYM(pl_, g_pl);
    SYM(fh, g_fh); SYM(fl, g_fl);
    bf16 *wqkvh, *wqkvl, *wckvh, *wckvl, *woh, *wol, *wcqh, *wcql, *wcoh, *wcol, *wf1h, *wf1l, *wf2h, *wf2l;
    SYM(wqkvh, g_wqkvh); SYM(wqkvl, g_wqkvl); SYM(wckvh, g_wckvh); SYM(wckvl, g_wckvl);
    SYM(woh, g_woh); SYM(wol, g_wol); SYM(wcqh, g_wcqh); SYM(wcql, g_wcql);
    SYM(wcoh, g_wcoh); SYM(wcol, g_wcol); SYM(wf1h, g_wf1h); SYM(wf1l, g_wf1l);
    SYM(wf2h, g_wf2h); SYM(wf2l, g_wf2l);

    float* xo = (float*)d_out;
    const long long NX = (long long)Bb * Ss * Dd;
    const long long DD = (long long)Dd * Dd;
    const long long SD = (long long)Ss * Dd;
    const long long SS2 = (long long)Ss * Ss;
    const long long SL = (long long)Ss * LCc;
    const float SCALE = 0.08838834764831845f;
    dim3 tb(32, 8);

    // ---- prep
    k_emadd<<<(Bb * 6 * Dd + 255) / 256, 256>>>(e, mod, em_);
    k_ln_mod_split<<<Bb * Ss, 256>>>(x, em_, txh, txl, 1, 0);
    k_tsplit<<<dim3(Dd/32, Dd/32), tb>>>(sq_w, wqkvh,          wqkvl,          Dd, Dd);
    k_tsplit<<<dim3(Dd/32, Dd/32), tb>>>(sk_w, wqkvh + DD,     wqkvl + DD,     Dd, Dd);
    k_tsplit<<<dim3(Dd/32, Dd/32), tb>>>(sv_w, wqkvh + 2 * DD, wqkvl + 2 * DD, Dd, Dd);
    gemm(0, txh, txl, wqkvh, wqkvl, Bb*Ss, 3*Dd, Dd, Dd, Dd,
         qkv, nullptr, nullptr, 3*Dd, sq_b, sk_b, sv_b, nullptr, -1, 1, 1, 0,0,0,0,0,0);

    k_copy<<<(int)((NX + 255) / 256), 256>>>(x, xo, NX);
    k_tsplit<<<dim3(Dd/32, Dd/32), tb>>>(so_w, woh,  wol,  Dd, Dd);
    k_tsplit<<<dim3(Dd/32, Dd/32), tb>>>(cq_w, wcqh, wcql, Dd, Dd);
    k_tsplit<<<dim3(Dd/32, Dd/32), tb>>>(ck_w, wckvh,      wckvl,      Dd, Dd);
    k_tsplit<<<dim3(Dd/32, Dd/32), tb>>>(cv_w, wckvh + DD, wckvl + DD, Dd, Dd);
    k_tsplit<<<dim3(Dd/32, Dd/32), tb>>>(co_w, wcoh, wcol, Dd, Dd);
    k_tsplit<<<dim3(Ff/32, Dd/32), tb>>>(f1_w, wf1h, wf1l, Dd, Ff);
    k_tsplit<<<dim3(Dd/32, Ff/32), tb>>>(f2_w, wf2h, wf2l, Ff, Dd);

    // ===================== self attention =====================
    k_rms_rope_split<<<Bb * Ss, 256>>>(qkv, 3*Dd, 0,  snq, fr, qh, ql, Ss);
    k_rms_rope_split<<<Bb * Ss, 256>>>(qkv, 3*Dd, Dd, snk, fr, kh, kl, Ss);
    k_vt_split<<<dim3(Ss/32, 4, Bb*Hh), tb>>>(qkv, 3*Dd, 2*Dd, vth, vtl, Ss);
    gemm(0, qh, ql, kh, kl, Ss, Ss, HDd, HDd, HDd,
         sc, nullptr, nullptr, Ss, nullptr, nullptr, nullptr, nullptr, -1, Bb*Hh, 1,
         (long long)Ss*HDd, 0, (long long)Ss*HDd, 0, SS2, 0);
    k_softmax_split<<<Bb * Hh * Ss, 256>>>(sc, ph_, pl_, Ss, SCALE);
    gemm(0, ph_, pl_, vth, vtl, Ss, HDd, Ss, Ss, Ss,
         y, nullptr, nullptr, Dd, nullptr, nullptr, nullptr, nullptr, -1, Bb*Hh, Hh,
         (long long)Hh*SS2, SS2, (long long)Hh*HDd*Ss, (long long)HDd*Ss, SD, HDd);
    k_split4<<<(int)(NX / 1024), 256>>>(y, txh, txl, NX);
    gemm(2, txh, txl, woh, wol, Bb*Ss, Dd, Dd, Dd, Dd,
         xo, nullptr, nullptr, Dd, so_b, nullptr, nullptr, em_, 2, 1, 1, 0,0,0,0,0,0);

    // ===================== cross attention =====================
    k_split4<<<(int)(NX / 1024), 256>>>(xo, txh, txl, NX);
    gemm(0, txh, txl, wcqh, wcql, Bb*Ss, Dd, Dd, Dd, Dd,
         qkv, nullptr, nullptr, Dd, cq_b, nullptr, nullptr, nullptr, -1, 1, 1, 0,0,0,0,0,0);
    k_rms_rope_split<<<Bb * Ss, 256>>>(qkv, Dd, 0, cnq, nullptr, qh, ql, Ss);
    k_split4<<<(int)((long long)Bb*LCc*Dd / 1024), 256>>>(ctx, cxh, cxl, (long long)Bb*LCc*Dd);
    gemm(0, cxh, cxl, wckvh, wckvl, Bb*LCc, 2*Dd, Dd, Dd, Dd,
         qkv, nullptr, nullptr, 2*Dd, ck_b, cv_b, nullptr, nullptr, -1, 1, 1, 0,0,0,0,0,0);
    k_rms_rope_split<<<Bb * LCc, 256>>>(qkv, 2*Dd, 0, cnk, nullptr, kh, kl, LCc);
    k_vt_split<<<dim3(LCc/32, 4, Bb*Hh), tb>>>(qkv, 2*Dd, Dd, vth, vtl, LCc);
    gemm(0, qh, ql, kh, kl, Ss, LCc, HDd, HDd, HDd,
         sc, nullptr, nullptr, LCc, nullptr, nullptr, nullptr, nullptr, -1, Bb*Hh, 1,
         (long long)Ss*HDd, 0, (long long)LCc*HDd, 0, SL, 0);
    k_softmax_split<<<Bb * Hh * Ss, 256>>>(sc, ph_, pl_, LCc, SCALE);
    gemm(0, ph_, pl_, vth, vtl, Ss, HDd, LCc, LCc, LCc,
         y, nullptr, nullptr, Dd, nullptr, nullptr, nullptr, nullptr, -1, Bb*Hh, Hh,
         (long long)Hh*SL, SL, (long long)Hh*HDd*LCc, (long long)HDd*LCc, SD, HDd);
    k_split4<<<(int)(NX / 1024), 256>>>(y, txh, txl, NX);
    gemm(2, txh, txl, wcoh, wcol, Bb*Ss, Dd, Dd, Dd, Dd,
         xo, nullptr, nullptr, Dd, co_b, nullptr, nullptr, em_, -1, 1, 1, 0,0,0,0,0,0);

    // ===================== FFN =====================
    k_ln_mod_split<<<Bb * Ss, 256>>>(xo, em_, txh, txl, 4, 3);
    gemm(1, txh, txl, wf1h, wf1l, Bb*Ss, Ff, Dd, Dd, Dd,
         nullptr, fh, fl, Ff, f1_b, nullptr, nullptr, nullptr, -1, 1, 1, 0,0,0,0,0,0);
    gemm(2, fh, fl, wf2h, wf2l, Bb*Ss, Dd, Ff, Ff, Ff,
         xo, nullptr, nullptr, Dd, f2_b, nullptr, nullptr, em_, 5, 1, 1, 0,0,0,0,0,0);
}

// round 9
// speedup vs baseline: 1.7787x; 1.0014x over previous
#include <cuda_runtime.h>
#include <cuda_bf16.h>
#include <cstdint>

using bf16 = __nv_bfloat16;

#define Bb  2
#define Ss  2048
#define Dd  2048
#define Hh  16
#define HDd 128
#define Ff  8192
#define LCc 512
#define EPSf 1e-6f

// ---------------------------------------------------------------------------
// Scratch (__device__ globals; allocation-free rule)
// ---------------------------------------------------------------------------
__device__ float g_em [Bb * 6 * Dd];
__device__ float g_qkv [(size_t)Bb * Ss * 3 * Dd];
__device__ float g_y   [(size_t)Bb * Ss * Dd];
__device__ float g_sc  [(size_t)Bb * Hh * Ss * Ss];

#define DECL2(nm, n) __device__ __align__(128) bf16 nm##h[(size_t)(n)]; __device__ __align__(128) bf16 nm##l[(size_t)(n)];
DECL2(g_tx, (size_t)Bb*Ss*Dd)
DECL2(g_cx, (size_t)Bb*LCc*Dd)
DECL2(g_q,  (size_t)Bb*Ss*Dd)
DECL2(g_k,  (size_t)Bb*Ss*Dd)
DECL2(g_vt, (size_t)Bb*Ss*Dd)
DECL2(g_p,  (size_t)Bb*Hh*Ss*Ss)
DECL2(g_f,  (size_t)Bb*Ss*Ff)
DECL2(g_wqkv, (size_t)3*Dd*Dd)
DECL2(g_wckv, (size_t)2*Dd*Dd)
DECL2(g_wo,   (size_t)Dd*Dd)
DECL2(g_wcq,  (size_t)Dd*Dd)
DECL2(g_wco,  (size_t)Dd*Dd)
DECL2(g_wf1,  (size_t)Ff*Dd)
DECL2(g_wf2,  (size_t)Dd*Ff)

// ---------------------------------------------------------------------------
// helpers
// ---------------------------------------------------------------------------
__device__ __forceinline__ uint32_t smem_u32(const void* p) {
    uint32_t a;
    asm("{ .reg .u64 t; cvta.to.shared.u64 t, %1; cvt.u32.u64 %0, t; }" : "=r"(a) : "l"(p));
    return a;
}
#define CP_COMMIT() asm volatile("cp.async.commit_group;" ::: "memory")

#define LDSM4(d, a) \
  asm volatile("ldmatrix.sync.aligned.m8n8.x4.shared.b16 {%0,%1,%2,%3}, [%4];" \
    : "=r"((d)[0]), "=r"((d)[1]), "=r"((d)[2]), "=r"((d)[3]) : "r"(a))

#define MMA16816(c, a, b0, b1) \
  asm volatile("mma.sync.aligned.m16n8k16.row.col.f32.bf16.bf16.f32 " \
    "{%0,%1,%2,%3}, {%4,%5,%6,%7}, {%8,%9}, {%0,%1,%2,%3};" \
    : "+f"((c)[0]), "+f"((c)[1]), "+f"((c)[2]), "+f"((c)[3]) \
    : "r"((a)[0]), "r"((a)[1]), "r"((a)[2]), "r"((a)[3]), "r"(b0), "r"(b1))

__device__ __forceinline__ float gelu_t(float x) {
    float x3 = x * x * x;
    return 0.5f * x * (1.f + tanhf(0.7978845608028654f * (x + 0.044715f * x3)));
}
__device__ __forceinline__ void split2(float v, bf16& h, bf16& l) {
    h = __float2bfloat16(v);
    l = __float2bfloat16(v - __bfloat162float(h));
}
__device__ __forceinline__ __nv_bfloat162 mkbf2(bf16 a, bf16 b) {
    __nv_bfloat162 r; r.x = a; r.y = b; return r;
}
// segmented bias: segments of 2048 columns (b1 null -> single segment b0)
__device__ __forceinline__ float bget(const float* b0, const float* b1,
                                      const float* b2, int c) {
    if (b1 == nullptr) return b0 ? b0[c] : 0.f;
    int seg = c >> 11, off = c & 2047;
    const float* bp = (seg == 0) ? b0 : ((seg == 1) ? b1 : b2);
    return bp[off];
}

// stage: Ah(10240) Al(10240) Bh(10240) Bl(10240); 80B row pitch, 128 rows, 32 bf16 cols
#define STAGE_BYTES 40960u
#define SMEM_TOTAL_G (2 * 40960)

// ---------------------------------------------------------------------------
// HMMA (mma.sync) GEMM: C(MxN) = A(MxK) @ B^T, B stored [N x K], bf16 hi/lo
// 3-term bf16x3 into fp32 acc. 2-stage pipeline, 2 CTAs/SM.
// EPI: 0 fp32(+bias); 1 gelu->bf16 h/l(+bias); 2 xo += (acc+bias)*gate;
//      3 bf16 h/l direct (no bias) — for attention PV outputs.
// ---------------------------------------------------------------------------
template <int EPI>
__global__ __launch_bounds__(256, 2)
void mma_gemm(const bf16* __restrict__ Ah, const bf16* __restrict__ Al,
              const bf16* __restrict__ Bh, const bf16* __restrict__ Bl,
              int K, int lda, int ldb,
              float* C, bf16* Ch, bf16* Cl, int ldc,
              const float* __restrict__ bias0, const float* __restrict__ bias1,
              const float* __restrict__ bias2,
              const float* __restrict__ em, int gateRow,
              int Hdiv,
              long long sAb, long long sAh_, long long sBb, long long sBh_,
              long long sCb, long long sCh_)
{
    extern __shared__ __align__(128) char smem[];
    const uint32_t sbase = smem_u32(smem);
    const int tid = threadIdx.x;
    const int w = tid >> 5, l = tid & 31;
    const int wm = w >> 2, wn = w & 3;          // 2 x 4 warp grid, warp tile 64x32

    const int z = blockIdx.z;
    const int zb = z / Hdiv, zh = z - zb * Hdiv;
    Ah += zb * sAb + zh * sAh_;  Al += zb * sAb + zh * sAh_;
    Bh += zb * sBb + zh * sBh_;  Bl += zb * sBb + zh * sBh_;
    const long long coff = zb * sCb + zh * sCh_;
    const int m0 = blockIdx.y * 128, n0 = blockIdx.x * 128;

    float acc[4][4][4];
#pragma unroll
    for (int i = 0; i < 4; i++)
#pragma unroll
        for (int j = 0; j < 4; j++)
#pragma unroll
            for (int r = 0; r < 4; r++) acc[i][j][r] = 0.f;

    auto load_chunk = [&](int kc, int stg) {
        const uint32_t sb = sbase + (uint32_t)stg * STAGE_BYTES;
        auto one = [&](const bf16* p, int r0, int ld, uint32_t off) {
#pragma unroll
            for (int it = 0; it < 2; it++) {
                int c = tid + it * 256;             // 0..511
                int r = c >> 2, c16 = c & 3;
                const char* g = (const char*)(p + (long long)(r0 + r) * ld + kc * 32) + c16 * 16;
                asm volatile("cp.async.cg.shared.global [%0], [%1], 16;"
                             :: "r"(sb + off + (uint32_t)(r * 80 + c16 * 16)), "l"(g));
            }
        };
        one(Ah, m0, lda, 0u);      one(Al, m0, lda, 10240u);
        one(Bh, n0, ldb, 20480u);  one(Bl, n0, ldb, 30720u);
        CP_COMMIT();
    };

    const uint32_t lrow  = (uint32_t)(l & 15) * 80u;
    const uint32_t lhalf = (uint32_t)(l >> 4) * 16u;

    // register-lean term sequencing: aH,bH -> t1; aL -> t2; bL -> t3
    auto compute = [&](int stg) {
        const uint32_t sb = sbase + (uint32_t)stg * STAGE_BYTES;
#pragma unroll
        for (int ks = 0; ks < 2; ks++) {
            const uint32_t kb = (uint32_t)ks * 32u + lhalf;
            uint32_t aH[4][4], bH[2][4], tmp[4][4];
            uint32_t ra[4], rb[2];
#pragma unroll
            for (int mt = 0; mt < 4; mt++) {
                ra[mt] = sb + (uint32_t)((wm * 64 + mt * 16) * 80) + lrow + kb;
                LDSM4(aH[mt], ra[mt]);
            }
#pragma unroll
            for (int bt = 0; bt < 2; bt++) {
                rb[bt] = sb + 20480u + (uint32_t)((wn * 32 + bt * 16) * 80) + lrow + kb;
                LDSM4(bH[bt], rb[bt]);
            }
#pragma unroll
            for (int mt = 0; mt < 4; mt++)
#pragma unroll
                for (int nt = 0; nt < 4; nt++) {
                    const int bt = nt >> 1, hi = nt & 1;
                    MMA16816(acc[mt][nt], aH[mt], bH[bt][hi], bH[bt][hi + 2]);
                }
#pragma unroll
            for (int mt = 0; mt < 4; mt++) LDSM4(tmp[mt], ra[mt] + 10240u);   // aL
#pragma unroll
            for (int mt = 0; mt < 4; mt++)
#pragma unroll
                for (int nt = 0; nt < 4; nt++) {
                    const int bt = nt >> 1, hi = nt & 1;
                    MMA16816(acc[mt][nt], tmp[mt], bH[bt][hi], bH[bt][hi + 2]);
                }
#pragma unroll
            for (int bt = 0; bt < 2; bt++) LDSM4(tmp[bt], rb[bt] + 10240u);   // bL
#pragma unroll
            for (int mt = 0; mt < 4; mt++)
#pragma unroll
                for (int nt = 0; nt < 4; nt++) {
                    const int bt = nt >> 1, hi = nt & 1;
                    MMA16816(acc[mt][nt], aH[mt], tmp[bt][hi], tmp[bt][hi + 2]);
                }
        }
    };

    const int nk = K / 32;
    load_chunk(0, 0);
    for (int i = 0; i < nk; i++) {
        if (i + 1 < nk) {
            load_chunk(i + 1, (i + 1) & 1);
            asm volatile("cp.async.wait_group 1;" ::: "memory");
        } else {
            asm volatile("cp.async.wait_group 0;" ::: "memory");
        }
        __syncthreads();
        compute(i & 1);
        __syncthreads();
    }

    // ---------------- epilogue ----------------
    const int r0f = l >> 2, c0f = (l & 3) * 2;
#pragma unroll
    for (int mt = 0; mt < 4; mt++) {
        const int gr = m0 + wm * 64 + mt * 16 + r0f;
#pragma unroll
        for (int nt = 0; nt < 4; nt++) {
            const int gc = n0 + wn * 32 + nt * 8 + c0f;
            float a0 = acc[mt][nt][0], a1 = acc[mt][nt][1];
            float a2 = acc[mt][nt][2], a3 = acc[mt][nt][3];
            if (EPI == 0) {
                float bx = bget(bias0, bias1, bias2, gc);
                float by = bget(bias0, bias1, bias2, gc + 1);
                float2 u0; u0.x = a0 + bx; u0.y = a1 + by;
                float2 u1; u1.x = a2 + bx; u1.y = a3 + by;
                *(float2*)(C + coff + (long long)gr * ldc + gc) = u0;
                *(float2*)(C + coff + (long long)(gr + 8) * ldc + gc) = u1;
            } else if (EPI == 1) {
                float bx = bias0[gc], by = bias0[gc + 1];
                float v0 = gelu_t(a0 + bx), v1 = gelu_t(a1 + by);
                float v2 = gelu_t(a2 + bx), v3 = gelu_t(a3 + by);
                bf16 h0, l0, h1, l1;
                split2(v0, h0, l0); split2(v1, h1, l1);
                *(__nv_bfloat162*)(Ch + coff + (long long)gr * ldc + gc) = mkbf2(h0, h1);
                *(__nv_bfloat162*)(Cl + coff + (long long)gr * ldc + gc) = mkbf2(l0, l1);
                split2(v2, h0, l0); split2(v3, h1, l1);
                *(__nv_bfloat162*)(Ch + coff + (long long)(gr + 8) * ldc + gc) = mkbf2(h0, h1);
                *(__nv_bfloat162*)(Cl + coff + (long long)(gr + 8) * ldc + gc) = mkbf2(l0, l1);
            } else if (EPI == 3) {
                bf16 h0, l0, h1, l1;
                split2(a0, h0, l0); split2(a1, h1, l1);
                *(__nv_bfloat162*)(Ch + coff + (long long)gr * ldc + gc) = mkbf2(h0, h1);
                *(__nv_bfloat162*)(Cl + coff + (long long)gr * ldc + gc) = mkbf2(l0, l1);
                split2(a2, h0, l0); split2(a3, h1, l1);
                *(__nv_bfloat162*)(Ch + coff + (long long)(gr + 8) * ldc + gc) = mkbf2(h0, h1);
                *(__nv_bfloat162*)(Cl + coff + (long long)(gr + 8) * ldc + gc) = mkbf2(l0, l1);
            } else {
                float bx = bias0[gc], by = bias0[gc + 1];
#pragma unroll
                for (int hh = 0; hh < 2; hh++) {
                    const int row = gr + hh * 8;
                    float va = (hh ? a2 : a0) + bx;
                    float vb = (hh ? a3 : a1) + by;
                    if (gateRow >= 0) {
                        const int b = row / Ss;
                        const float* gp = em + ((long long)b * 6 + gateRow) * Dd;
                        va *= gp[gc]; vb *= gp[gc + 1];
                    }
                    float2 o = *(float2*)(C + coff + (long long)row * ldc + gc);
                    o.x += va; o.y += vb;
                    *(float2*)(C + coff + (long long)row * ldc + gc) = o;
                }
            }
        }
    }
}

// ---------------------------------------------------------------------------
// Elementwise kernels
// ---------------------------------------------------------------------------
__global__ void k_copy(const float* __restrict__ a, float* __restrict__ o, long long n) {
    long long i = (long long)blockIdx.x * 256 + threadIdx.x;
    if (i < n) o[i] = a[i];
}
__global__ void k_emadd(const float* __restrict__ e, const float* __restrict__ mod,
                        float* __restrict__ em) {
    int i = blockIdx.x * 256 + threadIdx.x;
    if (i < Bb * 6 * Dd) em[i] = e[i] + mod[i % (6 * Dd)];
}
__global__ void k_split4(const float* __restrict__ in, bf16* __restrict__ oh,
                         bf16* __restrict__ ol, long long n) {
    long long i = ((long long)blockIdx.x * 256 + threadIdx.x) * 4;
    if (i >= n) return;
    float4 v = *(const float4*)(in + i);
    bf16 h0, l0, h1, l1;
    split2(v.x, h0, l0); split2(v.y, h1, l1);
    *(__nv_bfloat162*)(oh + i) = mkbf2(h0, h1);
    *(__nv_bfloat162*)(ol + i) = mkbf2(l0, l1);
    split2(v.z, h0, l0); split2(v.w, h1, l1);
    *(__nv_bfloat162*)(oh + i + 2) = mkbf2(h0, h1);
    *(__nv_bfloat162*)(ol + i + 2) = mkbf2(l0, l1);
}
// transpose+split: W[K x N] -> T[N x K] bf16 h/l
__global__ void k_tsplit(const float* __restrict__ W, bf16* __restrict__ Th,
                         bf16* __restrict__ Tl, int Kd, int Nd) {
    __shared__ float t[32][33];
    int n0 = blockIdx.x * 32, k0 = blockIdx.y * 32;
    int tx = threadIdx.x;
    for (int j = threadIdx.y; j < 32; j += 8)
        t[j][tx] = W[(long long)(k0 + j) * Nd + n0 + tx];        // t[k][n]
    __syncthreads();
    for (int j = threadIdx.y; j < 16; j += 8) {
        int n  = j * 2 + (tx >> 4);       // 0..31
        int kk = (tx & 15) * 2;           // 0..30
        float v0 = t[kk][n], v1 = t[kk + 1][n];
        long long o = (long long)(n0 + n) * Kd + k0 + kk;
        bf16 h0, l0, h1, l1;
        split2(v0, h0, l0); split2(v1, h1, l1);
        *(__nv_bfloat162*)(Th + o) = mkbf2(h0, h1);
        *(__nv_bfloat162*)(Tl + o) = mkbf2(l0, l1);
    }
}
// 3 square weights in one launch (blockIdx.z selects); keeps QKV GEMM at launch #4
__global__ void k_tsplit3(const float* __restrict__ w0, const float* __restrict__ w1,
                          const float* __restrict__ w2,
                          bf16* __restrict__ Th, bf16* __restrict__ Tl) {
    __shared__ float t[32][33];
    const float* W = (blockIdx.z == 0) ? w0 : ((blockIdx.z == 1) ? w1 : w2);
    size_t zoff = (size_t)blockIdx.z * Dd * Dd;
    int n0 = blockIdx.x * 32, k0 = blockIdx.y * 32;
    int tx = threadIdx.x;
    for (int j = threadIdx.y; j < 32; j += 8)
        t[j][tx] = W[(long long)(k0 + j) * Dd + n0 + tx];
    __syncthreads();
    for (int j = threadIdx.y; j < 16; j += 8) {
        int n  = j * 2 + (tx >> 4);
        int kk = (tx & 15) * 2;
        float v0 = t[kk][n], v1 = t[kk + 1][n];
        long long o = (long long)zoff + (long long)(n0 + n) * Dd + k0 + kk;
        bf16 h0, l0, h1, l1;
        split2(v0, h0, l0); split2(v1, h1, l1);
        *(__nv_bfloat162*)(Th + o) = mkbf2(h0, h1);
        *(__nv_bfloat162*)(Tl + o) = mkbf2(l0, l1);
    }
}
__global__ void k_ln_mod_split(const float* __restrict__ x, const float* __restrict__ em,
                               bf16* __restrict__ oh, bf16* __restrict__ ol,
                               int scaleRow, int shiftRow) {
    int row = blockIdx.x, b = row / Ss, t = threadIdx.x;
    const float* xr = x + (long long)row * Dd;
    const float* es = em + ((long long)b * 6 + scaleRow) * Dd;
    const float* eh = em + ((long long)b * 6 + shiftRow) * Dd;
    float v[8];
    float4 a0 = *(const float4*)(xr + t * 8);
    float4 a1 = *(const float4*)(xr + t * 8 + 4);
    v[0]=a0.x; v[1]=a0.y; v[2]=a0.z; v[3]=a0.w; v[4]=a1.x; v[5]=a1.y; v[6]=a1.z; v[7]=a1.w;
    float s = 0.f, s2 = 0.f;
#pragma unroll
    for (int i = 0; i < 8; i++) { s += v[i]; s2 += v[i] * v[i]; }
    __shared__ float sh[512];
    sh[t] = s; sh[256 + t] = s2;
    __syncthreads();
    for (int o = 128; o > 0; o >>= 1) {
        if (t < o) { sh[t] += sh[t + o]; sh[256 + t] += sh[256 + t + o]; }
        __syncthreads();
    }
    float m = sh[0] * (1.f / Dd);
    float var = sh[256] * (1.f / Dd) - m * m;
    float r = rsqrtf(var + EPSf);
    bf16 hh[8], ll[8];
#pragma unroll
    for (int i = 0; i < 8; i++) {
        int dI = t * 8 + i;
        float u = (v[i] - m) * r * (1.f + es[dI]) + eh[dI];
        split2(u, hh[i], ll[i]);
    }
    long long ob = (long long)row * Dd + t * 8;
#pragma unroll
    for (int i = 0; i < 8; i += 2) {
        *(__nv_bfloat162*)(oh + ob + i) = mkbf2(hh[i], hh[i + 1]);
        *(__nv_bfloat162*)(ol + ob + i) = mkbf2(ll[i], ll[i + 1]);
    }
}
__global__ void k_rms_rope_split(const float* __restrict__ in, int ldin, int off,
                                 const float* __restrict__ w, const float* __restrict__ freqs,
                                 bf16* __restrict__ oh, bf16* __restrict__ ol, int Sv) {
    int row = blockIdx.x, b = row / Sv, s = row % Sv, t = threadIdx.x;
    const float* xr = in + (long long)row * ldin + off;
    float v[8];
    float4 a0 = *(const float4*)(xr + t * 8);
    float4 a1 = *(const float4*)(xr + t * 8 + 4);
    v[0]=a0.x; v[1]=a0.y; v[2]=a0.z; v[3]=a0.w; v[4]=a1.x; v[5]=a1.y; v[6]=a1.z; v[7]=a1.w;
    float s2 = 0.f;
#pragma unroll
    for (int i = 0; i < 8; i++) s2 += v[i] * v[i];
    __shared__ float sh[256];
    sh[t] = s2;
    __syncthreads();
    for (int o = 128; o > 0; o >>= 1) {
        if (t < o) sh[t] += sh[t + o];
        __syncthreads();
    }
    float r = rsqrtf(sh[0] * (1.f / Dd) + EPSf);
    int dbase = t * 8, h = dbase >> 7, dd = dbase & 127;
    float u[8];
#pragma unroll
    for (int i = 0; i < 8; i++) u[i] = v[i] * r * w[dbase + i];
    if (freqs) {
#pragma unroll
        for (int pr = 0; pr < 4; pr++) {
            float sn, cs;
            __sincosf(freqs[s * 64 + (dd >> 1) + pr], &sn, &cs);
            float xr_ = u[2 * pr], xi = u[2 * pr + 1];
            u[2 * pr]     = xr_ * cs - xi * sn;
            u[2 * pr + 1] = xr_ * sn + xi * cs;
        }
    }
    long long ob = ((long long)(b * Hh + h) * Sv + s) * 128 + dd;
    bf16 hh[8], ll[8];
#pragma unroll
    for (int i = 0; i < 8; i++) split2(u[i], hh[i], ll[i]);
#pragma unroll
    for (int i = 0; i < 8; i += 2) {
        *(__nv_bfloat162*)(oh + ob + i) = mkbf2(hh[i], hh[i + 1]);
        *(__nv_bfloat162*)(ol + ob + i) = mkbf2(ll[i], ll[i + 1]);
    }
}
// V transpose+split: in[b, s, off + h*128 + d] -> out[((b*H+h)*128+d)*Sv + s]
__global__ void k_vt_split(const float* __restrict__ in, int ldin, int off,
                           bf16* __restrict__ oh, bf16* __restrict__ ol, int Sv) {
    __shared__ float t[32][33];
    int bh = blockIdx.z, b = bh >> 4, h = bh & 15;
    int s0 = blockIdx.x * 32, d0 = blockIdx.y * 32;
    int tx = threadIdx.x;
    for (int j = threadIdx.y; j < 32; j += 8)
        t[j][tx] = in[(long long)(b * Sv + s0 + j) * ldin + off + h * 128 + d0 + tx]; // t[s][d]
    __syncthreads();
    for (int j = threadIdx.y; j < 16; j += 8) {
        int d  = j * 2 + (tx >> 4);
        int ss = (tx & 15) * 2;
        float v0 = t[ss][d], v1 = t[ss + 1][d];
        long long o = (long long)(bh * 128 + d0 + d) * Sv + s0 + ss;
        bf16 h0, l0, h1, l1;
        split2(v0, h0, l0); split2(v1, h1, l1);
        *(__nv_bfloat162*)(oh + o) = mkbf2(h0, h1);
        *(__nv_bfloat162*)(ol + o) = mkbf2(l0, l1);
    }
}
// softmax: coalesced AND vectorized — thread t owns elements {2t, 2t+1} + k*512
__global__ void k_softmax_split(const float* __restrict__ S, bf16* __restrict__ oh,
                                bf16* __restrict__ ol, int ncols, float scale) {
    long long row = blockIdx.x;
    const float* p = S + row * ncols;
    bf16* Hp = oh + row * ncols;
    bf16* Lp = ol + row * ncols;
    int t = threadIdx.x;
    int np = ncols >> 9;                 // float2 per thread: 4 (self) / 1 (cross)
    float2 vv[4];
    float lm = -3.4e38f;
    for (int k = 0; k < np; k++) {
        vv[k] = *(const float2*)(p + (k << 9) + 2 * t);
        lm = fmaxf(lm, fmaxf(vv[k].x, vv[k].y));
    }
    __shared__ float sh[256];
    sh[t] = lm; __syncthreads();
    for (int o = 128; o > 0; o >>= 1) { if (t < o) sh[t] = fmaxf(sh[t], sh[t + o]); __syncthreads(); }
    float m = sh[0] * scale;
    __syncthreads();
    float ls = 0.f;
    for (int k = 0; k < np; k++) {
        float e0 = __expf(vv[k].x * scale - m);
        float e1 = __expf(vv[k].y * scale - m);
        vv[k].x = e0; vv[k].y = e1; ls += e0 + e1;
    }
    sh[t] = ls; __syncthreads();
    for (int o = 128; o > 0; o >>= 1) { if (t < o) sh[t] += sh[t + o]; __syncthreads(); }
    float inv = 1.f / sh[0];
    for (int k = 0; k < np; k++) {
        bf16 h0, l0, h1, l1;
        split2(vv[k].x * inv, h0, l0);
        split2(vv[k].y * inv, h1, l1);
        *(__nv_bfloat162*)(Hp + (k << 9) + 2 * t) = mkbf2(h0, h1);
        *(__nv_bfloat162*)(Lp + (k << 9) + 2 * t) = mkbf2(l0, l1);
    }
}

// ---------------------------------------------------------------------------
// Host orchestration
// ---------------------------------------------------------------------------
static void gemm(int epi, const bf16* Ah, const bf16* Al, const bf16* Bh, const bf16* Bl,
                 int M, int N, int K, int lda, int ldb,
                 float* C, bf16* Ch, bf16* Cl, int ldc,
                 const float* b0, const float* b1, const float* b2,
                 const float* em, int gateRow,
                 int batch, int Hdiv,
                 long long sAb, long long sAh, long long sBb, long long sBh,
                 long long sCb, long long sCh)
{
    dim3 g(N / 128, M / 128, batch), bl(256);
    size_t sm = SMEM_TOTAL_G;
    if (epi == 0)
        mma_gemm<0><<<g, bl, sm>>>(Ah, Al, Bh, Bl, K, lda, ldb, C, Ch, Cl, ldc,
                                   b0, b1, b2, em, gateRow, Hdiv, sAb, sAh, sBb, sBh, sCb, sCh);
    else if (epi == 1)
        mma_gemm<1><<<g, bl, sm>>>(Ah, Al, Bh, Bl, K, lda, ldb, C, Ch, Cl, ldc,
                                   b0, b1, b2, em, gateRow, Hdiv, sAb, sAh, sBb, sBh, sCb, sCh);
    else if (epi == 3)
        mma_gemm<3><<<g, bl, sm>>>(Ah, Al, Bh, Bl, K, lda, ldb, C, Ch, Cl, ldc,
                                   b0, b1, b2, em, gateRow, Hdiv, sAb, sAh, sBb, sBh, sCb, sCh);
    else
        mma_gemm<2><<<g, bl, sm>>>(Ah, Al, Bh, Bl, K, lda, ldb, C, Ch, Cl, ldc,
                                   b0, b1, b2, em, gateRow, Hdiv, sAb, sAh, sBb, sBh, sCb, sCh);
}

#define SYM(p, s) cudaGetSymbolAddress((void**)&p, s)

extern "C" void kernel_launch(void* const* d_in, const int* in_sizes, int n_in,
                              void* d_out, int out_size)
{
    bool sig = (in_sizes[13] == Dd);
    int I_snq, I_snk, I_cq_w, I_cq_b, I_ck_w, I_ck_b, I_cv_w, I_cv_b;
    int I_co_w, I_co_b, I_cnq, I_cnk, I_f1_w, I_f1_b, I_f2_w, I_f2_b;
    if (sig) {
        I_snq=13; I_snk=14; I_cq_w=15; I_cq_b=16; I_ck_w=17; I_ck_b=18;
        I_cv_w=19; I_cv_b=20; I_co_w=21; I_co_b=22; I_cnq=23; I_cnk=24;
        I_f1_w=25; I_f1_b=26; I_f2_w=27; I_f2_b=28;
    } else {
        I_cq_w=13; I_cq_b=14; I_ck_w=15; I_ck_b=16; I_cv_w=17; I_cv_b=18;
        I_co_w=19; I_co_b=20; I_f1_w=21; I_f1_b=22; I_f2_w=23; I_f2_b=24;
        I_snq=25; I_snk=26; I_cnq=27; I_cnk=28;
    }
    const float* x    = (const float*)d_in[0];
    const float* e    = (const float*)d_in[1];
    const float* ctx  = (const float*)d_in[2];
    const float* fr   = (const float*)d_in[3];
    const float* mod  = (const float*)d_in[4];
    const float* sq_w = (const float*)d_in[5];  const float* sq_b = (const float*)d_in[6];
    const float* sk_w = (const float*)d_in[7];  const float* sk_b = (const float*)d_in[8];
    const float* sv_w = (const float*)d_in[9];  const float* sv_b = (const float*)d_in[10];
    const float* so_w = (const float*)d_in[11]; const float* so_b = (const float*)d_in[12];
    const float* snq  = (const float*)d_in[I_snq];  const float* snk  = (const float*)d_in[I_snk];
    const float* cq_w = (const float*)d_in[I_cq_w]; const float* cq_b = (const float*)d_in[I_cq_b];
    const float* ck_w = (const float*)d_in[I_ck_w]; const float* ck_b = (const float*)d_in[I_ck_b];
    const float* cv_w = (const float*)d_in[I_cv_w]; const float* cv_b = (const float*)d_in[I_cv_b];
    const float* co_w = (const float*)d_in[I_co_w]; const float* co_b = (const float*)d_in[I_co_b];
    const float* cnq  = (const float*)d_in[I_cnq];  const float* cnk  = (const float*)d_in[I_cnk];
    const float* f1_w = (const float*)d_in[I_f1_w]; const float* f1_b = (const float*)d_in[I_f1_b];
    const float* f2_w = (const float*)d_in[I_f2_w]; const float* f2_b = (const float*)d_in[I_f2_b];

    cudaFuncSetAttribute(mma_gemm<0>, cudaFuncAttributeMaxDynamicSharedMemorySize, SMEM_TOTAL_G);
    cudaFuncSetAttribute(mma_gemm<1>, cudaFuncAttributeMaxDynamicSharedMemorySize, SMEM_TOTAL_G);
    cudaFuncSetAttribute(mma_gemm<2>, cudaFuncAttributeMaxDynamicSharedMemorySize, SMEM_TOTAL_G);
    cudaFuncSetAttribute(mma_gemm<3>, cudaFuncAttributeMaxDynamicSharedMemorySize, SMEM_TOTAL_G);

    float *em_, *qkv, *y, *sc;
    SYM(em_, g_em); SYM(qkv, g_qkv); SYM(y, g_y); SYM(sc, g_sc);
    bf16 *txh, *txl, *cxh, *cxl, *qh, *ql, *kh, *kl, *vth, *vtl, *ph_, *pl_, *fh, *fl;
    SYM(txh, g_txh); SYM(txl, g_txl); SYM(cxh, g_cxh); SYM(cxl, g_cxl);
    SYM(qh, g_qh); SYM(ql, g_ql); SYM(kh, g_kh); SYM(kl, g_kl);
    SYM(vth, g_vth); SYM(vtl, g_vtl); SYM(ph_, g_ph); SYM(pl_, g_pl);
    SYM(fh, g_fh); SYM(fl, g_fl);
    bf16 *wqkvh, *wqkvl, *wckvh, *wckvl, *woh, *wol, *wcqh, *wcql, *wcoh, *wcol, *wf1h, *wf1l, *wf2h, *wf2l;
    SYM(wqkvh, g_wqkvh); SYM(wqkvl, g_wqkvl); SYM(wckvh, g_wckvh); SYM(wckvl, g_wckvl);
    SYM(woh, g_woh); SYM(wol, g_wol); SYM(wcqh, g_wcqh); SYM(wcql, g_wcql);
    SYM(wcoh, g_wcoh); SYM(wcol, g_wcol); SYM(wf1h, g_wf1h); SYM(wf1l, g_wf1l);
    SYM(wf2h, g_wf2h); SYM(wf2l, g_wf2l);

    float* xo = (float*)d_out;
    const long long NX = (long long)Bb * Ss * Dd;
    const long long DD = (long long)Dd * Dd;
    const long long SD = (long long)Ss * Dd;
    const long long SS2 = (long long)Ss * Ss;
    const long long SL = (long long)Ss * LCc;
    const float SCALE = 0.08838834764831845f;
    dim3 tb(32, 8);

    // ---- launches 1-5: capture slot (#4/#5) = production mma_gemm ----
    k_emadd<<<(Bb * 6 * Dd + 255) / 256, 256>>>(e, mod, em_);                           // 1
    k_ln_mod_split<<<Bb * Ss, 256>>>(x, em_, txh, txl, 1, 0);                           // 2
    k_tsplit3<<<dim3(Dd/32, Dd/32, 3), tb>>>(sq_w, sk_w, sv_w, wqkvh, wqkvl);           // 3
    gemm(0, txh, txl, wqkvh, wqkvl, Bb*Ss, Dd, Dd, Dd, Dd,                              // 4 <- capture
         qkv, nullptr, nullptr, 3*Dd, sq_b, nullptr, nullptr, nullptr, -1, 1, 1, 0,0,0,0,0,0);
    gemm(0, txh, txl, wqkvh + DD, wqkvl + DD, Bb*Ss, 2*Dd, Dd, Dd, Dd,                  // 5 <- capture
         qkv + Dd, nullptr, nullptr, 3*Dd, sk_b, sv_b, nullptr, nullptr, -1, 1, 1, 0,0,0,0,0,0);

    k_copy<<<(int)((NX + 255) / 256), 256>>>(x, xo, NX);
    k_tsplit<<<dim3(Dd/32, Dd/32), tb>>>(so_w, woh,  wol,  Dd, Dd);
    k_tsplit<<<dim3(Dd/32, Dd/32), tb>>>(cq_w, wcqh, wcql, Dd, Dd);
    k_tsplit<<<dim3(Dd/32, Dd/32), tb>>>(ck_w, wckvh,      wckvl,      Dd, Dd);
    k_tsplit<<<dim3(Dd/32, Dd/32), tb>>>(cv_w, wckvh + DD, wckvl + DD, Dd, Dd);
    k_tsplit<<<dim3(Dd/32, Dd/32), tb>>>(co_w, wcoh, wcol, Dd, Dd);
    k_tsplit<<<dim3(Ff/32, Dd/32), tb>>>(f1_w, wf1h, wf1l, Dd, Ff);
    k_tsplit<<<dim3(Dd/32, Ff/32), tb>>>(f2_w, wf2h, wf2l, Ff, Dd);

    // ===================== self attention =====================
    k_rms_rope_split<<<Bb * Ss, 256>>>(qkv, 3*Dd, 0,  snq, fr, qh, ql, Ss);
    k_rms_rope_split<<<Bb * Ss, 256>>>(qkv, 3*Dd, Dd, snk, fr, kh, kl, Ss);
    k_vt_split<<<dim3(Ss/32, 4, Bb*Hh), tb>>>(qkv, 3*Dd, 2*Dd, vth, vtl, Ss);
    gemm(0, qh, ql, kh, kl, Ss, Ss, HDd, HDd, HDd,
         sc, nullptr, nullptr, Ss, nullptr, nullptr, nullptr, nullptr, -1, Bb*Hh, 1,
         (long long)Ss*HDd, 0, (long long)Ss*HDd, 0, SS2, 0);
    k_softmax_split<<<Bb * Hh * Ss, 256>>>(sc, ph_, pl_, Ss, SCALE);
    gemm(3, ph_, pl_, vth, vtl, Ss, HDd, Ss, Ss, Ss,
         nullptr, txh, txl, Dd, nullptr, nullptr, nullptr, nullptr, -1, Bb*Hh, Hh,
         (long long)Hh*SS2, SS2, (long long)Hh*HDd*Ss, (long long)HDd*Ss, SD, HDd);
    gemm(2, txh, txl, woh, wol, Bb*Ss, Dd, Dd, Dd, Dd,
         xo, nullptr, nullptr, Dd, so_b, nullptr, nullptr, em_, 2, 1, 1, 0,0,0,0,0,0);

    // ===================== cross attention =====================
    k_split4<<<(int)(NX / 1024), 256>>>(xo, txh, txl, NX);
    gemm(0, txh, txl, wcqh, wcql, Bb*Ss, Dd, Dd, Dd, Dd,
         qkv, nullptr, nullptr, Dd, cq_b, nullptr, nullptr, nullptr, -1, 1, 1, 0,0,0,0,0,0);
    k_rms_rope_split<<<Bb * Ss, 256>>>(qkv, Dd, 0, cnq, nullptr, qh, ql, Ss);
    k_split4<<<(int)((long long)Bb*LCc*Dd / 1024), 256>>>(ctx, cxh, cxl, (long long)Bb*LCc*Dd);
    gemm(0, cxh, cxl, wckvh, wckvl, Bb*LCc, 2*Dd, Dd, Dd, Dd,
         qkv, nullptr, nullptr, 2*Dd, ck_b, cv_b, nullptr, nullptr, -1, 1, 1, 0,0,0,0,0,0);
    k_rms_rope_split<<<Bb * LCc, 256>>>(qkv, 2*Dd, 0, cnk, nullptr, kh, kl, LCc);
    k_vt_split<<<dim3(LCc/32, 4, Bb*Hh), tb>>>(qkv, 2*Dd, Dd, vth, vtl, LCc);
    gemm(0, qh, ql, kh, kl, Ss, LCc, HDd, HDd, HDd,
         sc, nullptr, nullptr, LCc, nullptr, nullptr, nullptr, nullptr, -1, Bb*Hh, 1,
         (long long)Ss*HDd, 0, (long long)LCc*HDd, 0, SL, 0);
    k_softmax_split<<<Bb * Hh * Ss, 256>>>(sc, ph_, pl_, LCc, SCALE);
    gemm(3, ph_, pl_, vth, vtl, Ss, HDd, LCc, LCc, LCc,
         nullptr, txh, txl, Dd, nullptr, nullptr, nullptr, nullptr, -1, Bb*Hh, Hh,
         (long long)Hh*SL, SL, (long long)Hh*HDd*LCc, (long long)HDd*LCc, SD, HDd);
    gemm(2, txh, txl, wcoh, wcol, Bb*Ss, Dd, Dd, Dd, Dd,
         xo, nullptr, nullptr, Dd, co_b, nullptr, nullptr, em_, -1, 1, 1, 0,0,0,0,0,0);

    // ===================== FFN =====================
    k_ln_mod_split<<<Bb * Ss, 256>>>(xo, em_, txh, txl, 4, 3);
    gemm(1, txh, txl, wf1h, wf1l, Bb*Ss, Ff, Dd, Dd, Dd,
         nullptr, fh, fl, Ff, f1_b, nullptr, nullptr, nullptr, -1, 1, 1, 0,0,0,0,0,0);
    gemm(2, fh, fl, wf2h, wf2l, Bb*Ss, Dd, Ff, Ff, Ff,
         xo, nullptr, nullptr, Dd, f2_b, nullptr, nullptr, em_, 5, 1, 1, 0,0,0,0,0,0);
}

// round 12
// speedup vs baseline: 1.9786x; 1.1124x over previous
#include <cuda_runtime.h>
#include <cuda_bf16.h>
#include <cstdint>

using bf16 = __nv_bfloat16;

#define Bb  2
#define Ss  2048
#define Dd  2048
#define Hh  16
#define HDd 128
#define Ff  8192
#define LCc 512
#define EPSf 1e-6f

// ---------------------------------------------------------------------------
// Scratch (__device__ globals; allocation-free rule)
// ---------------------------------------------------------------------------
__device__ float g_em [Bb * 6 * Dd];
__device__ float g_qkv [(size_t)Bb * Ss * 3 * Dd];
__device__ float g_y   [(size_t)Bb * Ss * Dd];
__device__ float g_sc  [(size_t)Bb * Hh * Ss * Ss];

#define DECL2(nm, n) __device__ __align__(128) bf16 nm##h[(size_t)(n)]; __device__ __align__(128) bf16 nm##l[(size_t)(n)];
DECL2(g_tx, (size_t)Bb*Ss*Dd)
DECL2(g_cx, (size_t)Bb*LCc*Dd)
DECL2(g_q,  (size_t)Bb*Ss*Dd)
DECL2(g_k,  (size_t)Bb*Ss*Dd)
DECL2(g_vt, (size_t)Bb*Ss*Dd)
DECL2(g_p,  (size_t)Bb*Hh*Ss*Ss)
DECL2(g_f,  (size_t)Bb*Ss*Ff)
DECL2(g_wqkv, (size_t)3*Dd*Dd)
DECL2(g_wckv, (size_t)2*Dd*Dd)
DECL2(g_wo,   (size_t)Dd*Dd)
DECL2(g_wcq,  (size_t)Dd*Dd)
DECL2(g_wco,  (size_t)Dd*Dd)
DECL2(g_wf1,  (size_t)Ff*Dd)
DECL2(g_wf2,  (size_t)Dd*Ff)

// ---------------------------------------------------------------------------
// helpers
// ---------------------------------------------------------------------------
__device__ __forceinline__ uint32_t smem_u32(const void* p) {
    uint32_t a;
    asm("{ .reg .u64 t; cvta.to.shared.u64 t, %1; cvt.u32.u64 %0, t; }" : "=r"(a) : "l"(p));
    return a;
}
#define CP_COMMIT() asm volatile("cp.async.commit_group;" ::: "memory")

#define LDSM4(d, a) \
  asm volatile("ldmatrix.sync.aligned.m8n8.x4.shared.b16 {%0,%1,%2,%3}, [%4];" \
    : "=r"((d)[0]), "=r"((d)[1]), "=r"((d)[2]), "=r"((d)[3]) : "r"(a))

#define MMA16816(c, a, b0, b1) \
  asm volatile("mma.sync.aligned.m16n8k16.row.col.f32.bf16.bf16.f32 " \
    "{%0,%1,%2,%3}, {%4,%5,%6,%7}, {%8,%9}, {%0,%1,%2,%3};" \
    : "+f"((c)[0]), "+f"((c)[1]), "+f"((c)[2]), "+f"((c)[3]) \
    : "r"((a)[0]), "r"((a)[1]), "r"((a)[2]), "r"((a)[3]), "r"(b0), "r"(b1))

__device__ __forceinline__ float gelu_t(float x) {
    float x3 = x * x * x;
    return 0.5f * x * (1.f + tanhf(0.7978845608028654f * (x + 0.044715f * x3)));
}
__device__ __forceinline__ void split2(float v, bf16& h, bf16& l) {
    h = __float2bfloat16(v);
    l = __float2bfloat16(v - __bfloat162float(h));
}
__device__ __forceinline__ __nv_bfloat162 mkbf2(bf16 a, bf16 b) {
    __nv_bfloat162 r; r.x = a; r.y = b; return r;
}
// segmented bias: segments of 2048 columns (b1 null -> single segment b0)
__device__ __forceinline__ float bget(const float* b0, const float* b1,
                                      const float* b2, int c) {
    if (b1 == nullptr) return b0 ? b0[c] : 0.f;
    int seg = c >> 11, off = c & 2047;
    const float* bp = (seg == 0) ? b0 : ((seg == 1) ? b1 : b2);
    return bp[off];
}

// stage: Ah(8192) Al(8192) Bh(8192) Bl(8192); 64B row pitch, 16B-chunk XOR swizzle
// swizzle: chunk' = chunk ^ ((row>>1)&3)  -> conflict-free ldmatrix at 64B pitch
#define STAGE_BYTES 32768u
#define SMEM_TOTAL_G (3 * 32768)

// ---------------------------------------------------------------------------
// HMMA (mma.sync) GEMM: C(MxN) = A(MxK) @ B^T, B stored [N x K], bf16 hi/lo
// 3-term bf16x3 into fp32 acc. 3-stage pipeline, SINGLE __syncthreads per
// iteration, 2 CTAs/SM. EPI: 0 fp32(+bias); 1 gelu->bf16 h/l(+bias);
// 2 xo += (acc+bias)*gate; 3 bf16 h/l direct (attention PV).
// ---------------------------------------------------------------------------
template <int EPI>
__global__ __launch_bounds__(256, 2)
void mma_gemm(const bf16* __restrict__ Ah, const bf16* __restrict__ Al,
              const bf16* __restrict__ Bh, const bf16* __restrict__ Bl,
              int K, int lda, int ldb,
              float* C, bf16* Ch, bf16* Cl, int ldc,
              const float* __restrict__ bias0, const float* __restrict__ bias1,
              const float* __restrict__ bias2,
              const float* __restrict__ em, int gateRow,
              int Hdiv,
              long long sAb, long long sAh_, long long sBb, long long sBh_,
              long long sCb, long long sCh_)
{
    extern __shared__ __align__(128) char smem[];
    const uint32_t sbase = smem_u32(smem);
    const int tid = threadIdx.x;
    const int w = tid >> 5, l = tid & 31;
    const int wm = w >> 2, wn = w & 3;          // 2 x 4 warp grid, warp tile 64x32

    const int z = blockIdx.z;
    const int zb = z / Hdiv, zh = z - zb * Hdiv;
    Ah += zb * sAb + zh * sAh_;  Al += zb * sAb + zh * sAh_;
    Bh += zb * sBb + zh * sBh_;  Bl += zb * sBb + zh * sBh_;
    const long long coff = zb * sCb + zh * sCh_;
    const int m0 = blockIdx.y * 128, n0 = blockIdx.x * 128;

    float acc[4][4][4];
#pragma unroll
    for (int i = 0; i < 4; i++)
#pragma unroll
        for (int j = 0; j < 4; j++)
#pragma unroll
            for (int r = 0; r < 4; r++) acc[i][j][r] = 0.f;

    // one k-chunk (32 cols bf16 = 64B/row) of all 4 operand halves into stage
    auto load_chunk = [&](int kc, int stg) {
        const uint32_t sb = sbase + (uint32_t)stg * STAGE_BYTES;
        auto one = [&](const bf16* p, int r0, int ld, uint32_t off) {
#pragma unroll
            for (int it = 0; it < 2; it++) {
                int c = tid + it * 256;             // 0..511 segments of 16B
                int r = c >> 2, c16 = c & 3;
                const char* g = (const char*)(p + (long long)(r0 + r) * ld + kc * 32) + c16 * 16;
                uint32_t so = (uint32_t)(r * 64 + ((c16 ^ ((r >> 1) & 3)) * 16));
                asm volatile("cp.async.cg.shared.global [%0], [%1], 16;"
                             :: "r"(sb + off + so), "l"(g));
            }
        };
        one(Ah, m0, lda, 0u);      one(Al, m0, lda, 8192u);
        one(Bh, n0, ldb, 16384u);  one(Bl, n0, ldb, 24576u);
        CP_COMMIT();
    };

    // register-lean term sequencing: aH,bH -> t1; aL -> t2; bL -> t3
    auto compute = [&](int stg) {
        const uint32_t sb = sbase + (uint32_t)stg * STAGE_BYTES;
        uint32_t rowA[4], swA[4], rowB[2], swB[2];
#pragma unroll
        for (int mt = 0; mt < 4; mt++) {
            uint32_t r = (uint32_t)(wm * 64 + mt * 16 + (l & 15));
            rowA[mt] = sb + r * 64u;
            swA[mt]  = (r >> 1) & 3u;
        }
#pragma unroll
        for (int bt = 0; bt < 2; bt++) {
            uint32_t r = (uint32_t)(wn * 32 + bt * 16 + (l & 15));
            rowB[bt] = sb + 16384u + r * 64u;
            swB[bt]  = (r >> 1) & 3u;
        }
#pragma unroll
        for (int ks = 0; ks < 2; ks++) {
            const uint32_t ch = (uint32_t)(ks * 2 + (l >> 4));
            uint32_t aH[4][4], bH[2][4], tmp[4][4];
            uint32_t ra[4], rb[2];
#pragma unroll
            for (int mt = 0; mt < 4; mt++) {
                ra[mt] = rowA[mt] + ((ch ^ swA[mt]) * 16u);
                LDSM4(aH[mt], ra[mt]);
            }
#pragma unroll
            for (int bt = 0; bt < 2; bt++) {
                rb[bt] = rowB[bt] + ((ch ^ swB[bt]) * 16u);
                LDSM4(bH[bt], rb[bt]);
            }
#pragma unroll
            for (int mt = 0; mt < 4; mt++)
#pragma unroll
                for (int nt = 0; nt < 4; nt++) {
                    const int bt = nt >> 1, hi = nt & 1;
                    MMA16816(acc[mt][nt], aH[mt], bH[bt][hi], bH[bt][hi + 2]);
                }
#pragma unroll
            for (int mt = 0; mt < 4; mt++) LDSM4(tmp[mt], ra[mt] + 8192u);   // aL
#pragma unroll
            for (int mt = 0; mt < 4; mt++)
#pragma unroll
                for (int nt = 0; nt < 4; nt++) {
                    const int bt = nt >> 1, hi = nt & 1;
                    MMA16816(acc[mt][nt], tmp[mt], bH[bt][hi], bH[bt][hi + 2]);
                }
#pragma unroll
            for (int bt = 0; bt < 2; bt++) LDSM4(tmp[bt], rb[bt] + 8192u);   // bL
#pragma unroll
            for (int mt = 0; mt < 4; mt++)
#pragma unroll
                for (int nt = 0; nt < 4; nt++) {
                    const int bt = nt >> 1, hi = nt & 1;
                    MMA16816(acc[mt][nt], aH[mt], tmp[bt][hi], tmp[bt][hi + 2]);
                }
        }
    };

    const int nk = K / 32;
    load_chunk(0, 0);
    if (nk > 1) load_chunk(1, 1);
    for (int i = 0; i < nk; i++) {
        if (i + 1 < nk) asm volatile("cp.async.wait_group 1;" ::: "memory");
        else            asm volatile("cp.async.wait_group 0;" ::: "memory");
        __syncthreads();                       // single barrier per iteration
        if (i + 2 < nk) load_chunk(i + 2, (i + 2) % 3);
        compute(i % 3);
    }

    // ---------------- epilogue ----------------
    const int r0f = l >> 2, c0f = (l & 3) * 2;
#pragma unroll
    for (int mt = 0; mt < 4; mt++) {
        const int gr = m0 + wm * 64 + mt * 16 + r0f;
#pragma unroll
        for (int nt = 0; nt < 4; nt++) {
            const int gc = n0 + wn * 32 + nt * 8 + c0f;
            float a0 = acc[mt][nt][0], a1 = acc[mt][nt][1];
            float a2 = acc[mt][nt][2], a3 = acc[mt][nt][3];
            if (EPI == 0) {
                float bx = bget(bias0, bias1, bias2, gc);
                float by = bget(bias0, bias1, bias2, gc + 1);
                float2 u0; u0.x = a0 + bx; u0.y = a1 + by;
                float2 u1; u1.x = a2 + bx; u1.y = a3 + by;
                *(float2*)(C + coff + (long long)gr * ldc + gc) = u0;
                *(float2*)(C + coff + (long long)(gr + 8) * ldc + gc) = u1;
            } else if (EPI == 1) {
                float bx = bias0[gc], by = bias0[gc + 1];
                float v0 = gelu_t(a0 + bx), v1 = gelu_t(a1 + by);
                float v2 = gelu_t(a2 + bx), v3 = gelu_t(a3 + by);
                bf16 h0, l0, h1, l1;
                split2(v0, h0, l0); split2(v1, h1, l1);
                *(__nv_bfloat162*)(Ch + coff + (long long)gr * ldc + gc) = mkbf2(h0, h1);
                *(__nv_bfloat162*)(Cl + coff + (long long)gr * ldc + gc) = mkbf2(l0, l1);
                split2(v2, h0, l0); split2(v3, h1, l1);
                *(__nv_bfloat162*)(Ch + coff + (long long)(gr + 8) * ldc + gc) = mkbf2(h0, h1);
                *(__nv_bfloat162*)(Cl + coff + (long long)(gr + 8) * ldc + gc) = mkbf2(l0, l1);
            } else if (EPI == 3) {
                bf16 h0, l0, h1, l1;
                split2(a0, h0, l0); split2(a1, h1, l1);
                *(__nv_bfloat162*)(Ch + coff + (long long)gr * ldc + gc) = mkbf2(h0, h1);
                *(__nv_bfloat162*)(Cl + coff + (long long)gr * ldc + gc) = mkbf2(l0, l1);
                split2(a2, h0, l0); split2(a3, h1, l1);
                *(__nv_bfloat162*)(Ch + coff + (long long)(gr + 8) * ldc + gc) = mkbf2(h0, h1);
                *(__nv_bfloat162*)(Cl + coff + (long long)(gr + 8) * ldc + gc) = mkbf2(l0, l1);
            } else {
                float bx = bias0[gc], by = bias0[gc + 1];
#pragma unroll
                for (int hh = 0; hh < 2; hh++) {
                    const int row = gr + hh * 8;
                    float va = (hh ? a2 : a0) + bx;
                    float vb = (hh ? a3 : a1) + by;
                    if (gateRow >= 0) {
                        const int b = row / Ss;
                        const float* gp = em + ((long long)b * 6 + gateRow) * Dd;
                        va *= gp[gc]; vb *= gp[gc + 1];
                    }
                    float2 o = *(float2*)(C + coff + (long long)row * ldc + gc);
                    o.x += va; o.y += vb;
                    *(float2*)(C + coff + (long long)row * ldc + gc) = o;
                }
            }
        }
    }
}

// ---------------------------------------------------------------------------
// Elementwise kernels
// ---------------------------------------------------------------------------
__global__ void k_copy(const float* __restrict__ a, float* __restrict__ o, long long n) {
    long long i = (long long)blockIdx.x * 256 + threadIdx.x;
    if (i < n) o[i] = a[i];
}
__global__ void k_emadd(const float* __restrict__ e, const float* __restrict__ mod,
                        float* __restrict__ em) {
    int i = blockIdx.x * 256 + threadIdx.x;
    if (i < Bb * 6 * Dd) em[i] = e[i] + mod[i % (6 * Dd)];
}
__global__ void k_split4(const float* __restrict__ in, bf16* __restrict__ oh,
                         bf16* __restrict__ ol, long long n) {
    long long i = ((long long)blockIdx.x * 256 + threadIdx.x) * 4;
    if (i >= n) return;
    float4 v = *(const float4*)(in + i);
    bf16 h0, l0, h1, l1;
    split2(v.x, h0, l0); split2(v.y, h1, l1);
    *(__nv_bfloat162*)(oh + i) = mkbf2(h0, h1);
    *(__nv_bfloat162*)(ol + i) = mkbf2(l0, l1);
    split2(v.z, h0, l0); split2(v.w, h1, l1);
    *(__nv_bfloat162*)(oh + i + 2) = mkbf2(h0, h1);
    *(__nv_bfloat162*)(ol + i + 2) = mkbf2(l0, l1);
}
// transpose+split: W[K x N] -> T[N x K] bf16 h/l
__global__ void k_tsplit(const float* __restrict__ W, bf16* __restrict__ Th,
                         bf16* __restrict__ Tl, int Kd, int Nd) {
    __shared__ float t[32][33];
    int n0 = blockIdx.x * 32, k0 = blockIdx.y * 32;
    int tx = threadIdx.x;
    for (int j = threadIdx.y; j < 32; j += 8)
        t[j][tx] = W[(long long)(k0 + j) * Nd + n0 + tx];        // t[k][n]
    __syncthreads();
    for (int j = threadIdx.y; j < 16; j += 8) {
        int n  = j * 2 + (tx >> 4);       // 0..31
        int kk = (tx & 15) * 2;           // 0..30
        float v0 = t[kk][n], v1 = t[kk + 1][n];
        long long o = (long long)(n0 + n) * Kd + k0 + kk;
        bf16 h0, l0, h1, l1;
        split2(v0, h0, l0); split2(v1, h1, l1);
        *(__nv_bfloat162*)(Th + o) = mkbf2(h0, h1);
        *(__nv_bfloat162*)(Tl + o) = mkbf2(l0, l1);
    }
}
// 3 square weights in one launch (blockIdx.z selects)
__global__ void k_tsplit3(const float* __restrict__ w0, const float* __restrict__ w1,
                          const float* __restrict__ w2,
                          bf16* __restrict__ Th, bf16* __restrict__ Tl) {
    __shared__ float t[32][33];
    const float* W = (blockIdx.z == 0) ? w0 : ((blockIdx.z == 1) ? w1 : w2);
    size_t zoff = (size_t)blockIdx.z * Dd * Dd;
    int n0 = blockIdx.x * 32, k0 = blockIdx.y * 32;
    int tx = threadIdx.x;
    for (int j = threadIdx.y; j < 32; j += 8)
        t[j][tx] = W[(long long)(k0 + j) * Dd + n0 + tx];
    __syncthreads();
    for (int j = threadIdx.y; j < 16; j += 8) {
        int n  = j * 2 + (tx >> 4);
        int kk = (tx & 15) * 2;
        float v0 = t[kk][n], v1 = t[kk + 1][n];
        long long o = (long long)zoff + (long long)(n0 + n) * Dd + k0 + kk;
        bf16 h0, l0, h1, l1;
        split2(v0, h0, l0); split2(v1, h1, l1);
        *(__nv_bfloat162*)(Th + o) = mkbf2(h0, h1);
        *(__nv_bfloat162*)(Tl + o) = mkbf2(l0, l1);
    }
}
__global__ void k_ln_mod_split(const float* __restrict__ x, const float* __restrict__ em,
                               bf16* __restrict__ oh, bf16* __restrict__ ol,
                               int scaleRow, int shiftRow) {
    int row = blockIdx.x, b = row / Ss, t = threadIdx.x;
    const float* xr = x + (long long)row * Dd;
    const float* es = em + ((long long)b * 6 + scaleRow) * Dd;
    const float* eh = em + ((long long)b * 6 + shiftRow) * Dd;
    float v[8];
    float4 a0 = *(const float4*)(xr + t * 8);
    float4 a1 = *(const float4*)(xr + t * 8 + 4);
    v[0]=a0.x; v[1]=a0.y; v[2]=a0.z; v[3]=a0.w; v[4]=a1.x; v[5]=a1.y; v[6]=a1.z; v[7]=a1.w;
    float s = 0.f, s2 = 0.f;
#pragma unroll
    for (int i = 0; i < 8; i++) { s += v[i]; s2 += v[i] * v[i]; }
    __shared__ float sh[512];
    sh[t] = s; sh[256 + t] = s2;
    __syncthreads();
    for (int o = 128; o > 0; o >>= 1) {
        if (t < o) { sh[t] += sh[t + o]; sh[256 + t] += sh[256 + t + o]; }
        __syncthreads();
    }
    float m = sh[0] * (1.f / Dd);
    float var = sh[256] * (1.f / Dd) - m * m;
    float r = rsqrtf(var + EPSf);
    bf16 hh[8], ll[8];
#pragma unroll
    for (int i = 0; i < 8; i++) {
        int dI = t * 8 + i;
        float u = (v[i] - m) * r * (1.f + es[dI]) + eh[dI];
        split2(u, hh[i], ll[i]);
    }
    long long ob = (long long)row * Dd + t * 8;
#pragma unroll
    for (int i = 0; i < 8; i += 2) {
        *(__nv_bfloat162*)(oh + ob + i) = mkbf2(hh[i], hh[i + 1]);
        *(__nv_bfloat162*)(ol + ob + i) = mkbf2(ll[i], ll[i + 1]);
    }
}
__global__ void k_rms_rope_split(const float* __restrict__ in, int ldin, int off,
                                 const float* __restrict__ w, const float* __restrict__ freqs,
                                 bf16* __restrict__ oh, bf16* __restrict__ ol, int Sv) {
    int row = blockIdx.x, b = row / Sv, s = row % Sv, t = threadIdx.x;
    const float* xr = in + (long long)row * ldin + off;
    float v[8];
    float4 a0 = *(const float4*)(xr + t * 8);
    float4 a1 = *(const float4*)(xr + t * 8 + 4);
    v[0]=a0.x; v[1]=a0.y; v[2]=a0.z; v[3]=a0.w; v[4]=a1.x; v[5]=a1.y; v[6]=a1.z; v[7]=a1.w;
    float s2 = 0.f;
#pragma unroll
    for (int i = 0; i < 8; i++) s2 += v[i] * v[i];
    __shared__ float sh[256];
    sh[t] = s2;
    __syncthreads();
    for (int o = 128; o > 0; o >>= 1) {
        if (t < o) sh[t] += sh[t + o];
        __syncthreads();
    }
    float r = rsqrtf(sh[0] * (1.f / Dd) + EPSf);
    int dbase = t * 8, h = dbase >> 7, dd = dbase & 127;
    float u[8];
#pragma unroll
    for (int i = 0; i < 8; i++) u[i] = v[i] * r * w[dbase + i];
    if (freqs) {
#pragma unroll
        for (int pr = 0; pr < 4; pr++) {
            float sn, cs;
            __sincosf(freqs[s * 64 + (dd >> 1) + pr], &sn, &cs);
            float xr_ = u[2 * pr], xi = u[2 * pr + 1];
            u[2 * pr]     = xr_ * cs - xi * sn;
            u[2 * pr + 1] = xr_ * sn + xi * cs;
        }
    }
    long long ob = ((long long)(b * Hh + h) * Sv + s) * 128 + dd;
    bf16 hh[8], ll[8];
#pragma unroll
    for (int i = 0; i < 8; i++) split2(u[i], hh[i], ll[i]);
#pragma unroll
    for (int i = 0; i < 8; i += 2) {
        *(__nv_bfloat162*)(oh + ob + i) = mkbf2(hh[i], hh[i + 1]);
        *(__nv_bfloat162*)(ol + ob + i) = mkbf2(ll[i], ll[i + 1]);
    }
}
// V transpose+split: in[b, s, off + h*128 + d] -> out[((b*H+h)*128+d)*Sv + s]
__global__ void k_vt_split(const float* __restrict__ in, int ldin, int off,
                           bf16* __restrict__ oh, bf16* __restrict__ ol, int Sv) {
    __shared__ float t[32][33];
    int bh = blockIdx.z, b = bh >> 4, h = bh & 15;
    int s0 = blockIdx.x * 32, d0 = blockIdx.y * 32;
    int tx = threadIdx.x;
    for (int j = threadIdx.y; j < 32; j += 8)
        t[j][tx] = in[(long long)(b * Sv + s0 + j) * ldin + off + h * 128 + d0 + tx]; // t[s][d]
    __syncthreads();
    for (int j = threadIdx.y; j < 16; j += 8) {
        int d  = j * 2 + (tx >> 4);
        int ss = (tx & 15) * 2;
        float v0 = t[ss][d], v1 = t[ss + 1][d];
        long long o = (long long)(bh * 128 + d0 + d) * Sv + s0 + ss;
        bf16 h0, l0, h1, l1;
        split2(v0, h0, l0); split2(v1, h1, l1);
        *(__nv_bfloat162*)(oh + o) = mkbf2(h0, h1);
        *(__nv_bfloat162*)(ol + o) = mkbf2(l0, l1);
    }
}
// softmax: coalesced AND vectorized — thread t owns elements {2t, 2t+1} + k*512
__global__ void k_softmax_split(const float* __restrict__ S, bf16* __restrict__ oh,
                                bf16* __restrict__ ol, int ncols, float scale) {
    long long row = blockIdx.x;
    const float* p = S + row * ncols;
    bf16* Hp = oh + row * ncols;
    bf16* Lp = ol + row * ncols;
    int t = threadIdx.x;
    int np = ncols >> 9;                 // float2 per thread: 4 (self) / 1 (cross)
    float2 vv[4];
    float lm = -3.4e38f;
    for (int k = 0; k < np; k++) {
        vv[k] = *(const float2*)(p + (k << 9) + 2 * t);
        lm = fmaxf(lm, fmaxf(vv[k].x, vv[k].y));
    }
    __shared__ float sh[256];
    sh[t] = lm; __syncthreads();
    for (int o = 128; o > 0; o >>= 1) { if (t < o) sh[t] = fmaxf(sh[t], sh[t + o]); __syncthreads(); }
    float m = sh[0] * scale;
    __syncthreads();
    float ls = 0.f;
    for (int k = 0; k < np; k++) {
        float e0 = __expf(vv[k].x * scale - m);
        float e1 = __expf(vv[k].y * scale - m);
        vv[k].x = e0; vv[k].y = e1; ls += e0 + e1;
    }
    sh[t] = ls; __syncthreads();
    for (int o = 128; o > 0; o >>= 1) { if (t < o) sh[t] += sh[t + o]; __syncthreads(); }
    float inv = 1.f / sh[0];
    for (int k = 0; k < np; k++) {
        bf16 h0, l0, h1, l1;
        split2(vv[k].x * inv, h0, l0);
        split2(vv[k].y * inv, h1, l1);
        *(__nv_bfloat162*)(Hp + (k << 9) + 2 * t) = mkbf2(h0, h1);
        *(__nv_bfloat162*)(Lp + (k << 9) + 2 * t) = mkbf2(l0, l1);
    }
}

// ---------------------------------------------------------------------------
// Host orchestration
// ---------------------------------------------------------------------------
static void gemm(int epi, const bf16* Ah, const bf16* Al, const bf16* Bh, const bf16* Bl,
                 int M, int N, int K, int lda, int ldb,
                 float* C, bf16* Ch, bf16* Cl, int ldc,
                 const float* b0, const float* b1, const float* b2,
                 const float* em, int gateRow,
                 int batch, int Hdiv,
                 long long sAb, long long sAh, long long sBb, long long sBh,
                 long long sCb, long long sCh)
{
    dim3 g(N / 128, M / 128, batch), bl(256);
    size_t sm = SMEM_TOTAL_G;
    if (epi == 0)
        mma_gemm<0><<<g, bl, sm>>>(Ah, Al, Bh, Bl, K, lda, ldb, C, Ch, Cl, ldc,
                                   b0, b1, b2, em, gateRow, Hdiv, sAb, sAh, sBb, sBh, sCb, sCh);
    else if (epi == 1)
        mma_gemm<1><<<g, bl, sm>>>(Ah, Al, Bh, Bl, K, lda, ldb, C, Ch, Cl, ldc,
                                   b0, b1, b2, em, gateRow, Hdiv, sAb, sAh, sBb, sBh, sCb, sCh);
    else if (epi == 3)
        mma_gemm<3><<<g, bl, sm>>>(Ah, Al, Bh, Bl, K, lda, ldb, C, Ch, Cl, ldc,
                                   b0, b1, b2, em, gateRow, Hdiv, sAb, sAh, sBb, sBh, sCb, sCh);
    else
        mma_gemm<2><<<g, bl, sm>>>(Ah, Al, Bh, Bl, K, lda, ldb, C, Ch, Cl, ldc,
                                   b0, b1, b2, em, gateRow, Hdiv, sAb, sAh, sBb, sBh, sCb, sCh);
}

#define SYM(p, s) cudaGetSymbolAddress((void**)&p, s)

extern "C" void kernel_launch(void* const* d_in, const int* in_sizes, int n_in,
                              void* d_out, int out_size)
{
    bool sig = (in_sizes[13] == Dd);
    int I_snq, I_snk, I_cq_w, I_cq_b, I_ck_w, I_ck_b, I_cv_w, I_cv_b;
    int I_co_w, I_co_b, I_cnq, I_cnk, I_f1_w, I_f1_b, I_f2_w, I_f2_b;
    if (sig) {
        I_snq=13; I_snk=14; I_cq_w=15; I_cq_b=16; I_ck_w=17; I_ck_b=18;
        I_cv_w=19; I_cv_b=20; I_co_w=21; I_co_b=22; I_cnq=23; I_cnk=24;
        I_f1_w=25; I_f1_b=26; I_f2_w=27; I_f2_b=28;
    } else {
        I_cq_w=13; I_cq_b=14; I_ck_w=15; I_ck_b=16; I_cv_w=17; I_cv_b=18;
        I_co_w=19; I_co_b=20; I_f1_w=21; I_f1_b=22; I_f2_w=23; I_f2_b=24;
        I_snq=25; I_snk=26; I_cnq=27; I_cnk=28;
    }
    const float* x    = (const float*)d_in[0];
    const float* e    = (const float*)d_in[1];
    const float* ctx  = (const float*)d_in[2];
    const float* fr   = (const float*)d_in[3];
    const float* mod  = (const float*)d_in[4];
    const float* sq_w = (const float*)d_in[5];  const float* sq_b = (const float*)d_in[6];
    const float* sk_w = (const float*)d_in[7];  const float* sk_b = (const float*)d_in[8];
    const float* sv_w = (const float*)d_in[9];  const float* sv_b = (const float*)d_in[10];
    const float* so_w = (const float*)d_in[11]; const float* so_b = (const float*)d_in[12];
    const float* snq  = (const float*)d_in[I_snq];  const float* snk  = (const float*)d_in[I_snk];
    const float* cq_w = (const float*)d_in[I_cq_w]; const float* cq_b = (const float*)d_in[I_cq_b];
    const float* ck_w = (const float*)d_in[I_ck_w]; const float* ck_b = (const float*)d_in[I_ck_b];
    const float* cv_w = (const float*)d_in[I_cv_w]; const float* cv_b = (const float*)d_in[I_cv_b];
    const float* co_w = (const float*)d_in[I_co_w]; const float* co_b = (const float*)d_in[I_co_b];
    const float* cnq  = (const float*)d_in[I_cnq];  const float* cnk  = (const float*)d_in[I_cnk];
    const float* f1_w = (const float*)d_in[I_f1_w]; const float* f1_b = (const float*)d_in[I_f1_b];
    const float* f2_w = (const float*)d_in[I_f2_w]; const float* f2_b = (const float*)d_in[I_f2_b];

    cudaFuncSetAttribute(mma_gemm<0>, cudaFuncAttributeMaxDynamicSharedMemorySize, SMEM_TOTAL_G);
    cudaFuncSetAttribute(mma_gemm<1>, cudaFuncAttributeMaxDynamicSharedMemorySize, SMEM_TOTAL_G);
    cudaFuncSetAttribute(mma_gemm<2>, cudaFuncAttributeMaxDynamicSharedMemorySize, SMEM_TOTAL_G);
    cudaFuncSetAttribute(mma_gemm<3>, cudaFuncAttributeMaxDynamicSharedMemorySize, SMEM_TOTAL_G);

    float *em_, *qkv, *y, *sc;
    SYM(em_, g_em); SYM(qkv, g_qkv); SYM(y, g_y); SYM(sc, g_sc);
    bf16 *txh, *txl, *cxh, *cxl, *qh, *ql, *kh, *kl, *vth, *vtl, *ph_, *pl_, *fh, *fl;
    SYM(txh, g_txh); SYM(txl, g_txl); SYM(cxh, g_cxh); SYM(cxl, g_cxl);
    SYM(qh, g_qh); SYM(ql, g_ql); SYM(kh, g_kh); SYM(kl, g_kl);
    SYM(vth, g_vth); SYM(vtl, g_vtl); SYM(ph_, g_ph); SYM(pl_, g_pl);
    SYM(fh, g_fh); SYM(fl, g_fl);
    bf16 *wqkvh, *wqkvl, *wckvh, *wckvl, *woh, *wol, *wcqh, *wcql, *wcoh, *wcol, *wf1h, *wf1l, *wf2h, *wf2l;
    SYM(wqkvh, g_wqkvh); SYM(wqkvl, g_wqkvl); SYM(wckvh, g_wckvh); SYM(wckvl, g_wckvl);
    SYM(woh, g_woh); SYM(wol, g_wol); SYM(wcqh, g_wcqh); SYM(wcql, g_wcql);
    SYM(wcoh, g_wcoh); SYM(wcol, g_wcol); SYM(wf1h, g_wf1h); SYM(wf1l, g_wf1l);
    SYM(wf2h, g_wf2h); SYM(wf2l, g_wf2l);

    float* xo = (float*)d_out;
    const long long NX = (long long)Bb * Ss * Dd;
    const long long DD = (long long)Dd * Dd;
    const long long SD = (long long)Ss * Dd;
    const long long SS2 = (long long)Ss * Ss;
    const long long SL = (long long)Ss * LCc;
    const float SCALE = 0.08838834764831845f;
    dim3 tb(32, 8);

    // ---- launches 1-5: capture slot (#4/#5) = production mma_gemm ----
    k_emadd<<<(Bb * 6 * Dd + 255) / 256, 256>>>(e, mod, em_);                           // 1
    k_ln_mod_split<<<Bb * Ss, 256>>>(x, em_, txh, txl, 1, 0);                           // 2
    k_tsplit3<<<dim3(Dd/32, Dd/32, 3), tb>>>(sq_w, sk_w, sv_w, wqkvh, wqkvl);           // 3
    gemm(0, txh, txl, wqkvh, wqkvl, Bb*Ss, Dd, Dd, Dd, Dd,                              // 4 <- capture
         qkv, nullptr, nullptr, 3*Dd, sq_b, nullptr, nullptr, nullptr, -1, 1, 1, 0,0,0,0,0,0);
    gemm(0, txh, txl, wqkvh + DD, wqkvl + DD, Bb*Ss, 2*Dd, Dd, Dd, Dd,                  // 5 <- capture
         qkv + Dd, nullptr, nullptr, 3*Dd, sk_b, sv_b, nullptr, nullptr, -1, 1, 1, 0,0,0,0,0,0);

    k_copy<<<(int)((NX + 255) / 256), 256>>>(x, xo, NX);
    k_tsplit<<<dim3(Dd/32, Dd/32), tb>>>(so_w, woh,  wol,  Dd, Dd);
    k_tsplit<<<dim3(Dd/32, Dd/32), tb>>>(cq_w, wcqh, wcql, Dd, Dd);
    k_tsplit<<<dim3(Dd/32, Dd/32), tb>>>(ck_w, wckvh,      wckvl,      Dd, Dd);
    k_tsplit<<<dim3(Dd/32, Dd/32), tb>>>(cv_w, wckvh + DD, wckvl + DD, Dd, Dd);
    k_tsplit<<<dim3(Dd/32, Dd/32), tb>>>(co_w, wcoh, wcol, Dd, Dd);
    k_tsplit<<<dim3(Ff/32, Dd/32), tb>>>(f1_w, wf1h, wf1l, Dd, Ff);
    k_tsplit<<<dim3(Dd/32, Ff/32), tb>>>(f2_w, wf2h, wf2l, Ff, Dd);

    // ===================== self attention =====================
    k_rms_rope_split<<<Bb * Ss, 256>>>(qkv, 3*Dd, 0,  snq, fr, qh, ql, Ss);
    k_rms_rope_split<<<Bb * Ss, 256>>>(qkv, 3*Dd, Dd, snk, fr, kh, kl, Ss);
    k_vt_split<<<dim3(Ss/32, 4, Bb*Hh), tb>>>(qkv, 3*Dd, 2*Dd, vth, vtl, Ss);
    gemm(0, qh, ql, kh, kl, Ss, Ss, HDd, HDd, HDd,
         sc, nullptr, nullptr, Ss, nullptr, nullptr, nullptr, nullptr, -1, Bb*Hh, 1,
         (long long)Ss*HDd, 0, (long long)Ss*HDd, 0, SS2, 0);
    k_softmax_split<<<Bb * Hh * Ss, 256>>>(sc, ph_, pl_, Ss, SCALE);
    gemm(3, ph_, pl_, vth, vtl, Ss, HDd, Ss, Ss, Ss,
         nullptr, txh, txl, Dd, nullptr, nullptr, nullptr, nullptr, -1, Bb*Hh, Hh,
         (long long)Hh*SS2, SS2, (long long)Hh*HDd*Ss, (long long)HDd*Ss, SD, HDd);
    gemm(2, txh, txl, woh, wol, Bb*Ss, Dd, Dd, Dd, Dd,
         xo, nullptr, nullptr, Dd, so_b, nullptr, nullptr, em_, 2, 1, 1, 0,0,0,0,0,0);

    // ===================== cross attention =====================
    k_split4<<<(int)(NX / 1024), 256>>>(xo, txh, txl, NX);
    gemm(0, txh, txl, wcqh, wcql, Bb*Ss, Dd, Dd, Dd, Dd,
         qkv, nullptr, nullptr, Dd, cq_b, nullptr, nullptr, nullptr, -1, 1, 1, 0,0,0,0,0,0);
    k_rms_rope_split<<<Bb * Ss, 256>>>(qkv, Dd, 0, cnq, nullptr, qh, ql, Ss);
    k_split4<<<(int)((long long)Bb*LCc*Dd / 1024), 256>>>(ctx, cxh, cxl, (long long)Bb*LCc*Dd);
    gemm(0, cxh, cxl, wckvh, wckvl, Bb*LCc, 2*Dd, Dd, Dd, Dd,
         qkv, nullptr, nullptr, 2*Dd, ck_b, cv_b, nullptr, nullptr, -1, 1, 1, 0,0,0,0,0,0);
    k_rms_rope_split<<<Bb * LCc, 256>>>(qkv, 2*Dd, 0, cnk, nullptr, kh, kl, LCc);
    k_vt_split<<<dim3(LCc/32, 4, Bb*Hh), tb>>>(qkv, 2*Dd, Dd, vth, vtl, LCc);
    gemm(0, qh, ql, kh, kl, Ss, LCc, HDd, HDd, HDd,
         sc, nullptr, nullptr, LCc, nullptr, nullptr, nullptr, nullptr, -1, Bb*Hh, 1,
         (long long)Ss*HDd, 0, (long long)LCc*HDd, 0, SL, 0);
    k_softmax_split<<<Bb * Hh * Ss, 256>>>(sc, ph_, pl_, LCc, SCALE);
    gemm(3, ph_, pl_, vth, vtl, Ss, HDd, LCc, LCc, LCc,
         nullptr, txh, txl, Dd, nullptr, nullptr, nullptr, nullptr, -1, Bb*Hh, Hh,
         (long long)Hh*SL, SL, (long long)Hh*HDd*LCc, (long long)HDd*LCc, SD, HDd);
    gemm(2, txh, txl, wcoh, wcol, Bb*Ss, Dd, Dd, Dd, Dd,
         xo, nullptr, nullptr, Dd, co_b, nullptr, nullptr, em_, -1, 1, 1, 0,0,0,0,0,0);

    // ===================== FFN =====================
    k_ln_mod_split<<<Bb * Ss, 256>>>(xo, em_, txh, txl, 4, 3);
    gemm(1, txh, txl, wf1h, wf1l, Bb*Ss, Ff, Dd, Dd, Dd,
         nullptr, fh, fl, Ff, f1_b, nullptr, nullptr, nullptr, -1, 1, 1, 0,0,0,0,0,0);
    gemm(2, fh, fl, wf2h, wf2l, Bb*Ss, Dd, Ff, Ff, Ff,
         xo, nullptr, nullptr, Dd, f2_b, nullptr, nullptr, em_, 5, 1, 1, 0,0,0,0,0,0);
}

// round 14
// speedup vs baseline: 2.0904x; 1.0565x over previous
#include <cuda_runtime.h>
#include <cuda_bf16.h>
#include <cstdint>

using bf16 = __nv_bfloat16;

#define Bb  2
#define Ss  2048
#define Dd  2048
#define Hh  16
#define HDd 128
#define Ff  8192
#define LCc 512
#define EPSf 1e-6f

// ---------------------------------------------------------------------------
// Scratch (__device__ globals; allocation-free rule)
// ---------------------------------------------------------------------------
__device__ float g_em [Bb * 6 * Dd];
__device__ float g_qkv [(size_t)Bb * Ss * 3 * Dd];
__device__ float g_y   [(size_t)Bb * Ss * Dd];
__device__ float g_sc  [(size_t)Bb * Hh * Ss * Ss];

#define DECL2(nm, n) __device__ __align__(128) bf16 nm##h[(size_t)(n)]; __device__ __align__(128) bf16 nm##l[(size_t)(n)];
DECL2(g_tx, (size_t)Bb*Ss*Dd)
DECL2(g_cx, (size_t)Bb*LCc*Dd)
DECL2(g_q,  (size_t)Bb*Ss*Dd)
DECL2(g_k,  (size_t)Bb*Ss*Dd)
DECL2(g_vt, (size_t)Bb*Ss*Dd)
DECL2(g_p,  (size_t)Bb*Hh*Ss*Ss)
DECL2(g_f,  (size_t)Bb*Ss*Ff)
DECL2(g_wqkv, (size_t)3*Dd*Dd)
DECL2(g_wckv, (size_t)2*Dd*Dd)
DECL2(g_wo,   (size_t)Dd*Dd)
DECL2(g_wcq,  (size_t)Dd*Dd)
DECL2(g_wco,  (size_t)Dd*Dd)
DECL2(g_wf1,  (size_t)Ff*Dd)
DECL2(g_wf2,  (size_t)Dd*Ff)

// ---------------------------------------------------------------------------
// helpers
// ---------------------------------------------------------------------------
__device__ __forceinline__ uint32_t smem_u32(const void* p) {
    uint32_t a;
    asm("{ .reg .u64 t; cvta.to.shared.u64 t, %1; cvt.u32.u64 %0, t; }" : "=r"(a) : "l"(p));
    return a;
}
#define CP_COMMIT() asm volatile("cp.async.commit_group;" ::: "memory")

#define LDSM4(d, a) \
  asm volatile("ldmatrix.sync.aligned.m8n8.x4.shared.b16 {%0,%1,%2,%3}, [%4];" \
    : "=r"((d)[0]), "=r"((d)[1]), "=r"((d)[2]), "=r"((d)[3]) : "r"(a))

#define MMA16816(c, a, b0, b1) \
  asm volatile("mma.sync.aligned.m16n8k16.row.col.f32.bf16.bf16.f32 " \
    "{%0,%1,%2,%3}, {%4,%5,%6,%7}, {%8,%9}, {%0,%1,%2,%3};" \
    : "+f"((c)[0]), "+f"((c)[1]), "+f"((c)[2]), "+f"((c)[3]) \
    : "r"((a)[0]), "r"((a)[1]), "r"((a)[2]), "r"((a)[3]), "r"(b0), "r"(b1))

__device__ __forceinline__ float gelu_t(float x) {
    float x3 = x * x * x;
    return 0.5f * x * (1.f + tanhf(0.7978845608028654f * (x + 0.044715f * x3)));
}
__device__ __forceinline__ void split2(float v, bf16& h, bf16& l) {
    h = __float2bfloat16(v);
    l = __float2bfloat16(v - __bfloat162float(h));
}
__device__ __forceinline__ __nv_bfloat162 mkbf2(bf16 a, bf16 b) {
    __nv_bfloat162 r; r.x = a; r.y = b; return r;
}
// segmented bias: segments of 2048 columns (b1 null -> single segment b0)
__device__ __forceinline__ float bget(const float* b0, const float* b1,
                                      const float* b2, int c) {
    if (b1 == nullptr) return b0 ? b0[c] : 0.f;
    int seg = c >> 11, off = c & 2047;
    const float* bp = (seg == 0) ? b0 : ((seg == 1) ? b1 : b2);
    return bp[off];
}

// CTA tile 64x128. stage: Ah(4096) Al(4096) Bh(8192) Bl(8192) = 24KB.
// 64B row pitch, 16B-chunk XOR swizzle: chunk' = chunk ^ ((row>>1)&3)
#define STAGE_BYTES 24576u
#define SMEM_TOTAL_G (3 * 24576)

// ---------------------------------------------------------------------------
// HMMA (mma.sync) GEMM: C(MxN) = A(MxK) @ B^T, B stored [N x K], bf16 hi/lo
// 3-term bf16x3 into fp32 acc. CTA tile 64x128, 3-stage pipeline, single
// __syncthreads per iteration, 3 CTAs/SM (R12 profile: tensor 50%, occ 21%,
// concurrency-bound -> more resident CTAs is the proven lever).
// EPI: 0 fp32(+bias); 1 gelu->bf16 h/l(+bias); 2 xo += (acc+bias)*gate;
//      3 bf16 h/l direct (attention PV).
// ---------------------------------------------------------------------------
template <int EPI>
__global__ __launch_bounds__(256, 3)
void mma_gemm(const bf16* __restrict__ Ah, const bf16* __restrict__ Al,
              const bf16* __restrict__ Bh, const bf16* __restrict__ Bl,
              int K, int lda, int ldb,
              float* C, bf16* Ch, bf16* Cl, int ldc,
              const float* __restrict__ bias0, const float* __restrict__ bias1,
              const float* __restrict__ bias2,
              const float* __restrict__ em, int gateRow,
              int Hdiv,
              long long sAb, long long sAh_, long long sBb, long long sBh_,
              long long sCb, long long sCh_)
{
    extern __shared__ __align__(128) char smem[];
    const uint32_t sbase = smem_u32(smem);
    const int tid = threadIdx.x;
    const int w = tid >> 5, l = tid & 31;
    const int wm = w >> 2, wn = w & 3;          // 2 x 4 warp grid, warp tile 32x32

    const int z = blockIdx.z;
    const int zb = z / Hdiv, zh = z - zb * Hdiv;
    Ah += zb * sAb + zh * sAh_;  Al += zb * sAb + zh * sAh_;
    Bh += zb * sBb + zh * sBh_;  Bl += zb * sBb + zh * sBh_;
    const long long coff = zb * sCb + zh * sCh_;
    const int m0 = blockIdx.y * 64, n0 = blockIdx.x * 128;

    float acc[2][4][4];
#pragma unroll
    for (int i = 0; i < 2; i++)
#pragma unroll
        for (int j = 0; j < 4; j++)
#pragma unroll
            for (int r = 0; r < 4; r++) acc[i][j][r] = 0.f;

    // one k-chunk (32 cols bf16 = 64B/row): A 64 rows (1 pass), B 128 rows (2)
    auto load_chunk = [&](int kc, int stg) {
        const uint32_t sb = sbase + (uint32_t)stg * STAGE_BYTES;
        {   // Ah / Al : 64 rows x 4 chunks = 256 segments, 1 per thread
            int r = tid >> 2, c16 = tid & 3;
            uint32_t so = (uint32_t)(r * 64 + ((c16 ^ ((r >> 1) & 3)) * 16));
            const char* ga = (const char*)(Ah + (long long)(m0 + r) * lda + kc * 32) + c16 * 16;
            asm volatile("cp.async.cg.shared.global [%0], [%1], 16;" :: "r"(sb + so), "l"(ga));
            const char* gl = (const char*)(Al + (long long)(m0 + r) * lda + kc * 32) + c16 * 16;
            asm volatile("cp.async.cg.shared.global [%0], [%1], 16;" :: "r"(sb + 4096u + so), "l"(gl));
        }
        {   // Bh / Bl : 128 rows x 4 chunks = 512 segments, 2 per thread
#pragma unroll
            for (int it = 0; it < 2; it++) {
                int c = tid + it * 256;
                int r = c >> 2, c16 = c & 3;
                uint32_t so = (uint32_t)(r * 64 + ((c16 ^ ((r >> 1) & 3)) * 16));
                const char* gh = (const char*)(Bh + (long long)(n0 + r) * ldb + kc * 32) + c16 * 16;
                asm volatile("cp.async.cg.shared.global [%0], [%1], 16;" :: "r"(sb + 8192u + so), "l"(gh));
                const char* gl = (const char*)(Bl + (long long)(n0 + r) * ldb + kc * 32) + c16 * 16;
                asm volatile("cp.async.cg.shared.global [%0], [%1], 16;" :: "r"(sb + 16384u + so), "l"(gl));
            }
        }
        CP_COMMIT();
    };

    // register-lean term sequencing: aH,bH -> t1; aL -> t2; bL -> t3
    auto compute = [&](int stg) {
        const uint32_t sb = sbase + (uint32_t)stg * STAGE_BYTES;
        uint32_t rowA[2], swA[2], rowB[2], swB[2];
#pragma unroll
        for (int mt = 0; mt < 2; mt++) {
            uint32_t r = (uint32_t)(wm * 32 + mt * 16 + (l & 15));
            rowA[mt] = sb + r * 64u;
            swA[mt]  = (r >> 1) & 3u;
        }
#pragma unroll
        for (int bt = 0; bt < 2; bt++) {
            uint32_t r = (uint32_t)(wn * 32 + bt * 16 + (l & 15));
            rowB[bt] = sb + 8192u + r * 64u;
            swB[bt]  = (r >> 1) & 3u;
        }
#pragma unroll
        for (int ks = 0; ks < 2; ks++) {
            const uint32_t ch = (uint32_t)(ks * 2 + (l >> 4));
            uint32_t aH[2][4], bH[2][4], tmp[2][4];
            uint32_t ra[2], rb[2];
#pragma unroll
            for (int mt = 0; mt < 2; mt++) {
                ra[mt] = rowA[mt] + ((ch ^ swA[mt]) * 16u);
                LDSM4(aH[mt], ra[mt]);
            }
#pragma unroll
            for (int bt = 0; bt < 2; bt++) {
                rb[bt] = rowB[bt] + ((ch ^ swB[bt]) * 16u);
                LDSM4(bH[bt], rb[bt]);
            }
#pragma unroll
            for (int mt = 0; mt < 2; mt++)
#pragma unroll
                for (int nt = 0; nt < 4; nt++) {
                    const int bt = nt >> 1, hi = nt & 1;
                    MMA16816(acc[mt][nt], aH[mt], bH[bt][hi], bH[bt][hi + 2]);
                }
#pragma unroll
            for (int mt = 0; mt < 2; mt++) LDSM4(tmp[mt], ra[mt] + 4096u);   // aL
#pragma unroll
            for (int mt = 0; mt < 2; mt++)
#pragma unroll
                for (int nt = 0; nt < 4; nt++) {
                    const int bt = nt >> 1, hi = nt & 1;
                    MMA16816(acc[mt][nt], tmp[mt], bH[bt][hi], bH[bt][hi + 2]);
                }
#pragma unroll
            for (int bt = 0; bt < 2; bt++) LDSM4(tmp[bt], rb[bt] + 8192u);   // bL
#pragma unroll
            for (int mt = 0; mt < 2; mt++)
#pragma unroll
                for (int nt = 0; nt < 4; nt++) {
                    const int bt = nt >> 1, hi = nt & 1;
                    MMA16816(acc[mt][nt], aH[mt], tmp[bt][hi], tmp[bt][hi + 2]);
                }
        }
    };

    const int nk = K / 32;
    load_chunk(0, 0);
    if (nk > 1) load_chunk(1, 1);
    for (int i = 0; i < nk; i++) {
        if (i + 1 < nk) asm volatile("cp.async.wait_group 1;" ::: "memory");
        else            asm volatile("cp.async.wait_group 0;" ::: "memory");
        __syncthreads();                       // single barrier per iteration
        if (i + 2 < nk) load_chunk(i + 2, (i + 2) % 3);
        compute(i % 3);
    }

    // ---------------- epilogue ----------------
    const int r0f = l >> 2, c0f = (l & 3) * 2;
#pragma unroll
    for (int mt = 0; mt < 2; mt++) {
        const int gr = m0 + wm * 32 + mt * 16 + r0f;
#pragma unroll
        for (int nt = 0; nt < 4; nt++) {
            const int gc = n0 + wn * 32 + nt * 8 + c0f;
            float a0 = acc[mt][nt][0], a1 = acc[mt][nt][1];
            float a2 = acc[mt][nt][2], a3 = acc[mt][nt][3];
            if (EPI == 0) {
                float bx = bget(bias0, bias1, bias2, gc);
                float by = bget(bias0, bias1, bias2, gc + 1);
                float2 u0; u0.x = a0 + bx; u0.y = a1 + by;
                float2 u1; u1.x = a2 + bx; u1.y = a3 + by;
                *(float2*)(C + coff + (long long)gr * ldc + gc) = u0;
                *(float2*)(C + coff + (long long)(gr + 8) * ldc + gc) = u1;
            } else if (EPI == 1) {
                float bx = bias0[gc], by = bias0[gc + 1];
                float v0 = gelu_t(a0 + bx), v1 = gelu_t(a1 + by);
                float v2 = gelu_t(a2 + bx), v3 = gelu_t(a3 + by);
                bf16 h0, l0, h1, l1;
                split2(v0, h0, l0); split2(v1, h1, l1);
                *(__nv_bfloat162*)(Ch + coff + (long long)gr * ldc + gc) = mkbf2(h0, h1);
                *(__nv_bfloat162*)(Cl + coff + (long long)gr * ldc + gc) = mkbf2(l0, l1);
                split2(v2, h0, l0); split2(v3, h1, l1);
                *(__nv_bfloat162*)(Ch + coff + (long long)(gr + 8) * ldc + gc) = mkbf2(h0, h1);
                *(__nv_bfloat162*)(Cl + coff + (long long)(gr + 8) * ldc + gc) = mkbf2(l0, l1);
            } else if (EPI == 3) {
                bf16 h0, l0, h1, l1;
                split2(a0, h0, l0); split2(a1, h1, l1);
                *(__nv_bfloat162*)(Ch + coff + (long long)gr * ldc + gc) = mkbf2(h0, h1);
                *(__nv_bfloat162*)(Cl + coff + (long long)gr * ldc + gc) = mkbf2(l0, l1);
                split2(a2, h0, l0); split2(a3, h1, l1);
                *(__nv_bfloat162*)(Ch + coff + (long long)(gr + 8) * ldc + gc) = mkbf2(h0, h1);
                *(__nv_bfloat162*)(Cl + coff + (long long)(gr + 8) * ldc + gc) = mkbf2(l0, l1);
            } else {
                float bx = bias0[gc], by = bias0[gc + 1];
#pragma unroll
                for (int hh = 0; hh < 2; hh++) {
                    const int row = gr + hh * 8;
                    float va = (hh ? a2 : a0) + bx;
                    float vb = (hh ? a3 : a1) + by;
                    if (gateRow >= 0) {
                        const int b = row / Ss;
                        const float* gp = em + ((long long)b * 6 + gateRow) * Dd;
                        va *= gp[gc]; vb *= gp[gc + 1];
                    }
                    float2 o = *(float2*)(C + coff + (long long)row * ldc + gc);
                    o.x += va; o.y += vb;
                    *(float2*)(C + coff + (long long)row * ldc + gc) = o;
                }
            }
        }
    }
}

// ---------------------------------------------------------------------------
// Elementwise kernels
// ---------------------------------------------------------------------------
__global__ void k_copy(const float* __restrict__ a, float* __restrict__ o, long long n) {
    long long i = (long long)blockIdx.x * 256 + threadIdx.x;
    if (i < n) o[i] = a[i];
}
__global__ void k_emadd(const float* __restrict__ e, const float* __restrict__ mod,
                        float* __restrict__ em) {
    int i = blockIdx.x * 256 + threadIdx.x;
    if (i < Bb * 6 * Dd) em[i] = e[i] + mod[i % (6 * Dd)];
}
__global__ void k_split4(const float* __restrict__ in, bf16* __restrict__ oh,
                         bf16* __restrict__ ol, long long n) {
    long long i = ((long long)blockIdx.x * 256 + threadIdx.x) * 4;
    if (i >= n) return;
    float4 v = *(const float4*)(in + i);
    bf16 h0, l0, h1, l1;
    split2(v.x, h0, l0); split2(v.y, h1, l1);
    *(__nv_bfloat162*)(oh + i) = mkbf2(h0, h1);
    *(__nv_bfloat162*)(ol + i) = mkbf2(l0, l1);
    split2(v.z, h0, l0); split2(v.w, h1, l1);
    *(__nv_bfloat162*)(oh + i + 2) = mkbf2(h0, h1);
    *(__nv_bfloat162*)(ol + i + 2) = mkbf2(l0, l1);
}
// transpose+split: W[K x N] -> T[N x K] bf16 h/l
__global__ void k_tsplit(const float* __restrict__ W, bf16* __restrict__ Th,
                         bf16* __restrict__ Tl, int Kd, int Nd) {
    __shared__ float t[32][33];
    int n0 = blockIdx.x * 32, k0 = blockIdx.y * 32;
    int tx = threadIdx.x;
    for (int j = threadIdx.y; j < 32; j += 8)
        t[j][tx] = W[(long long)(k0 + j) * Nd + n0 + tx];        // t[k][n]
    __syncthreads();
    for (int j = threadIdx.y; j < 16; j += 8) {
        int n  = j * 2 + (tx >> 4);       // 0..31
        int kk = (tx & 15) * 2;           // 0..30
        float v0 = t[kk][n], v1 = t[kk + 1][n];
        long long o = (long long)(n0 + n) * Kd + k0 + kk;
        bf16 h0, l0, h1, l1;
        split2(v0, h0, l0); split2(v1, h1, l1);
        *(__nv_bfloat162*)(Th + o) = mkbf2(h0, h1);
        *(__nv_bfloat162*)(Tl + o) = mkbf2(l0, l1);
    }
}
// 3 square weights in one launch (blockIdx.z selects)
__global__ void k_tsplit3(const float* __restrict__ w0, const float* __restrict__ w1,
                          const float* __restrict__ w2,
                          bf16* __restrict__ Th, bf16* __restrict__ Tl) {
    __shared__ float t[32][33];
    const float* W = (blockIdx.z == 0) ? w0 : ((blockIdx.z == 1) ? w1 : w2);
    size_t zoff = (size_t)blockIdx.z * Dd * Dd;
    int n0 = blockIdx.x * 32, k0 = blockIdx.y * 32;
    int tx = threadIdx.x;
    for (int j = threadIdx.y; j < 32; j += 8)
        t[j][tx] = W[(long long)(k0 + j) * Dd + n0 + tx];
    __syncthreads();
    for (int j = threadIdx.y; j < 16; j += 8) {
        int n  = j * 2 + (tx >> 4);
        int kk = (tx & 15) * 2;
        float v0 = t[kk][n], v1 = t[kk + 1][n];
        long long o = (long long)zoff + (long long)(n0 + n) * Dd + k0 + kk;
        bf16 h0, l0, h1, l1;
        split2(v0, h0, l0); split2(v1, h1, l1);
        *(__nv_bfloat162*)(Th + o) = mkbf2(h0, h1);
        *(__nv_bfloat162*)(Tl + o) = mkbf2(l0, l1);
    }
}
__global__ void k_ln_mod_split(const float* __restrict__ x, const float* __restrict__ em,
                               bf16* __restrict__ oh, bf16* __restrict__ ol,
                               int scaleRow, int shiftRow) {
    int row = blockIdx.x, b = row / Ss, t = threadIdx.x;
    const float* xr = x + (long long)row * Dd;
    const float* es = em + ((long long)b * 6 + scaleRow) * Dd;
    const float* eh = em + ((long long)b * 6 + shiftRow) * Dd;
    float v[8];
    float4 a0 = *(const float4*)(xr + t * 8);
    float4 a1 = *(const float4*)(xr + t * 8 + 4);
    v[0]=a0.x; v[1]=a0.y; v[2]=a0.z; v[3]=a0.w; v[4]=a1.x; v[5]=a1.y; v[6]=a1.z; v[7]=a1.w;
    float s = 0.f, s2 = 0.f;
#pragma unroll
    for (int i = 0; i < 8; i++) { s += v[i]; s2 += v[i] * v[i]; }
    __shared__ float sh[512];
    sh[t] = s; sh[256 + t] = s2;
    __syncthreads();
    for (int o = 128; o > 0; o >>= 1) {
        if (t < o) { sh[t] += sh[t + o]; sh[256 + t] += sh[256 + t + o]; }
        __syncthreads();
    }
    float m = sh[0] * (1.f / Dd);
    float var = sh[256] * (1.f / Dd) - m * m;
    float r = rsqrtf(var + EPSf);
    bf16 hh[8], ll[8];
#pragma unroll
    for (int i = 0; i < 8; i++) {
        int dI = t * 8 + i;
        float u = (v[i] - m) * r * (1.f + es[dI]) + eh[dI];
        split2(u, hh[i], ll[i]);
    }
    long long ob = (long long)row * Dd + t * 8;
#pragma unroll
    for (int i = 0; i < 8; i += 2) {
        *(__nv_bfloat162*)(oh + ob + i) = mkbf2(hh[i], hh[i + 1]);
        *(__nv_bfloat162*)(ol + ob + i) = mkbf2(ll[i], ll[i + 1]);
    }
}
__global__ void k_rms_rope_split(const float* __restrict__ in, int ldin, int off,
                                 const float* __restrict__ w, const float* __restrict__ freqs,
                                 bf16* __restrict__ oh, bf16* __restrict__ ol, int Sv) {
    int row = blockIdx.x, b = row / Sv, s = row % Sv, t = threadIdx.x;
    const float* xr = in + (long long)row * ldin + off;
    float v[8];
    float4 a0 = *(const float4*)(xr + t * 8);
    float4 a1 = *(const float4*)(xr + t * 8 + 4);
    v[0]=a0.x; v[1]=a0.y; v[2]=a0.z; v[3]=a0.w; v[4]=a1.x; v[5]=a1.y; v[6]=a1.z; v[7]=a1.w;
    float s2 = 0.f;
#pragma unroll
    for (int i = 0; i < 8; i++) s2 += v[i] * v[i];
    __shared__ float sh[256];
    sh[t] = s2;
    __syncthreads();
    for (int o = 128; o > 0; o >>= 1) {
        if (t < o) sh[t] += sh[t + o];
        __syncthreads();
    }
    float r = rsqrtf(sh[0] * (1.f / Dd) + EPSf);
    int dbase = t * 8, h = dbase >> 7, dd = dbase & 127;
    float u[8];
#pragma unroll
    for (int i = 0; i < 8; i++) u[i] = v[i] * r * w[dbase + i];
    if (freqs) {
#pragma unroll
        for (int pr = 0; pr < 4; pr++) {
            float sn, cs;
            __sincosf(freqs[s * 64 + (dd >> 1) + pr], &sn, &cs);
            float xr_ = u[2 * pr], xi = u[2 * pr + 1];
            u[2 * pr]     = xr_ * cs - xi * sn;
            u[2 * pr + 1] = xr_ * sn + xi * cs;
        }
    }
    long long ob = ((long long)(b * Hh + h) * Sv + s) * 128 + dd;
    bf16 hh[8], ll[8];
#pragma unroll
    for (int i = 0; i < 8; i++) split2(u[i], hh[i], ll[i]);
#pragma unroll
    for (int i = 0; i < 8; i += 2) {
        *(__nv_bfloat162*)(oh + ob + i) = mkbf2(hh[i], hh[i + 1]);
        *(__nv_bfloat162*)(ol + ob + i) = mkbf2(ll[i], ll[i + 1]);
    }
}
// V transpose+split: in[b, s, off + h*128 + d] -> out[((b*H+h)*128+d)*Sv + s]
__global__ void k_vt_split(const float* __restrict__ in, int ldin, int off,
                           bf16* __restrict__ oh, bf16* __restrict__ ol, int Sv) {
    __shared__ float t[32][33];
    int bh = blockIdx.z, b = bh >> 4, h = bh & 15;
    int s0 = blockIdx.x * 32, d0 = blockIdx.y * 32;
    int tx = threadIdx.x;
    for (int j = threadIdx.y; j < 32; j += 8)
        t[j][tx] = in[(long long)(b * Sv + s0 + j) * ldin + off + h * 128 + d0 + tx]; // t[s][d]
    __syncthreads();
    for (int j = threadIdx.y; j < 16; j += 8) {
        int d  = j * 2 + (tx >> 4);
        int ss = (tx & 15) * 2;
        float v0 = t[ss][d], v1 = t[ss + 1][d];
        long long o = (long long)(bh * 128 + d0 + d) * Sv + s0 + ss;
        bf16 h0, l0, h1, l1;
        split2(v0, h0, l0); split2(v1, h1, l1);
        *(__nv_bfloat162*)(oh + o) = mkbf2(h0, h1);
        *(__nv_bfloat162*)(ol + o) = mkbf2(l0, l1);
    }
}
// softmax: coalesced AND vectorized — thread t owns elements {2t, 2t+1} + k*512
__global__ void k_softmax_split(const float* __restrict__ S, bf16* __restrict__ oh,
                                bf16* __restrict__ ol, int ncols, float scale) {
    long long row = blockIdx.x;
    const float* p = S + row * ncols;
    bf16* Hp = oh + row * ncols;
    bf16* Lp = ol + row * ncols;
    int t = threadIdx.x;
    int np = ncols >> 9;                 // float2 per thread: 4 (self) / 1 (cross)
    float2 vv[4];
    float lm = -3.4e38f;
    for (int k = 0; k < np; k++) {
        vv[k] = *(const float2*)(p + (k << 9) + 2 * t);
        lm = fmaxf(lm, fmaxf(vv[k].x, vv[k].y));
    }
    __shared__ float sh[256];
    sh[t] = lm; __syncthreads();
    for (int o = 128; o > 0; o >>= 1) { if (t < o) sh[t] = fmaxf(sh[t], sh[t + o]); __syncthreads(); }
    float m = sh[0] * scale;
    __syncthreads();
    float ls = 0.f;
    for (int k = 0; k < np; k++) {
        float e0 = __expf(vv[k].x * scale - m);
        float e1 = __expf(vv[k].y * scale - m);
        vv[k].x = e0; vv[k].y = e1; ls += e0 + e1;
    }
    sh[t] = ls; __syncthreads();
    for (int o = 128; o > 0; o >>= 1) { if (t < o) sh[t] += sh[t + o]; __syncthreads(); }
    float inv = 1.f / sh[0];
    for (int k = 0; k < np; k++) {
        bf16 h0, l0, h1, l1;
        split2(vv[k].x * inv, h0, l0);
        split2(vv[k].y * inv, h1, l1);
        *(__nv_bfloat162*)(Hp + (k << 9) + 2 * t) = mkbf2(h0, h1);
        *(__nv_bfloat162*)(Lp + (k << 9) + 2 * t) = mkbf2(l0, l1);
    }
}

// ---------------------------------------------------------------------------
// Host orchestration
// ---------------------------------------------------------------------------
static void gemm(int epi, const bf16* Ah, const bf16* Al, const bf16* Bh, const bf16* Bl,
                 int M, int N, int K, int lda, int ldb,
                 float* C, bf16* Ch, bf16* Cl, int ldc,
                 const float* b0, const float* b1, const float* b2,
                 const float* em, int gateRow,
                 int batch, int Hdiv,
                 long long sAb, long long sAh, long long sBb, long long sBh,
                 long long sCb, long long sCh)
{
    dim3 g(N / 128, M / 64, batch), bl(256);
    size_t sm = SMEM_TOTAL_G;
    if (epi == 0)
        mma_gemm<0><<<g, bl, sm>>>(Ah, Al, Bh, Bl, K, lda, ldb, C, Ch, Cl, ldc,
                                   b0, b1, b2, em, gateRow, Hdiv, sAb, sAh, sBb, sBh, sCb, sCh);
    else if (epi == 1)
        mma_gemm<1><<<g, bl, sm>>>(Ah, Al, Bh, Bl, K, lda, ldb, C, Ch, Cl, ldc,
                                   b0, b1, b2, em, gateRow, Hdiv, sAb, sAh, sBb, sBh, sCb, sCh);
    else if (epi == 3)
        mma_gemm<3><<<g, bl, sm>>>(Ah, Al, Bh, Bl, K, lda, ldb, C, Ch, Cl, ldc,
                                   b0, b1, b2, em, gateRow, Hdiv, sAb, sAh, sBb, sBh, sCb, sCh);
    else
        mma_gemm<2><<<g, bl, sm>>>(Ah, Al, Bh, Bl, K, lda, ldb, C, Ch, Cl, ldc,
                                   b0, b1, b2, em, gateRow, Hdiv, sAb, sAh, sBb, sBh, sCb, sCh);
}

#define SYM(p, s) cudaGetSymbolAddress((void**)&p, s)

extern "C" void kernel_launch(void* const* d_in, const int* in_sizes, int n_in,
                              void* d_out, int out_size)
{
    bool sig = (in_sizes[13] == Dd);
    int I_snq, I_snk, I_cq_w, I_cq_b, I_ck_w, I_ck_b, I_cv_w, I_cv_b;
    int I_co_w, I_co_b, I_cnq, I_cnk, I_f1_w, I_f1_b, I_f2_w, I_f2_b;
    if (sig) {
        I_snq=13; I_snk=14; I_cq_w=15; I_cq_b=16; I_ck_w=17; I_ck_b=18;
        I_cv_w=19; I_cv_b=20; I_co_w=21; I_co_b=22; I_cnq=23; I_cnk=24;
        I_f1_w=25; I_f1_b=26; I_f2_w=27; I_f2_b=28;
    } else {
        I_cq_w=13; I_cq_b=14; I_ck_w=15; I_ck_b=16; I_cv_w=17; I_cv_b=18;
        I_co_w=19; I_co_b=20; I_f1_w=21; I_f1_b=22; I_f2_w=23; I_f2_b=24;
        I_snq=25; I_snk=26; I_cnq=27; I_cnk=28;
    }
    const float* x    = (const float*)d_in[0];
    const float* e    = (const float*)d_in[1];
    const float* ctx  = (const float*)d_in[2];
    const float* fr   = (const float*)d_in[3];
    const float* mod  = (const float*)d_in[4];
    const float* sq_w = (const float*)d_in[5];  const float* sq_b = (const float*)d_in[6];
    const float* sk_w = (const float*)d_in[7];  const float* sk_b = (const float*)d_in[8];
    const float* sv_w = (const float*)d_in[9];  const float* sv_b = (const float*)d_in[10];
    const float* so_w = (const float*)d_in[11]; const float* so_b = (const float*)d_in[12];
    const float* snq  = (const float*)d_in[I_snq];  const float* snk  = (const float*)d_in[I_snk];
    const float* cq_w = (const float*)d_in[I_cq_w]; const float* cq_b = (const float*)d_in[I_cq_b];
    const float* ck_w = (const float*)d_in[I_ck_w]; const float* ck_b = (const float*)d_in[I_ck_b];
    const float* cv_w = (const float*)d_in[I_cv_w]; const float* cv_b = (const float*)d_in[I_cv_b];
    const float* co_w = (const float*)d_in[I_co_w]; const float* co_b = (const float*)d_in[I_co_b];
    const float* cnq  = (const float*)d_in[I_cnq];  const float* cnk  = (const float*)d_in[I_cnk];
    const float* f1_w = (const float*)d_in[I_f1_w]; const float* f1_b = (const float*)d_in[I_f1_b];
    const float* f2_w = (const float*)d_in[I_f2_w]; const float* f2_b = (const float*)d_in[I_f2_b];

    cudaFuncSetAttribute(mma_gemm<0>, cudaFuncAttributeMaxDynamicSharedMemorySize, SMEM_TOTAL_G);
    cudaFuncSetAttribute(mma_gemm<1>, cudaFuncAttributeMaxDynamicSharedMemorySize, SMEM_TOTAL_G);
    cudaFuncSetAttribute(mma_gemm<2>, cudaFuncAttributeMaxDynamicSharedMemorySize, SMEM_TOTAL_G);
    cudaFuncSetAttribute(mma_gemm<3>, cudaFuncAttributeMaxDynamicSharedMemorySize, SMEM_TOTAL_G);

    float *em_, *qkv, *y, *sc;
    SYM(em_, g_em); SYM(qkv, g_qkv); SYM(y, g_y); SYM(sc, g_sc);
    bf16 *txh, *txl, *cxh, *cxl, *qh, *ql, *kh, *kl, *vth, *vtl, *ph_, *pl_, *fh, *fl;
    SYM(txh, g_txh); SYM(txl, g_txl); SYM(cxh, g_cxh); SYM(cxl, g_cxl);
    SYM(qh, g_qh); SYM(ql, g_ql); SYM(kh, g_kh); SYM(kl, g_kl);
    SYM(vth, g_vth); SYM(vtl, g_vtl); SYM(ph_, g_ph); SYM(pl_, g_pl);
    SYM(fh, g_fh); SYM(fl, g_fl);
    bf16 *wqkvh, *wqkvl, *wckvh, *wckvl, *woh, *wol, *wcqh, *wcql, *wcoh, *wcol, *wf1h, *wf1l, *wf2h, *wf2l;
    SYM(wqkvh, g_wqkvh); SYM(wqkvl, g_wqkvl); SYM(wckvh, g_wckvh); SYM(wckvl, g_wckvl);
    SYM(woh, g_woh); SYM(wol, g_wol); SYM(wcqh, g_wcqh); SYM(wcql, g_wcql);
    SYM(wcoh, g_wcoh); SYM(wcol, g_wcol); SYM(wf1h, g_wf1h); SYM(wf1l, g_wf1l);
    SYM(wf2h, g_wf2h); SYM(wf2l, g_wf2l);

    float* xo = (float*)d_out;
    const long long NX = (long long)Bb * Ss * Dd;
    const long long DD = (long long)Dd * Dd;
    const long long SD = (long long)Ss * Dd;
    const long long SS2 = (long long)Ss * Ss;
    const long long SL = (long long)Ss * LCc;
    const float SCALE = 0.08838834764831845f;
    dim3 tb(32, 8);

    // ---- launches 1-5: capture slot (#4/#5) = production mma_gemm ----
    k_emadd<<<(Bb * 6 * Dd + 255) / 256, 256>>>(e, mod, em_);                           // 1
    k_ln_mod_split<<<Bb * Ss, 256>>>(x, em_, txh, txl, 1, 0);                           // 2
    k_tsplit3<<<dim3(Dd/32, Dd/32, 3), tb>>>(sq_w, sk_w, sv_w, wqkvh, wqkvl);           // 3
    gemm(0, txh, txl, wqkvh, wqkvl, Bb*Ss, Dd, Dd, Dd, Dd,                              // 4 <- capture
         qkv, nullptr, nullptr, 3*Dd, sq_b, nullptr, nullptr, nullptr, -1, 1, 1, 0,0,0,0,0,0);
    gemm(0, txh, txl, wqkvh + DD, wqkvl + DD, Bb*Ss, 2*Dd, Dd, Dd, Dd,                  // 5 <- capture
         qkv + Dd, nullptr, nullptr, 3*Dd, sk_b, sv_b, nullptr, nullptr, -1, 1, 1, 0,0,0,0,0,0);

    k_copy<<<(int)((NX + 255) / 256), 256>>>(x, xo, NX);
    k_tsplit<<<dim3(Dd/32, Dd/32), tb>>>(so_w, woh,  wol,  Dd, Dd);
    k_tsplit<<<dim3(Dd/32, Dd/32), tb>>>(cq_w, wcqh, wcql, Dd, Dd);
    k_tsplit<<<dim3(Dd/32, Dd/32), tb>>>(ck_w, wckvh,      wckvl,      Dd, Dd);
    k_tsplit<<<dim3(Dd/32, Dd/32), tb>>>(cv_w, wckvh + DD, wckvl + DD, Dd, Dd);
    k_tsplit<<<dim3(Dd/32, Dd/32), tb>>>(co_w, wcoh, wcol, Dd, Dd);
    k_tsplit<<<dim3(Ff/32, Dd/32), tb>>>(f1_w, wf1h, wf1l, Dd, Ff);
    k_tsplit<<<dim3(Dd/32, Ff/32), tb>>>(f2_w, wf2h, wf2l, Ff, Dd);

    // ===================== self attention =====================
    k_rms_rope_split<<<Bb * Ss, 256>>>(qkv, 3*Dd, 0,  snq, fr, qh, ql, Ss);
    k_rms_rope_split<<<Bb * Ss, 256>>>(qkv, 3*Dd, Dd, snk, fr, kh, kl, Ss);
    k_vt_split<<<dim3(Ss/32, 4, Bb*Hh), tb>>>(qkv, 3*Dd, 2*Dd, vth, vtl, Ss);
    gemm(0, qh, ql, kh, kl, Ss, Ss, HDd, HDd, HDd,
         sc, nullptr, nullptr, Ss, nullptr, nullptr, nullptr, nullptr, -1, Bb*Hh, 1,
         (long long)Ss*HDd, 0, (long long)Ss*HDd, 0, SS2, 0);
    k_softmax_split<<<Bb * Hh * Ss, 256>>>(sc, ph_, pl_, Ss, SCALE);
    gemm(3, ph_, pl_, vth, vtl, Ss, HDd, Ss, Ss, Ss,
         nullptr, txh, txl, Dd, nullptr, nullptr, nullptr, nullptr, -1, Bb*Hh, Hh,
         (long long)Hh*SS2, SS2, (long long)Hh*HDd*Ss, (long long)HDd*Ss, SD, HDd);
    gemm(2, txh, txl, woh, wol, Bb*Ss, Dd, Dd, Dd, Dd,
         xo, nullptr, nullptr, Dd, so_b, nullptr, nullptr, em_, 2, 1, 1, 0,0,0,0,0,0);

    // ===================== cross attention =====================
    k_split4<<<(int)(NX / 1024), 256>>>(xo, txh, txl, NX);
    gemm(0, txh, txl, wcqh, wcql, Bb*Ss, Dd, Dd, Dd, Dd,
         qkv, nullptr, nullptr, Dd, cq_b, nullptr, nullptr, nullptr, -1, 1, 1, 0,0,0,0,0,0);
    k_rms_rope_split<<<Bb * Ss, 256>>>(qkv, Dd, 0, cnq, nullptr, qh, ql, Ss);
    k_split4<<<(int)((long long)Bb*LCc*Dd / 1024), 256>>>(ctx, cxh, cxl, (long long)Bb*LCc*Dd);
    gemm(0, cxh, cxl, wckvh, wckvl, Bb*LCc, 2*Dd, Dd, Dd, Dd,
         qkv, nullptr, nullptr, 2*Dd, ck_b, cv_b, nullptr, nullptr, -1, 1, 1, 0,0,0,0,0,0);
    k_rms_rope_split<<<Bb * LCc, 256>>>(qkv, 2*Dd, 0, cnk, nullptr, kh, kl, LCc);
    k_vt_split<<<dim3(LCc/32, 4, Bb*Hh), tb>>>(qkv, 2*Dd, Dd, vth, vtl, LCc);
    gemm(0, qh, ql, kh, kl, Ss, LCc, HDd, HDd, HDd,
         sc, nullptr, nullptr, LCc, nullptr, nullptr, nullptr, nullptr, -1, Bb*Hh, 1,
         (long long)Ss*HDd, 0, (long long)LCc*HDd, 0, SL, 0);
    k_softmax_split<<<Bb * Hh * Ss, 256>>>(sc, ph_, pl_, LCc, SCALE);
    gemm(3, ph_, pl_, vth, vtl, Ss, HDd, LCc, LCc, LCc,
         nullptr, txh, txl, Dd, nullptr, nullptr, nullptr, nullptr, -1, Bb*Hh, Hh,
         (long long)Hh*SL, SL, (long long)Hh*HDd*LCc, (long long)HDd*LCc, SD, HDd);
    gemm(2, txh, txl, wcoh, wcol, Bb*Ss, Dd, Dd, Dd, Dd,
         xo, nullptr, nullptr, Dd, co_b, nullptr, nullptr, em_, -1, 1, 1, 0,0,0,0,0,0);

    // ===================== FFN =====================
    k_ln_mod_split<<<Bb * Ss, 256>>>(xo, em_, txh, txl, 4, 3);
    gemm(1, txh, txl, wf1h, wf1l, Bb*Ss, Ff, Dd, Dd, Dd,
         nullptr, fh, fl, Ff, f1_b, nullptr, nullptr, nullptr, -1, 1, 1, 0,0,0,0,0,0);
    gemm(2, fh, fl, wf2h, wf2l, Bb*Ss, Dd, Ff, Ff, Ff,
         xo, nullptr, nullptr, Dd, f2_b, nullptr, nullptr, em_, 5, 1, 1, 0,0,0,0,0,0);
}

// round 16
// speedup vs baseline: 2.1420x; 1.0247x over previous
#include <cuda_runtime.h>
#include <cuda_bf16.h>
#include <cstdint>

using bf16 = __nv_bfloat16;

#define Bb  2
#define Ss  2048
#define Dd  2048
#define Hh  16
#define HDd 128
#define Ff  8192
#define LCc 512
#define EPSf 1e-6f

// ---------------------------------------------------------------------------
// Scratch (__device__ globals; allocation-free rule)
// ---------------------------------------------------------------------------
__device__ float g_em [Bb * 6 * Dd];
__device__ float g_qkv [(size_t)Bb * Ss * 3 * Dd];
__device__ float g_sc  [(size_t)Bb * Hh * Ss * Ss];
__device__ float g_scc [(size_t)Bb * Hh * Ss * LCc];   // cross scores (stream-safe)

#define DECL2(nm, n) __device__ __align__(128) bf16 nm##h[(size_t)(n)]; __device__ __align__(128) bf16 nm##l[(size_t)(n)];
DECL2(g_tx, (size_t)Bb*Ss*Dd)
DECL2(g_cx, (size_t)Bb*LCc*Dd)
DECL2(g_q,  (size_t)Bb*Ss*Dd)
DECL2(g_k,  (size_t)Bb*Ss*Dd)
DECL2(g_vt, (size_t)Bb*Ss*Dd)
DECL2(g_ck, (size_t)Bb*LCc*Dd)          // cross keys (stream-safe)
DECL2(g_cvt,(size_t)Bb*LCc*Dd)          // cross V^T (stream-safe)
DECL2(g_p,  (size_t)Bb*Hh*Ss*Ss)
DECL2(g_pc, (size_t)Bb*Hh*Ss*LCc)       // cross probs (stream-safe)
DECL2(g_f,  (size_t)Bb*Ss*Ff)
DECL2(g_wqkv, (size_t)3*Dd*Dd)
DECL2(g_wckv, (size_t)2*Dd*Dd)
DECL2(g_wo,   (size_t)Dd*Dd)
DECL2(g_wcq,  (size_t)Dd*Dd)
DECL2(g_wco,  (size_t)Dd*Dd)
DECL2(g_wf1,  (size_t)Ff*Dd)
DECL2(g_wf2,  (size_t)Dd*Ff)

// ---------------------------------------------------------------------------
// helpers
// ---------------------------------------------------------------------------
__device__ __forceinline__ uint32_t smem_u32(const void* p) {
    uint32_t a;
    asm("{ .reg .u64 t; cvta.to.shared.u64 t, %1; cvt.u32.u64 %0, t; }" : "=r"(a) : "l"(p));
    return a;
}
#define CP_COMMIT() asm volatile("cp.async.commit_group;" ::: "memory")

#define LDSM4(d, a) \
  asm volatile("ldmatrix.sync.aligned.m8n8.x4.shared.b16 {%0,%1,%2,%3}, [%4];" \
    : "=r"((d)[0]), "=r"((d)[1]), "=r"((d)[2]), "=r"((d)[3]) : "r"(a))

#define MMA16816(c, a, b0, b1) \
  asm volatile("mma.sync.aligned.m16n8k16.row.col.f32.bf16.bf16.f32 " \
    "{%0,%1,%2,%3}, {%4,%5,%6,%7}, {%8,%9}, {%0,%1,%2,%3};" \
    : "+f"((c)[0]), "+f"((c)[1]), "+f"((c)[2]), "+f"((c)[3]) \
    : "r"((a)[0]), "r"((a)[1]), "r"((a)[2]), "r"((a)[3]), "r"(b0), "r"(b1))

__device__ __forceinline__ float gelu_t(float x) {
    float x3 = x * x * x;
    return 0.5f * x * (1.f + tanhf(0.7978845608028654f * (x + 0.044715f * x3)));
}
__device__ __forceinline__ void split2(float v, bf16& h, bf16& l) {
    h = __float2bfloat16(v);
    l = __float2bfloat16(v - __bfloat162float(h));
}
__device__ __forceinline__ __nv_bfloat162 mkbf2(bf16 a, bf16 b) {
    __nv_bfloat162 r; r.x = a; r.y = b; return r;
}
__device__ __forceinline__ float bget(const float* b0, const float* b1,
                                      const float* b2, int c) {
    if (b1 == nullptr) return b0 ? b0[c] : 0.f;
    int seg = c >> 11, off = c & 2047;
    const float* bp = (seg == 0) ? b0 : ((seg == 1) ? b1 : b2);
    return bp[off];
}

// CTA tile 64x128. stage: Ah(4096) Al(4096) Bh(8192) Bl(8192) = 24KB.
// 64B row pitch, 16B-chunk XOR swizzle: chunk' = chunk ^ ((row>>1)&3)
#define STAGE_BYTES 24576u
#define SMEM_TOTAL_G (3 * 24576)

// ---------------------------------------------------------------------------
// HMMA GEMM (R14-measured: tensor 56.7%, 3 CTAs/SM) — UNCHANGED.
// ---------------------------------------------------------------------------
template <int EPI>
__global__ __launch_bounds__(256, 3)
void mma_gemm(const bf16* __restrict__ Ah, const bf16* __restrict__ Al,
              const bf16* __restrict__ Bh, const bf16* __restrict__ Bl,
              int K, int lda, int ldb,
              float* C, bf16* Ch, bf16* Cl, int ldc,
              const float* __restrict__ bias0, const float* __restrict__ bias1,
              const float* __restrict__ bias2,
              const float* __restrict__ em, int gateRow,
              int Hdiv,
              long long sAb, long long sAh_, long long sBb, long long sBh_,
              long long sCb, long long sCh_)
{
    extern __shared__ __align__(128) char smem[];
    const uint32_t sbase = smem_u32(smem);
    const int tid = threadIdx.x;
    const int w = tid >> 5, l = tid & 31;
    const int wm = w >> 2, wn = w & 3;

    const int z = blockIdx.z;
    const int zb = z / Hdiv, zh = z - zb * Hdiv;
    Ah += zb * sAb + zh * sAh_;  Al += zb * sAb + zh * sAh_;
    Bh += zb * sBb + zh * sBh_;  Bl += zb * sBb + zh * sBh_;
    const long long coff = zb * sCb + zh * sCh_;
    const int m0 = blockIdx.y * 64, n0 = blockIdx.x * 128;

    float acc[2][4][4];
#pragma unroll
    for (int i = 0; i < 2; i++)
#pragma unroll
        for (int j = 0; j < 4; j++)
#pragma unroll
            for (int r = 0; r < 4; r++) acc[i][j][r] = 0.f;

    auto load_chunk = [&](int kc, int stg) {
        const uint32_t sb = sbase + (uint32_t)stg * STAGE_BYTES;
        {
            int r = tid >> 2, c16 = tid & 3;
            uint32_t so = (uint32_t)(r * 64 + ((c16 ^ ((r >> 1) & 3)) * 16));
            const char* ga = (const char*)(Ah + (long long)(m0 + r) * lda + kc * 32) + c16 * 16;
            asm volatile("cp.async.cg.shared.global [%0], [%1], 16;" :: "r"(sb + so), "l"(ga));
            const char* gl = (const char*)(Al + (long long)(m0 + r) * lda + kc * 32) + c16 * 16;
            asm volatile("cp.async.cg.shared.global [%0], [%1], 16;" :: "r"(sb + 4096u + so), "l"(gl));
        }
        {
#pragma unroll
            for (int it = 0; it < 2; it++) {
                int c = tid + it * 256;
                int r = c >> 2, c16 = c & 3;
                uint32_t so = (uint32_t)(r * 64 + ((c16 ^ ((r >> 1) & 3)) * 16));
                const char* gh = (const char*)(Bh + (long long)(n0 + r) * ldb + kc * 32) + c16 * 16;
                asm volatile("cp.async.cg.shared.global [%0], [%1], 16;" :: "r"(sb + 8192u + so), "l"(gh));
                const char* gl = (const char*)(Bl + (long long)(n0 + r) * ldb + kc * 32) + c16 * 16;
                asm volatile("cp.async.cg.shared.global [%0], [%1], 16;" :: "r"(sb + 16384u + so), "l"(gl));
            }
        }
        CP_COMMIT();
    };

    auto compute = [&](int stg) {
        const uint32_t sb = sbase + (uint32_t)stg * STAGE_BYTES;
        uint32_t rowA[2], swA[2], rowB[2], swB[2];
#pragma unroll
        for (int mt = 0; mt < 2; mt++) {
            uint32_t r = (uint32_t)(wm * 32 + mt * 16 + (l & 15));
            rowA[mt] = sb + r * 64u;
            swA[mt]  = (r >> 1) & 3u;
        }
#pragma unroll
        for (int bt = 0; bt < 2; bt++) {
            uint32_t r = (uint32_t)(wn * 32 + bt * 16 + (l & 15));
            rowB[bt] = sb + 8192u + r * 64u;
            swB[bt]  = (r >> 1) & 3u;
        }
#pragma unroll
        for (int ks = 0; ks < 2; ks++) {
            const uint32_t ch = (uint32_t)(ks * 2 + (l >> 4));
            uint32_t aH[2][4], bH[2][4], tmp[2][4];
            uint32_t ra[2], rb[2];
#pragma unroll
            for (int mt = 0; mt < 2; mt++) {
                ra[mt] = rowA[mt] + ((ch ^ swA[mt]) * 16u);
                LDSM4(aH[mt], ra[mt]);
            }
#pragma unroll
            for (int bt = 0; bt < 2; bt++) {
                rb[bt] = rowB[bt] + ((ch ^ swB[bt]) * 16u);
                LDSM4(bH[bt], rb[bt]);
            }
#pragma unroll
            for (int mt = 0; mt < 2; mt++)
#pragma unroll
                for (int nt = 0; nt < 4; nt++) {
                    const int bt = nt >> 1, hi = nt & 1;
                    MMA16816(acc[mt][nt], aH[mt], bH[bt][hi], bH[bt][hi + 2]);
                }
#pragma unroll
            for (int mt = 0; mt < 2; mt++) LDSM4(tmp[mt], ra[mt] + 4096u);
#pragma unroll
            for (int mt = 0; mt < 2; mt++)
#pragma unroll
                for (int nt = 0; nt < 4; nt++) {
                    const int bt = nt >> 1, hi = nt & 1;
                    MMA16816(acc[mt][nt], tmp[mt], bH[bt][hi], bH[bt][hi + 2]);
                }
#pragma unroll
            for (int bt = 0; bt < 2; bt++) LDSM4(tmp[bt], rb[bt] + 8192u);
#pragma unroll
            for (int mt = 0; mt < 2; mt++)
#pragma unroll
                for (int nt = 0; nt < 4; nt++) {
                    const int bt = nt >> 1, hi = nt & 1;
                    MMA16816(acc[mt][nt], aH[mt], tmp[bt][hi], tmp[bt][hi + 2]);
                }
        }
    };

    const int nk = K / 32;
    load_chunk(0, 0);
    if (nk > 1) load_chunk(1, 1);
    for (int i = 0; i < nk; i++) {
        if (i + 1 < nk) asm volatile("cp.async.wait_group 1;" ::: "memory");
        else            asm volatile("cp.async.wait_group 0;" ::: "memory");
        __syncthreads();
        if (i + 2 < nk) load_chunk(i + 2, (i + 2) % 3);
        compute(i % 3);
    }

    const int r0f = l >> 2, c0f = (l & 3) * 2;
#pragma unroll
    for (int mt = 0; mt < 2; mt++) {
        const int gr = m0 + wm * 32 + mt * 16 + r0f;
#pragma unroll
        for (int nt = 0; nt < 4; nt++) {
            const int gc = n0 + wn * 32 + nt * 8 + c0f;
            float a0 = acc[mt][nt][0], a1 = acc[mt][nt][1];
            float a2 = acc[mt][nt][2], a3 = acc[mt][nt][3];
            if (EPI == 0) {
                float bx = bget(bias0, bias1, bias2, gc);
                float by = bget(bias0, bias1, bias2, gc + 1);
                float2 u0; u0.x = a0 + bx; u0.y = a1 + by;
                float2 u1; u1.x = a2 + bx; u1.y = a3 + by;
                *(float2*)(C + coff + (long long)gr * ldc + gc) = u0;
                *(float2*)(C + coff + (long long)(gr + 8) * ldc + gc) = u1;
            } else if (EPI == 1) {
                float bx = bias0[gc], by = bias0[gc + 1];
                float v0 = gelu_t(a0 + bx), v1 = gelu_t(a1 + by);
                float v2 = gelu_t(a2 + bx), v3 = gelu_t(a3 + by);
                bf16 h0, l0, h1, l1;
                split2(v0, h0, l0); split2(v1, h1, l1);
                *(__nv_bfloat162*)(Ch + coff + (long long)gr * ldc + gc) = mkbf2(h0, h1);
                *(__nv_bfloat162*)(Cl + coff + (long long)gr * ldc + gc) = mkbf2(l0, l1);
                split2(v2, h0, l0); split2(v3, h1, l1);
                *(__nv_bfloat162*)(Ch + coff + (long long)(gr + 8) * ldc + gc) = mkbf2(h0, h1);
                *(__nv_bfloat162*)(Cl + coff + (long long)(gr + 8) * ldc + gc) = mkbf2(l0, l1);
            } else if (EPI == 3) {
                bf16 h0, l0, h1, l1;
                split2(a0, h0, l0); split2(a1, h1, l1);
                *(__nv_bfloat162*)(Ch + coff + (long long)gr * ldc + gc) = mkbf2(h0, h1);
                *(__nv_bfloat162*)(Cl + coff + (long long)gr * ldc + gc) = mkbf2(l0, l1);
                split2(a2, h0, l0); split2(a3, h1, l1);
                *(__nv_bfloat162*)(Ch + coff + (long long)(gr + 8) * ldc + gc) = mkbf2(h0, h1);
                *(__nv_bfloat162*)(Cl + coff + (long long)(gr + 8) * ldc + gc) = mkbf2(l0, l1);
            } else {
                float bx = bias0[gc], by = bias0[gc + 1];
#pragma unroll
                for (int hh = 0; hh < 2; hh++) {
                    const int row = gr + hh * 8;
                    float va = (hh ? a2 : a0) + bx;
                    float vb = (hh ? a3 : a1) + by;
                    if (gateRow >= 0) {
                        const int b = row / Ss;   // per-batch launch: always 0
                        const float* gp = em + ((long long)b * 6 + gateRow) * Dd;
                        va *= gp[gc]; vb *= gp[gc + 1];
                    }
                    float2 o = *(float2*)(C + coff + (long long)row * ldc + gc);
                    o.x += va; o.y += vb;
                    *(float2*)(C + coff + (long long)row * ldc + gc) = o;
                }
            }
        }
    }
}

// ---------------------------------------------------------------------------
// Elementwise kernels (unchanged math; pointers arrive pre-offset per batch)
// ---------------------------------------------------------------------------
__global__ void k_copy(const float* __restrict__ a, float* __restrict__ o, long long n) {
    long long i = (long long)blockIdx.x * 256 + threadIdx.x;
    if (i < n) o[i] = a[i];
}
__global__ void k_emadd(const float* __restrict__ e, const float* __restrict__ mod,
                        float* __restrict__ em) {
    int i = blockIdx.x * 256 + threadIdx.x;
    if (i < Bb * 6 * Dd) em[i] = e[i] + mod[i % (6 * Dd)];
}
__global__ void k_split4(const float* __restrict__ in, bf16* __restrict__ oh,
                         bf16* __restrict__ ol, long long n) {
    long long i = ((long long)blockIdx.x * 256 + threadIdx.x) * 4;
    if (i >= n) return;
    float4 v = *(const float4*)(in + i);
    bf16 h0, l0, h1, l1;
    split2(v.x, h0, l0); split2(v.y, h1, l1);
    *(__nv_bfloat162*)(oh + i) = mkbf2(h0, h1);
    *(__nv_bfloat162*)(ol + i) = mkbf2(l0, l1);
    split2(v.z, h0, l0); split2(v.w, h1, l1);
    *(__nv_bfloat162*)(oh + i + 2) = mkbf2(h0, h1);
    *(__nv_bfloat162*)(ol + i + 2) = mkbf2(l0, l1);
}
__global__ void k_tsplit(const float* __restrict__ W, bf16* __restrict__ Th,
                         bf16* __restrict__ Tl, int Kd, int Nd) {
    __shared__ float t[32][33];
    int n0 = blockIdx.x * 32, k0 = blockIdx.y * 32;
    int tx = threadIdx.x;
    for (int j = threadIdx.y; j < 32; j += 8)
        t[j][tx] = W[(long long)(k0 + j) * Nd + n0 + tx];
    __syncthreads();
    for (int j = threadIdx.y; j < 16; j += 8) {
        int n  = j * 2 + (tx >> 4);
        int kk = (tx & 15) * 2;
        float v0 = t[kk][n], v1 = t[kk + 1][n];
        long long o = (long long)(n0 + n) * Kd + k0 + kk;
        bf16 h0, l0, h1, l1;
        split2(v0, h0, l0); split2(v1, h1, l1);
        *(__nv_bfloat162*)(Th + o) = mkbf2(h0, h1);
        *(__nv_bfloat162*)(Tl + o) = mkbf2(l0, l1);
    }
}
__global__ void k_tsplit3(const float* __restrict__ w0, const float* __restrict__ w1,
                          const float* __restrict__ w2,
                          bf16* __restrict__ Th, bf16* __restrict__ Tl) {
    __shared__ float t[32][33];
    const float* W = (blockIdx.z == 0) ? w0 : ((blockIdx.z == 1) ? w1 : w2);
    size_t zoff = (size_t)blockIdx.z * Dd * Dd;
    int n0 = blockIdx.x * 32, k0 = blockIdx.y * 32;
    int tx = threadIdx.x;
    for (int j = threadIdx.y; j < 32; j += 8)
        t[j][tx] = W[(long long)(k0 + j) * Dd + n0 + tx];
    __syncthreads();
    for (int j = threadIdx.y; j < 16; j += 8) {
        int n  = j * 2 + (tx >> 4);
        int kk = (tx & 15) * 2;
        float v0 = t[kk][n], v1 = t[kk + 1][n];
        long long o = (long long)zoff + (long long)(n0 + n) * Dd + k0 + kk;
        bf16 h0, l0, h1, l1;
        split2(v0, h0, l0); split2(v1, h1, l1);
        *(__nv_bfloat162*)(Th + o) = mkbf2(h0, h1);
        *(__nv_bfloat162*)(Tl + o) = mkbf2(l0, l1);
    }
}
__global__ void k_ln_mod_split(const float* __restrict__ x, const float* __restrict__ em,
                               bf16* __restrict__ oh, bf16* __restrict__ ol,
                               int scaleRow, int shiftRow) {
    int row = blockIdx.x, b = row / Ss, t = threadIdx.x;   // per-batch: b=0
    const float* xr = x + (long long)row * Dd;
    const float* es = em + ((long long)b * 6 + scaleRow) * Dd;
    const float* eh = em + ((long long)b * 6 + shiftRow) * Dd;
    float v[8];
    float4 a0 = *(const float4*)(xr + t * 8);
    float4 a1 = *(const float4*)(xr + t * 8 + 4);
    v[0]=a0.x; v[1]=a0.y; v[2]=a0.z; v[3]=a0.w; v[4]=a1.x; v[5]=a1.y; v[6]=a1.z; v[7]=a1.w;
    float s = 0.f, s2 = 0.f;
#pragma unroll
    for (int i = 0; i < 8; i++) { s += v[i]; s2 += v[i] * v[i]; }
    __shared__ float sh[512];
    sh[t] = s; sh[256 + t] = s2;
    __syncthreads();
    for (int o = 128; o > 0; o >>= 1) {
        if (t < o) { sh[t] += sh[t + o]; sh[256 + t] += sh[256 + t + o]; }
        __syncthreads();
    }
    float m = sh[0] * (1.f / Dd);
    float var = sh[256] * (1.f / Dd) - m * m;
    float r = rsqrtf(var + EPSf);
    bf16 hh[8], ll[8];
#pragma unroll
    for (int i = 0; i < 8; i++) {
        int dI = t * 8 + i;
        float u = (v[i] - m) * r * (1.f + es[dI]) + eh[dI];
        split2(u, hh[i], ll[i]);
    }
    long long ob = (long long)row * Dd + t * 8;
#pragma unroll
    for (int i = 0; i < 8; i += 2) {
        *(__nv_bfloat162*)(oh + ob + i) = mkbf2(hh[i], hh[i + 1]);
        *(__nv_bfloat162*)(ol + ob + i) = mkbf2(ll[i], ll[i + 1]);
    }
}
__global__ void k_rms_rope_split(const float* __restrict__ in, int ldin, int off,
                                 const float* __restrict__ w, const float* __restrict__ freqs,
                                 bf16* __restrict__ oh, bf16* __restrict__ ol, int Sv) {
    int row = blockIdx.x, b = row / Sv, s = row % Sv, t = threadIdx.x;  // per-batch: b=0
    const float* xr = in + (long long)row * ldin + off;
    float v[8];
    float4 a0 = *(const float4*)(xr + t * 8);
    float4 a1 = *(const float4*)(xr + t * 8 + 4);
    v[0]=a0.x; v[1]=a0.y; v[2]=a0.z; v[3]=a0.w; v[4]=a1.x; v[5]=a1.y; v[6]=a1.z; v[7]=a1.w;
    float s2 = 0.f;
#pragma unroll
    for (int i = 0; i < 8; i++) s2 += v[i] * v[i];
    __shared__ float sh[256];
    sh[t] = s2;
    __syncthreads();
    for (int o = 128; o > 0; o >>= 1) {
        if (t < o) sh[t] += sh[t + o];
        __syncthreads();
    }
    float r = rsqrtf(sh[0] * (1.f / Dd) + EPSf);
    int dbase = t * 8, h = dbase >> 7, dd = dbase & 127;
    float u[8];
#pragma unroll
    for (int i = 0; i < 8; i++) u[i] = v[i] * r * w[dbase + i];
    if (freqs) {
#pragma unroll
        for (int pr = 0; pr < 4; pr++) {
            float sn, cs;
            __sincosf(freqs[s * 64 + (dd >> 1) + pr], &sn, &cs);
            float xr_ = u[2 * pr], xi = u[2 * pr + 1];
            u[2 * pr]     = xr_ * cs - xi * sn;
            u[2 * pr + 1] = xr_ * sn + xi * cs;
        }
    }
    long long ob = ((long long)(b * Hh + h) * Sv + s) * 128 + dd;
    bf16 hh[8], ll[8];
#pragma unroll
    for (int i = 0; i < 8; i++) split2(u[i], hh[i], ll[i]);
#pragma unroll
    for (int i = 0; i < 8; i += 2) {
        *(__nv_bfloat162*)(oh + ob + i) = mkbf2(hh[i], hh[i + 1]);
        *(__nv_bfloat162*)(ol + ob + i) = mkbf2(ll[i], ll[i + 1]);
    }
}
__global__ void k_vt_split(const float* __restrict__ in, int ldin, int off,
                           bf16* __restrict__ oh, bf16* __restrict__ ol, int Sv) {
    __shared__ float t[32][33];
    int bh = blockIdx.z, b = bh >> 4, h = bh & 15;   // per-batch z-dim 16: b=0
    int s0 = blockIdx.x * 32, d0 = blockIdx.y * 32;
    int tx = threadIdx.x;
    for (int j = threadIdx.y; j < 32; j += 8)
        t[j][tx] = in[(long long)(b * Sv + s0 + j) * ldin + off + h * 128 + d0 + tx];
    __syncthreads();
    for (int j = threadIdx.y; j < 16; j += 8) {
        int d  = j * 2 + (tx >> 4);
        int ss = (tx & 15) * 2;
        float v0 = t[ss][d], v1 = t[ss + 1][d];
        long long o = (long long)(bh * 128 + d0 + d) * Sv + s0 + ss;
        bf16 h0, l0, h1, l1;
        split2(v0, h0, l0); split2(v1, h1, l1);
        *(__nv_bfloat162*)(oh + o) = mkbf2(h0, h1);
        *(__nv_bfloat162*)(ol + o) = mkbf2(l0, l1);
    }
}
__global__ void k_softmax_split(const float* __restrict__ S, bf16* __restrict__ oh,
                                bf16* __restrict__ ol, int ncols, float scale) {
    long long row = blockIdx.x;
    const float* p = S + row * ncols;
    bf16* Hp = oh + row * ncols;
    bf16* Lp = ol + row * ncols;
    int t = threadIdx.x;
    int np = ncols >> 9;
    float2 vv[4];
    float lm = -3.4e38f;
    for (int k = 0; k < np; k++) {
        vv[k] = *(const float2*)(p + (k << 9) + 2 * t);
        lm = fmaxf(lm, fmaxf(vv[k].x, vv[k].y));
    }
    __shared__ float sh[256];
    sh[t] = lm; __syncthreads();
    for (int o = 128; o > 0; o >>= 1) { if (t < o) sh[t] = fmaxf(sh[t], sh[t + o]); __syncthreads(); }
    float m = sh[0] * scale;
    __syncthreads();
    float ls = 0.f;
    for (int k = 0; k < np; k++) {
        float e0 = __expf(vv[k].x * scale - m);
        float e1 = __expf(vv[k].y * scale - m);
        vv[k].x = e0; vv[k].y = e1; ls += e0 + e1;
    }
    sh[t] = ls; __syncthreads();
    for (int o = 128; o > 0; o >>= 1) { if (t < o) sh[t] += sh[t + o]; __syncthreads(); }
    float inv = 1.f / sh[0];
    for (int k = 0; k < np; k++) {
        bf16 h0, l0, h1, l1;
        split2(vv[k].x * inv, h0, l0);
        split2(vv[k].y * inv, h1, l1);
        *(__nv_bfloat162*)(Hp + (k << 9) + 2 * t) = mkbf2(h0, h1);
        *(__nv_bfloat162*)(Lp + (k << 9) + 2 * t) = mkbf2(l0, l1);
    }
}

// ---------------------------------------------------------------------------
// Host orchestration — two per-batch streams forked/joined with events
// ---------------------------------------------------------------------------
static void gemm(cudaStream_t st, int epi,
                 const bf16* Ah, const bf16* Al, const bf16* Bh, const bf16* Bl,
                 int M, int N, int K, int lda, int ldb,
                 float* C, bf16* Ch, bf16* Cl, int ldc,
                 const float* b0, const float* b1, const float* b2,
                 const float* em, int gateRow,
                 int batch, int Hdiv,
                 long long sAh, long long sBh, long long sCh)
{
    dim3 g(N / 128, M / 64, batch), bl(256);
    size_t sm = SMEM_TOTAL_G;
    if (epi == 0)
        mma_gemm<0><<<g, bl, sm, st>>>(Ah, Al, Bh, Bl, K, lda, ldb, C, Ch, Cl, ldc,
                                       b0, b1, b2, em, gateRow, Hdiv, 0, sAh, 0, sBh, 0, sCh);
    else if (epi == 1)
        mma_gemm<1><<<g, bl, sm, st>>>(Ah, Al, Bh, Bl, K, lda, ldb, C, Ch, Cl, ldc,
                                       b0, b1, b2, em, gateRow, Hdiv, 0, sAh, 0, sBh, 0, sCh);
    else if (epi == 3)
        mma_gemm<3><<<g, bl, sm, st>>>(Ah, Al, Bh, Bl, K, lda, ldb, C, Ch, Cl, ldc,
                                       b0, b1, b2, em, gateRow, Hdiv, 0, sAh, 0, sBh, 0, sCh);
    else
        mma_gemm<2><<<g, bl, sm, st>>>(Ah, Al, Bh, Bl, K, lda, ldb, C, Ch, Cl, ldc,
                                       b0, b1, b2, em, gateRow, Hdiv, 0, sAh, 0, sBh, 0, sCh);
}

#define SYM(p, s) cudaGetSymbolAddress((void**)&p, s)

extern "C" void kernel_launch(void* const* d_in, const int* in_sizes, int n_in,
                              void* d_out, int out_size)
{
    bool sig = (in_sizes[13] == Dd);
    int I_snq, I_snk, I_cq_w, I_cq_b, I_ck_w, I_ck_b, I_cv_w, I_cv_b;
    int I_co_w, I_co_b, I_cnq, I_cnk, I_f1_w, I_f1_b, I_f2_w, I_f2_b;
    if (sig) {
        I_snq=13; I_snk=14; I_cq_w=15; I_cq_b=16; I_ck_w=17; I_ck_b=18;
        I_cv_w=19; I_cv_b=20; I_co_w=21; I_co_b=22; I_cnq=23; I_cnk=24;
        I_f1_w=25; I_f1_b=26; I_f2_w=27; I_f2_b=28;
    } else {
        I_cq_w=13; I_cq_b=14; I_ck_w=15; I_ck_b=16; I_cv_w=17; I_cv_b=18;
        I_co_w=19; I_co_b=20; I_f1_w=21; I_f1_b=22; I_f2_w=23; I_f2_b=24;
        I_snq=25; I_snk=26; I_cnq=27; I_cnk=28;
    }
    const float* x    = (const float*)d_in[0];
    const float* e    = (const float*)d_in[1];
    const float* ctx  = (const float*)d_in[2];
    const float* fr   = (const float*)d_in[3];
    const float* mod  = (const float*)d_in[4];
    const float* sq_w = (const float*)d_in[5];  const float* sq_b = (const float*)d_in[6];
    const float* sk_w = (const float*)d_in[7];  const float* sk_b = (const float*)d_in[8];
    const float* sv_w = (const float*)d_in[9];  const float* sv_b = (const float*)d_in[10];
    const float* so_w = (const float*)d_in[11]; const float* so_b = (const float*)d_in[12];
    const float* snq  = (const float*)d_in[I_snq];  const float* snk  = (const float*)d_in[I_snk];
    const float* cq_w = (const float*)d_in[I_cq_w]; const float* cq_b = (const float*)d_in[I_cq_b];
    const float* ck_w = (const float*)d_in[I_ck_w]; const float* ck_b = (const float*)d_in[I_ck_b];
    const float* cv_w = (const float*)d_in[I_cv_w]; const float* cv_b = (const float*)d_in[I_cv_b];
    const float* co_w = (const float*)d_in[I_co_w]; const float* co_b = (const float*)d_in[I_co_b];
    const float* cnq  = (const float*)d_in[I_cnq];  const float* cnk  = (const float*)d_in[I_cnk];
    const float* f1_w = (const float*)d_in[I_f1_w]; const float* f1_b = (const float*)d_in[I_f1_b];
    const float* f2_w = (const float*)d_in[I_f2_w]; const float* f2_b = (const float*)d_in[I_f2_b];

    cudaFuncSetAttribute(mma_gemm<0>, cudaFuncAttributeMaxDynamicSharedMemorySize, SMEM_TOTAL_G);
    cudaFuncSetAttribute(mma_gemm<1>, cudaFuncAttributeMaxDynamicSharedMemorySize, SMEM_TOTAL_G);
    cudaFuncSetAttribute(mma_gemm<2>, cudaFuncAttributeMaxDynamicSharedMemorySize, SMEM_TOTAL_G);
    cudaFuncSetAttribute(mma_gemm<3>, cudaFuncAttributeMaxDynamicSharedMemorySize, SMEM_TOTAL_G);

    // streams/events: created once on the FIRST (uncaptured) call; reused under capture
    static cudaStream_t stm[2] = {nullptr, nullptr};
    static cudaEvent_t evF = nullptr, evJ0 = nullptr, evJ1 = nullptr;
    if (stm[0] == nullptr) {
        cudaStreamCreateWithFlags(&stm[0], cudaStreamNonBlocking);
        cudaStreamCreateWithFlags(&stm[1], cudaStreamNonBlocking);
        cudaEventCreateWithFlags(&evF,  cudaEventDisableTiming);
        cudaEventCreateWithFlags(&evJ0, cudaEventDisableTiming);
        cudaEventCreateWithFlags(&evJ1, cudaEventDisableTiming);
    }

    float *em_, *qkv, *sc, *scc;
    SYM(em_, g_em); SYM(qkv, g_qkv); SYM(sc, g_sc); SYM(scc, g_scc);
    bf16 *txh, *txl, *cxh, *cxl, *qh, *ql, *kh, *kl, *vth, *vtl;
    bf16 *ckh, *ckl, *cvth, *cvtl, *ph_, *pl_, *pch, *pcl, *fh, *fl;
    SYM(txh, g_txh); SYM(txl, g_txl); SYM(cxh, g_cxh); SYM(cxl, g_cxl);
    SYM(qh, g_qh); SYM(ql, g_ql); SYM(kh, g_kh); SYM(kl, g_kl);
    SYM(vth, g_vth); SYM(vtl, g_vtl);
    SYM(ckh, g_ckh); SYM(ckl, g_ckl); SYM(cvth, g_cvth); SYM(cvtl, g_cvtl);
    SYM(ph_, g_ph); SYM(pl_, g_pl); SYM(pch, g_pch); SYM(pcl, g_pcl);
    SYM(fh, g_fh); SYM(fl, g_fl);
    bf16 *wqkvh, *wqkvl, *wckvh, *wckvl, *woh, *wol, *wcqh, *wcql, *wcoh, *wcol, *wf1h, *wf1l, *wf2h, *wf2l;
    SYM(wqkvh, g_wqkvh); SYM(wqkvl, g_wqkvl); SYM(wckvh, g_wckvh); SYM(wckvl, g_wckvl);
    SYM(woh, g_woh); SYM(wol, g_wol); SYM(wcqh, g_wcqh); SYM(wcql, g_wcql);
    SYM(wcoh, g_wcoh); SYM(wcol, g_wcol); SYM(wf1h, g_wf1h); SYM(wf1l, g_wf1l);
    SYM(wf2h, g_wf2h); SYM(wf2l, g_wf2l);

    float* xo = (float*)d_out;
    const long long DD  = (long long)Dd * Dd;
    const long long SD  = (long long)Ss * Dd;
    const long long SS2 = (long long)Ss * Ss;
    const long long SL  = (long long)Ss * LCc;
    const long long LD  = (long long)LCc * Dd;
    const float SCALE = 0.08838834764831845f;
    dim3 tb(32, 8);

    // ---------------- prep (shared weights) on root stream ----------------
    k_emadd<<<(Bb * 6 * Dd + 255) / 256, 256>>>(e, mod, em_);
    k_tsplit3<<<dim3(Dd/32, Dd/32, 3), tb>>>(sq_w, sk_w, sv_w, wqkvh, wqkvl);
    k_tsplit<<<dim3(Dd/32, Dd/32), tb>>>(so_w, woh,  wol,  Dd, Dd);
    k_tsplit<<<dim3(Dd/32, Dd/32), tb>>>(cq_w, wcqh, wcql, Dd, Dd);
    k_tsplit<<<dim3(Dd/32, Dd/32), tb>>>(ck_w, wckvh,      wckvl,      Dd, Dd);
    k_tsplit<<<dim3(Dd/32, Dd/32), tb>>>(cv_w, wckvh + DD, wckvl + DD, Dd, Dd);
    k_tsplit<<<dim3(Dd/32, Dd/32), tb>>>(co_w, wcoh, wcol, Dd, Dd);
    k_tsplit<<<dim3(Ff/32, Dd/32), tb>>>(f1_w, wf1h, wf1l, Dd, Ff);
    k_tsplit<<<dim3(Dd/32, Ff/32), tb>>>(f2_w, wf2h, wf2l, Ff, Dd);
    cudaEventRecord(evF, 0);

    // ---------------- per-batch chains on two streams ----------------
    for (int b = 0; b < Bb; b++) {
        cudaStream_t st = stm[b];
        cudaStreamWaitEvent(st, evF, 0);

        const float* xb  = x   + (long long)b * SD;
        float*       xob = xo  + (long long)b * SD;
        const float* emb = em_ + (long long)b * 6 * Dd;
        float* qkvb = qkv + (long long)b * Ss * 3 * Dd;
        bf16 *txhb = txh + b*SD,  *txlb = txl + b*SD;
        bf16 *qhb  = qh  + b*SD,  *qlb  = ql  + b*SD;
        bf16 *khb  = kh  + b*SD,  *klb  = kl  + b*SD;
        bf16 *vthb = vth + b*SD,  *vtlb = vtl + b*SD;
        bf16 *ckhb = ckh + b*LD,  *cklb = ckl + b*LD;
        bf16 *cvthb= cvth+ b*LD,  *cvtlb= cvtl+ b*LD;
        bf16 *cxhb = cxh + b*LD,  *cxlb = cxl + b*LD;
        float* scb  = sc  + (long long)b * Hh * SS2;
        float* sccb = scc + (long long)b * Hh * SL;
        bf16 *phb = ph_ + (long long)b*Hh*SS2, *plb = pl_ + (long long)b*Hh*SS2;
        bf16 *pchb= pch + (long long)b*Hh*SL,  *pclb= pcl + (long long)b*Hh*SL;
        bf16 *fhb = fh + (long long)b*Ss*Ff,   *flb = fl + (long long)b*Ss*Ff;
        const float* ctxb = ctx + (long long)b * LD;

        // self attention
        k_copy<<<(int)((SD + 255) / 256), 256, 0, st>>>(xb, xob, SD);
        k_ln_mod_split<<<Ss, 256, 0, st>>>(xb, emb, txhb, txlb, 1, 0);
        gemm(st, 0, txhb, txlb, wqkvh, wqkvl, Ss, 3*Dd, Dd, Dd, Dd,
             qkvb, nullptr, nullptr, 3*Dd, sq_b, sk_b, sv_b, nullptr, -1, 1, 1, 0, 0, 0);
        k_rms_rope_split<<<Ss, 256, 0, st>>>(qkvb, 3*Dd, 0,  snq, fr, qhb, qlb, Ss);
        k_rms_rope_split<<<Ss, 256, 0, st>>>(qkvb, 3*Dd, Dd, snk, fr, khb, klb, Ss);
        k_vt_split<<<dim3(Ss/32, 4, Hh), tb, 0, st>>>(qkvb, 3*Dd, 2*Dd, vthb, vtlb, Ss);
        gemm(st, 0, qhb, qlb, khb, klb, Ss, Ss, HDd, HDd, HDd,
             scb, nullptr, nullptr, Ss, nullptr, nullptr, nullptr, nullptr, -1, Hh, Hh,
             (long long)Ss*HDd, (long long)Ss*HDd, SS2);
        k_softmax_split<<<Hh * Ss, 256, 0, st>>>(scb, phb, plb, Ss, SCALE);
        gemm(st, 3, phb, plb, vthb, vtlb, Ss, HDd, Ss, Ss, Ss,
             nullptr, txhb, txlb, Dd, nullptr, nullptr, nullptr, nullptr, -1, Hh, Hh,
             SS2, (long long)HDd*Ss, HDd);
        gemm(st, 2, txhb, txlb, woh, wol, Ss, Dd, Dd, Dd, Dd,
             xob, nullptr, nullptr, Dd, so_b, nullptr, nullptr, emb, 2, 1, 1, 0, 0, 0);

        // cross attention
        k_split4<<<(int)(SD / 1024), 256, 0, st>>>(xob, txhb, txlb, SD);
        gemm(st, 0, txhb, txlb, wcqh, wcql, Ss, Dd, Dd, Dd, Dd,
             qkvb, nullptr, nullptr, Dd, cq_b, nullptr, nullptr, nullptr, -1, 1, 1, 0, 0, 0);
        k_rms_rope_split<<<Ss, 256, 0, st>>>(qkvb, Dd, 0, cnq, nullptr, qhb, qlb, Ss);
        k_split4<<<(int)(LD / 1024), 256, 0, st>>>(ctxb, cxhb, cxlb, LD);
        gemm(st, 0, cxhb, cxlb, wckvh, wckvl, LCc, 2*Dd, Dd, Dd, Dd,
             qkvb, nullptr, nullptr, 2*Dd, ck_b, cv_b, nullptr, nullptr, -1, 1, 1, 0, 0, 0);
        k_rms_rope_split<<<LCc, 256, 0, st>>>(qkvb, 2*Dd, 0, cnk, nullptr, ckhb, cklb, LCc);
        k_vt_split<<<dim3(LCc/32, 4, Hh), tb, 0, st>>>(qkvb, 2*Dd, Dd, cvthb, cvtlb, LCc);
        gemm(st, 0, qhb, qlb, ckhb, cklb, Ss, LCc, HDd, HDd, HDd,
             sccb, nullptr, nullptr, LCc, nullptr, nullptr, nullptr, nullptr, -1, Hh, Hh,
             (long long)Ss*HDd, (long long)LCc*HDd, SL);
        k_softmax_split<<<Hh * Ss, 256, 0, st>>>(sccb, pchb, pclb, LCc, SCALE);
        gemm(st, 3, pchb, pclb, cvthb, cvtlb, Ss, HDd, LCc, LCc, LCc,
             nullptr, txhb, txlb, Dd, nullptr, nullptr, nullptr, nullptr, -1, Hh, Hh,
             SL, (long long)HDd*LCc, HDd);
        gemm(st, 2, txhb, txlb, wcoh, wcol, Ss, Dd, Dd, Dd, Dd,
             xob, nullptr, nullptr, Dd, co_b, nullptr, nullptr, emb, -1, 1, 1, 0, 0, 0);

        // FFN
        k_ln_mod_split<<<Ss, 256, 0, st>>>(xob, emb, txhb, txlb, 4, 3);
        gemm(st, 1, txhb, txlb, wf1h, wf1l, Ss, Ff, Dd, Dd, Dd,
             nullptr, fhb, flb, Ff, f1_b, nullptr, nullptr, nullptr, -1, 1, 1, 0, 0, 0);
        gemm(st, 2, fhb, flb, wf2h, wf2l, Ss, Dd, Ff, Ff, Ff,
             xob, nullptr, nullptr, Dd, f2_b, nullptr, nullptr, emb, 5, 1, 1, 0, 0, 0);

        cudaEventRecord(b == 0 ? evJ0 : evJ1, st);
    }

    // join back to root stream
    cudaStreamWaitEvent(0, evJ0, 0);
    cudaStreamWaitEvent(0, evJ1, 0);
}

// round 17
// speedup vs baseline: 2.3971x; 1.1191x over previous
#include <cuda_runtime.h>
#include <cuda_bf16.h>
#include <cstdint>

using bf16 = __nv_bfloat16;

#define Bb  2
#define Ss  2048
#define Dd  2048
#define Hh  16
#define HDd 128
#define Ff  8192
#define LCc 512
#define EPSf 1e-6f

// ---------------------------------------------------------------------------
// Scratch (__device__ globals; allocation-free rule)
// ---------------------------------------------------------------------------
__device__ float g_em [Bb * 6 * Dd];
__device__ float g_qkv [(size_t)Bb * Ss * 3 * Dd];

#define DECL2(nm, n) __device__ __align__(128) bf16 nm##h[(size_t)(n)]; __device__ __align__(128) bf16 nm##l[(size_t)(n)];
DECL2(g_tx, (size_t)Bb*Ss*Dd)
DECL2(g_cx, (size_t)Bb*LCc*Dd)
DECL2(g_q,  (size_t)Bb*Ss*Dd)
DECL2(g_k,  (size_t)Bb*Ss*Dd)
DECL2(g_vt, (size_t)Bb*Ss*Dd)
DECL2(g_ck, (size_t)Bb*LCc*Dd)
DECL2(g_cvt,(size_t)Bb*LCc*Dd)
DECL2(g_f,  (size_t)Bb*Ss*Ff)
DECL2(g_wqkv, (size_t)3*Dd*Dd)
DECL2(g_wckv, (size_t)2*Dd*Dd)
DECL2(g_wo,   (size_t)Dd*Dd)
DECL2(g_wcq,  (size_t)Dd*Dd)
DECL2(g_wco,  (size_t)Dd*Dd)
DECL2(g_wf1,  (size_t)Ff*Dd)
DECL2(g_wf2,  (size_t)Dd*Ff)

// ---------------------------------------------------------------------------
// helpers
// ---------------------------------------------------------------------------
__device__ __forceinline__ uint32_t smem_u32(const void* p) {
    uint32_t a;
    asm("{ .reg .u64 t; cvta.to.shared.u64 t, %1; cvt.u32.u64 %0, t; }" : "=r"(a) : "l"(p));
    return a;
}
#define CP_COMMIT() asm volatile("cp.async.commit_group;" ::: "memory")

#define LDSM4(d, a) \
  asm volatile("ldmatrix.sync.aligned.m8n8.x4.shared.b16 {%0,%1,%2,%3}, [%4];" \
    : "=r"((d)[0]), "=r"((d)[1]), "=r"((d)[2]), "=r"((d)[3]) : "r"(a))

#define MMA16816(c, a, b0, b1) \
  asm volatile("mma.sync.aligned.m16n8k16.row.col.f32.bf16.bf16.f32 " \
    "{%0,%1,%2,%3}, {%4,%5,%6,%7}, {%8,%9}, {%0,%1,%2,%3};" \
    : "+f"((c)[0]), "+f"((c)[1]), "+f"((c)[2]), "+f"((c)[3]) \
    : "r"((a)[0]), "r"((a)[1]), "r"((a)[2]), "r"((a)[3]), "r"(b0), "r"(b1))

__device__ __forceinline__ float gelu_t(float x) {
    float x3 = x * x * x;
    return 0.5f * x * (1.f + tanhf(0.7978845608028654f * (x + 0.044715f * x3)));
}
__device__ __forceinline__ void split2(float v, bf16& h, bf16& l) {
    h = __float2bfloat16(v);
    l = __float2bfloat16(v - __bfloat162float(h));
}
__device__ __forceinline__ __nv_bfloat162 mkbf2(bf16 a, bf16 b) {
    __nv_bfloat162 r; r.x = a; r.y = b; return r;
}
__device__ __forceinline__ void packsplit(float a, float b, uint32_t& ph, uint32_t& pl) {
    bf16 ha, la, hb, lb;
    split2(a, ha, la); split2(b, hb, lb);
    __nv_bfloat162 th = mkbf2(ha, hb), tl = mkbf2(la, lb);
    ph = *(uint32_t*)&th; pl = *(uint32_t*)&tl;
}
__device__ __forceinline__ float bget(const float* b0, const float* b1,
                                      const float* b2, int c) {
    if (b1 == nullptr) return b0 ? b0[c] : 0.f;
    int seg = c >> 11, off = c & 2047;
    const float* bp = (seg == 0) ? b0 : ((seg == 1) ? b1 : b2);
    return bp[off];
}

// ---------------------------------------------------------------------------
// GEMM (R14-measured config) — UNCHANGED
// ---------------------------------------------------------------------------
#define STAGE_BYTES 24576u
#define SMEM_TOTAL_G (3 * 24576)

template <int EPI>
__global__ __launch_bounds__(256, 3)
void mma_gemm(const bf16* __restrict__ Ah, const bf16* __restrict__ Al,
              const bf16* __restrict__ Bh, const bf16* __restrict__ Bl,
              int K, int lda, int ldb,
              float* C, bf16* Ch, bf16* Cl, int ldc,
              const float* __restrict__ bias0, const float* __restrict__ bias1,
              const float* __restrict__ bias2,
              const float* __restrict__ em, int gateRow,
              int Hdiv,
              long long sAb, long long sAh_, long long sBb, long long sBh_,
              long long sCb, long long sCh_)
{
    extern __shared__ __align__(128) char smem[];
    const uint32_t sbase = smem_u32(smem);
    const int tid = threadIdx.x;
    const int w = tid >> 5, l = tid & 31;
    const int wm = w >> 2, wn = w & 3;

    const int z = blockIdx.z;
    const int zb = z / Hdiv, zh = z - zb * Hdiv;
    Ah += zb * sAb + zh * sAh_;  Al += zb * sAb + zh * sAh_;
    Bh += zb * sBb + zh * sBh_;  Bl += zb * sBb + zh * sBh_;
    const long long coff = zb * sCb + zh * sCh_;
    const int m0 = blockIdx.y * 64, n0 = blockIdx.x * 128;

    float acc[2][4][4];
#pragma unroll
    for (int i = 0; i < 2; i++)
#pragma unroll
        for (int j = 0; j < 4; j++)
#pragma unroll
            for (int r = 0; r < 4; r++) acc[i][j][r] = 0.f;

    auto load_chunk = [&](int kc, int stg) {
        const uint32_t sb = sbase + (uint32_t)stg * STAGE_BYTES;
        {
            int r = tid >> 2, c16 = tid & 3;
            uint32_t so = (uint32_t)(r * 64 + ((c16 ^ ((r >> 1) & 3)) * 16));
            const char* ga = (const char*)(Ah + (long long)(m0 + r) * lda + kc * 32) + c16 * 16;
            asm volatile("cp.async.cg.shared.global [%0], [%1], 16;" :: "r"(sb + so), "l"(ga));
            const char* gl = (const char*)(Al + (long long)(m0 + r) * lda + kc * 32) + c16 * 16;
            asm volatile("cp.async.cg.shared.global [%0], [%1], 16;" :: "r"(sb + 4096u + so), "l"(gl));
        }
        {
#pragma unroll
            for (int it = 0; it < 2; it++) {
                int c = tid + it * 256;
                int r = c >> 2, c16 = c & 3;
                uint32_t so = (uint32_t)(r * 64 + ((c16 ^ ((r >> 1) & 3)) * 16));
                const char* gh = (const char*)(Bh + (long long)(n0 + r) * ldb + kc * 32) + c16 * 16;
                asm volatile("cp.async.cg.shared.global [%0], [%1], 16;" :: "r"(sb + 8192u + so), "l"(gh));
                const char* gl = (const char*)(Bl + (long long)(n0 + r) * ldb + kc * 32) + c16 * 16;
                asm volatile("cp.async.cg.shared.global [%0], [%1], 16;" :: "r"(sb + 16384u + so), "l"(gl));
            }
        }
        CP_COMMIT();
    };

    auto compute = [&](int stg) {
        const uint32_t sb = sbase + (uint32_t)stg * STAGE_BYTES;
        uint32_t rowA[2], swA[2], rowB[2], swB[2];
#pragma unroll
        for (int mt = 0; mt < 2; mt++) {
            uint32_t r = (uint32_t)(wm * 32 + mt * 16 + (l & 15));
            rowA[mt] = sb + r * 64u;
            swA[mt]  = (r >> 1) & 3u;
        }
#pragma unroll
        for (int bt = 0; bt < 2; bt++) {
            uint32_t r = (uint32_t)(wn * 32 + bt * 16 + (l & 15));
            rowB[bt] = sb + 8192u + r * 64u;
            swB[bt]  = (r >> 1) & 3u;
        }
#pragma unroll
        for (int ks = 0; ks < 2; ks++) {
            const uint32_t ch = (uint32_t)(ks * 2 + (l >> 4));
            uint32_t aH[2][4], bH[2][4], tmp[2][4];
            uint32_t ra[2], rb[2];
#pragma unroll
            for (int mt = 0; mt < 2; mt++) {
                ra[mt] = rowA[mt] + ((ch ^ swA[mt]) * 16u);
                LDSM4(aH[mt], ra[mt]);
            }
#pragma unroll
            for (int bt = 0; bt < 2; bt++) {
                rb[bt] = rowB[bt] + ((ch ^ swB[bt]) * 16u);
                LDSM4(bH[bt], rb[bt]);
            }
#pragma unroll
            for (int mt = 0; mt < 2; mt++)
#pragma unroll
                for (int nt = 0; nt < 4; nt++) {
                    const int bt = nt >> 1, hi = nt & 1;
                    MMA16816(acc[mt][nt], aH[mt], bH[bt][hi], bH[bt][hi + 2]);
                }
#pragma unroll
            for (int mt = 0; mt < 2; mt++) LDSM4(tmp[mt], ra[mt] + 4096u);
#pragma unroll
            for (int mt = 0; mt < 2; mt++)
#pragma unroll
                for (int nt = 0; nt < 4; nt++) {
                    const int bt = nt >> 1, hi = nt & 1;
                    MMA16816(acc[mt][nt], tmp[mt], bH[bt][hi], bH[bt][hi + 2]);
                }
#pragma unroll
            for (int bt = 0; bt < 2; bt++) LDSM4(tmp[bt], rb[bt] + 8192u);
#pragma unroll
            for (int mt = 0; mt < 2; mt++)
#pragma unroll
                for (int nt = 0; nt < 4; nt++) {
                    const int bt = nt >> 1, hi = nt & 1;
                    MMA16816(acc[mt][nt], aH[mt], tmp[bt][hi], tmp[bt][hi + 2]);
                }
        }
    };

    const int nk = K / 32;
    load_chunk(0, 0);
    if (nk > 1) load_chunk(1, 1);
    for (int i = 0; i < nk; i++) {
        if (i + 1 < nk) asm volatile("cp.async.wait_group 1;" ::: "memory");
        else            asm volatile("cp.async.wait_group 0;" ::: "memory");
        __syncthreads();
        if (i + 2 < nk) load_chunk(i + 2, (i + 2) % 3);
        compute(i % 3);
    }

    const int r0f = l >> 2, c0f = (l & 3) * 2;
#pragma unroll
    for (int mt = 0; mt < 2; mt++) {
        const int gr = m0 + wm * 32 + mt * 16 + r0f;
#pragma unroll
        for (int nt = 0; nt < 4; nt++) {
            const int gc = n0 + wn * 32 + nt * 8 + c0f;
            float a0 = acc[mt][nt][0], a1 = acc[mt][nt][1];
            float a2 = acc[mt][nt][2], a3 = acc[mt][nt][3];
            if (EPI == 0) {
                float bx = bget(bias0, bias1, bias2, gc);
                float by = bget(bias0, bias1, bias2, gc + 1);
                float2 u0; u0.x = a0 + bx; u0.y = a1 + by;
                float2 u1; u1.x = a2 + bx; u1.y = a3 + by;
                *(float2*)(C + coff + (long long)gr * ldc + gc) = u0;
                *(float2*)(C + coff + (long long)(gr + 8) * ldc + gc) = u1;
            } else if (EPI == 1) {
                float bx = bias0[gc], by = bias0[gc + 1];
                float v0 = gelu_t(a0 + bx), v1 = gelu_t(a1 + by);
                float v2 = gelu_t(a2 + bx), v3 = gelu_t(a3 + by);
                bf16 h0, l0, h1, l1;
                split2(v0, h0, l0); split2(v1, h1, l1);
                *(__nv_bfloat162*)(Ch + coff + (long long)gr * ldc + gc) = mkbf2(h0, h1);
                *(__nv_bfloat162*)(Cl + coff + (long long)gr * ldc + gc) = mkbf2(l0, l1);
                split2(v2, h0, l0); split2(v3, h1, l1);
                *(__nv_bfloat162*)(Ch + coff + (long long)(gr + 8) * ldc + gc) = mkbf2(h0, h1);
                *(__nv_bfloat162*)(Cl + coff + (long long)(gr + 8) * ldc + gc) = mkbf2(l0, l1);
            } else {
                float bx = bias0[gc], by = bias0[gc + 1];
#pragma unroll
                for (int hh = 0; hh < 2; hh++) {
                    const int row = gr + hh * 8;
                    float va = (hh ? a2 : a0) + bx;
                    float vb = (hh ? a3 : a1) + by;
                    if (gateRow >= 0) {
                        const float* gp = em + (long long)gateRow * Dd;
                        va *= gp[gc]; vb *= gp[gc + 1];
                    }
                    float2 o = *(float2*)(C + coff + (long long)row * ldc + gc);
                    o.x += va; o.y += vb;
                    *(float2*)(C + coff + (long long)row * ldc + gc) = o;
                }
            }
        }
    }
}

// ---------------------------------------------------------------------------
// Flash attention: per (q-tile 64, head). bf16x3 QK^T -> online softmax ->
// bf16x3 P*V. Inputs: q/k [h][s][128] hi/lo, v^T [h*128+d][s] hi/lo.
// Output: [s][Dd] hi/lo (col = h*128+d). 4 warps x 16 q-rows; Bc=32;
// 3-stage cp.async ring (R12 pattern), 2 CTAs/SM.
// ---------------------------------------------------------------------------
#define FA_STAGE 32768u
#define FA_SMEM  (3 * 32768)

__global__ __launch_bounds__(128, 2)
void flash_attn(const bf16* __restrict__ qh, const bf16* __restrict__ ql,
                const bf16* __restrict__ kh, const bf16* __restrict__ kl,
                const bf16* __restrict__ vth, const bf16* __restrict__ vtl,
                bf16* __restrict__ outh, bf16* __restrict__ outl,
                int Sq, int Sk)
{
    extern __shared__ __align__(128) char smem[];
    const uint32_t sbase = smem_u32(smem);
    const int tid = threadIdx.x;
    const int w = tid >> 5, l = tid & 31;
    const int h = blockIdx.y;
    const int q0 = blockIdx.x * 64;
    const float SCALE = 0.08838834764831845f;

    // ---- stage Q tile (64 x 128) and extract A fragments (held in regs) ----
    {
        const bf16* qs[2] = {qh, ql};
        for (int hf = 0; hf < 2; hf++) {
            const bf16* p = qs[hf] + ((long long)(h * Sq + q0)) * 128;
            uint32_t off = sbase + (uint32_t)hf * 16384u;
            for (int it = 0; it < 8; it++) {
                int seg = tid + it * 128;           // 0..1023
                int r = seg >> 4, c = seg & 15;
                uint32_t so = (uint32_t)(r * 256 + ((c ^ (r & 7)) * 16));
                asm volatile("cp.async.cg.shared.global [%0], [%1], 16;"
                             :: "r"(off + so), "l"((const char*)(p + (long long)r * 128) + c * 16));
            }
        }
        CP_COMMIT();
        asm volatile("cp.async.wait_group 0;" ::: "memory");
        __syncthreads();
    }
    uint32_t qfh[8][4], qfl[8][4];
    {
        int r = w * 16 + (l & 15);
        uint32_t rowoff = (uint32_t)(r * 256);
#pragma unroll
        for (int kk = 0; kk < 8; kk++) {
            uint32_t ch = (uint32_t)(2 * kk + (l >> 4));
            uint32_t a = sbase + rowoff + ((ch ^ (uint32_t)(r & 7)) * 16u);
            LDSM4(qfh[kk], a);
            LDSM4(qfl[kk], a + 16384u);
        }
    }
    __syncthreads();

    float o[16][4];
#pragma unroll
    for (int i = 0; i < 16; i++)
#pragma unroll
        for (int j = 0; j < 4; j++) o[i][j] = 0.f;
    float mrow0 = -3.4e38f, mrow1 = -3.4e38f;
    float lrow0 = 0.f, lrow1 = 0.f;

    // stage: Kh@0 Kl@8192 Vh@16384 Vl@24576
    auto load_kv = [&](int blk, int stg) {
        const uint32_t sb = sbase + (uint32_t)stg * FA_STAGE;
        int k0 = blk * 32;
        for (int it = 0; it < 4; it++) {            // K: 32 rows x 16 chunks
            int seg = tid + it * 128;
            int r = seg >> 4, c = seg & 15;
            uint32_t so = (uint32_t)(r * 256 + ((c ^ (r & 7)) * 16));
            const char* gh = (const char*)(kh + ((long long)(h * Sk + k0 + r)) * 128) + c * 16;
            asm volatile("cp.async.cg.shared.global [%0], [%1], 16;" :: "r"(sb + so), "l"(gh));
            const char* gl = (const char*)(kl + ((long long)(h * Sk + k0 + r)) * 128) + c * 16;
            asm volatile("cp.async.cg.shared.global [%0], [%1], 16;" :: "r"(sb + 8192u + so), "l"(gl));
        }
        for (int it = 0; it < 4; it++) {            // V^T: 128 rows x 4 chunks
            int seg = tid + it * 128;
            int r = seg >> 2, c = seg & 3;
            uint32_t so = (uint32_t)(r * 64 + ((c ^ ((r >> 1) & 3)) * 16));
            const char* gh = (const char*)(vth + ((long long)(h * 128 + r)) * Sk + k0) + c * 16;
            asm volatile("cp.async.cg.shared.global [%0], [%1], 16;" :: "r"(sb + 16384u + so), "l"(gh));
            const char* gl = (const char*)(vtl + ((long long)(h * 128 + r)) * Sk + k0) + c * 16;
            asm volatile("cp.async.cg.shared.global [%0], [%1], 16;" :: "r"(sb + 24576u + so), "l"(gl));
        }
        CP_COMMIT();
    };

    const int nb = Sk / 32;
    load_kv(0, 0);
    if (nb > 1) load_kv(1, 1);
    for (int i = 0; i < nb; i++) {
        if (i + 1 < nb) asm volatile("cp.async.wait_group 1;" ::: "memory");
        else            asm volatile("cp.async.wait_group 0;" ::: "memory");
        __syncthreads();
        if (i + 2 < nb) load_kv(i + 2, (i + 2) % 3);
        const uint32_t sb = sbase + (uint32_t)(i % 3) * FA_STAGE;

        // ---- S = Q K^T (warp: 16 x 32), 3-term ----
        float s[4][4];
#pragma unroll
        for (int t1 = 0; t1 < 4; t1++)
#pragma unroll
            for (int t2 = 0; t2 < 4; t2++) s[t1][t2] = 0.f;
#pragma unroll
        for (int kk = 0; kk < 8; kk++) {
            uint32_t bh_[2][4], bl_[2][4];
#pragma unroll
            for (int g = 0; g < 2; g++) {
                int r = g * 16 + (l & 15);
                uint32_t ch = (uint32_t)(2 * kk + (l >> 4));
                uint32_t a = sb + (uint32_t)(r * 256) + ((ch ^ (uint32_t)(r & 7)) * 16u);
                LDSM4(bh_[g], a);
                LDSM4(bl_[g], a + 8192u);
            }
#pragma unroll
            for (int nt = 0; nt < 4; nt++) {
                const int g = nt >> 1, hi = nt & 1;
                MMA16816(s[nt], qfh[kk], bh_[g][hi], bh_[g][hi + 2]);
                MMA16816(s[nt], qfl[kk], bh_[g][hi], bh_[g][hi + 2]);
                MMA16816(s[nt], qfh[kk], bl_[g][hi], bl_[g][hi + 2]);
            }
        }

        // ---- online softmax (rows l>>2 and +8; quad shuffles) ----
        float tm0 = -3.4e38f, tm1 = -3.4e38f;
#pragma unroll
        for (int nt = 0; nt < 4; nt++) {
#pragma unroll
            for (int j = 0; j < 4; j++) s[nt][j] *= SCALE;
            tm0 = fmaxf(tm0, fmaxf(s[nt][0], s[nt][1]));
            tm1 = fmaxf(tm1, fmaxf(s[nt][2], s[nt][3]));
        }
        tm0 = fmaxf(tm0, __shfl_xor_sync(0xffffffff, tm0, 1));
        tm0 = fmaxf(tm0, __shfl_xor_sync(0xffffffff, tm0, 2));
        tm1 = fmaxf(tm1, __shfl_xor_sync(0xffffffff, tm1, 1));
        tm1 = fmaxf(tm1, __shfl_xor_sync(0xffffffff, tm1, 2));
        float mn0 = fmaxf(mrow0, tm0), mn1 = fmaxf(mrow1, tm1);
        float al0 = __expf(mrow0 - mn0), al1 = __expf(mrow1 - mn1);
        float ts0 = 0.f, ts1 = 0.f;
#pragma unroll
        for (int nt = 0; nt < 4; nt++) {
            s[nt][0] = __expf(s[nt][0] - mn0);
            s[nt][1] = __expf(s[nt][1] - mn0);
            s[nt][2] = __expf(s[nt][2] - mn1);
            s[nt][3] = __expf(s[nt][3] - mn1);
            ts0 += s[nt][0] + s[nt][1];
            ts1 += s[nt][2] + s[nt][3];
        }
        ts0 += __shfl_xor_sync(0xffffffff, ts0, 1);
        ts0 += __shfl_xor_sync(0xffffffff, ts0, 2);
        ts1 += __shfl_xor_sync(0xffffffff, ts1, 1);
        ts1 += __shfl_xor_sync(0xffffffff, ts1, 2);
        lrow0 = lrow0 * al0 + ts0;
        lrow1 = lrow1 * al1 + ts1;
        mrow0 = mn0; mrow1 = mn1;
#pragma unroll
        for (int nt = 0; nt < 16; nt++) {
            o[nt][0] *= al0; o[nt][1] *= al0;
            o[nt][2] *= al1; o[nt][3] *= al1;
        }

        // ---- P fragments (C-frag -> A-frag identity) ----
        uint32_t pfh[2][4], pfl[2][4];
#pragma unroll
        for (int kk = 0; kk < 2; kk++) {
            packsplit(s[2*kk][0],   s[2*kk][1],   pfh[kk][0], pfl[kk][0]);
            packsplit(s[2*kk][2],   s[2*kk][3],   pfh[kk][1], pfl[kk][1]);
            packsplit(s[2*kk+1][0], s[2*kk+1][1], pfh[kk][2], pfl[kk][2]);
            packsplit(s[2*kk+1][2], s[2*kk+1][3], pfh[kk][3], pfl[kk][3]);
        }

        // ---- O += P * V (3-term) ----
#pragma unroll
        for (int kk = 0; kk < 2; kk++) {
#pragma unroll
            for (int ng = 0; ng < 8; ng++) {
                uint32_t vh_[4], vl_[4];
                int r = ng * 16 + (l & 15);
                uint32_t ch = (uint32_t)(2 * kk + (l >> 4));
                uint32_t a = sb + 16384u + (uint32_t)(r * 64) + ((ch ^ (uint32_t)((r >> 1) & 3)) * 16u);
                LDSM4(vh_, a);
                LDSM4(vl_, a + 8192u);
#pragma unroll
                for (int hi = 0; hi < 2; hi++) {
                    MMA16816(o[ng*2+hi], pfh[kk], vh_[hi], vh_[hi + 2]);
                    MMA16816(o[ng*2+hi], pfl[kk], vh_[hi], vh_[hi + 2]);
                    MMA16816(o[ng*2+hi], pfh[kk], vl_[hi], vl_[hi + 2]);
                }
            }
        }
    }

    // ---- normalize + store (EPI3 layout) ----
    float inv0 = 1.f / lrow0, inv1 = 1.f / lrow1;
    int r0 = q0 + w * 16 + (l >> 2);
    int c0 = h * 128 + (l & 3) * 2;
#pragma unroll
    for (int nt = 0; nt < 16; nt++) {
        int gc = c0 + nt * 8;
        float v0 = o[nt][0] * inv0, v1 = o[nt][1] * inv0;
        float v2 = o[nt][2] * inv1, v3 = o[nt][3] * inv1;
        bf16 h0, l0_, h1, l1_;
        split2(v0, h0, l0_); split2(v1, h1, l1_);
        *(__nv_bfloat162*)(outh + (long long)r0 * Dd + gc) = mkbf2(h0, h1);
        *(__nv_bfloat162*)(outl + (long long)r0 * Dd + gc) = mkbf2(l0_, l1_);
        split2(v2, h0, l0_); split2(v3, h1, l1_);
        *(__nv_bfloat162*)(outh + (long long)(r0 + 8) * Dd + gc) = mkbf2(h0, h1);
        *(__nv_bfloat162*)(outl + (long long)(r0 + 8) * Dd + gc) = mkbf2(l0_, l1_);
    }
}

// ---------------------------------------------------------------------------
// Elementwise kernels
// ---------------------------------------------------------------------------
__global__ void k_copy(const float* __restrict__ a, float* __restrict__ o, long long n) {
    long long i = (long long)blockIdx.x * 256 + threadIdx.x;
    if (i < n) o[i] = a[i];
}
__global__ void k_emadd(const float* __restrict__ e, const float* __restrict__ mod,
                        float* __restrict__ em) {
    int i = blockIdx.x * 256 + threadIdx.x;
    if (i < Bb * 6 * Dd) em[i] = e[i] + mod[i % (6 * Dd)];
}
__global__ void k_split4(const float* __restrict__ in, bf16* __restrict__ oh,
                         bf16* __restrict__ ol, long long n) {
    long long i = ((long long)blockIdx.x * 256 + threadIdx.x) * 4;
    if (i >= n) return;
    float4 v = *(const float4*)(in + i);
    bf16 h0, l0, h1, l1;
    split2(v.x, h0, l0); split2(v.y, h1, l1);
    *(__nv_bfloat162*)(oh + i) = mkbf2(h0, h1);
    *(__nv_bfloat162*)(ol + i) = mkbf2(l0, l1);
    split2(v.z, h0, l0); split2(v.w, h1, l1);
    *(__nv_bfloat162*)(oh + i + 2) = mkbf2(h0, h1);
    *(__nv_bfloat162*)(ol + i + 2) = mkbf2(l0, l1);
}
__global__ void k_tsplit(const float* __restrict__ W, bf16* __restrict__ Th,
                         bf16* __restrict__ Tl, int Kd, int Nd) {
    __shared__ float t[32][33];
    int n0 = blockIdx.x * 32, k0 = blockIdx.y * 32;
    int tx = threadIdx.x;
    for (int j = threadIdx.y; j < 32; j += 8)
        t[j][tx] = W[(long long)(k0 + j) * Nd + n0 + tx];
    __syncthreads();
    for (int j = threadIdx.y; j < 16; j += 8) {
        int n  = j * 2 + (tx >> 4);
        int kk = (tx & 15) * 2;
        float v0 = t[kk][n], v1 = t[kk + 1][n];
        long long o = (long long)(n0 + n) * Kd + k0 + kk;
        bf16 h0, l0, h1, l1;
        split2(v0, h0, l0); split2(v1, h1, l1);
        *(__nv_bfloat162*)(Th + o) = mkbf2(h0, h1);
        *(__nv_bfloat162*)(Tl + o) = mkbf2(l0, l1);
    }
}
__global__ void k_tsplit3(const float* __restrict__ w0, const float* __restrict__ w1,
                          const float* __restrict__ w2,
                          bf16* __restrict__ Th, bf16* __restrict__ Tl) {
    __shared__ float t[32][33];
    const float* W = (blockIdx.z == 0) ? w0 : ((blockIdx.z == 1) ? w1 : w2);
    size_t zoff = (size_t)blockIdx.z * Dd * Dd;
    int n0 = blockIdx.x * 32, k0 = blockIdx.y * 32;
    int tx = threadIdx.x;
    for (int j = threadIdx.y; j < 32; j += 8)
        t[j][tx] = W[(long long)(k0 + j) * Dd + n0 + tx];
    __syncthreads();
    for (int j = threadIdx.y; j < 16; j += 8) {
        int n  = j * 2 + (tx >> 4);
        int kk = (tx & 15) * 2;
        float v0 = t[kk][n], v1 = t[kk + 1][n];
        long long o = (long long)zoff + (long long)(n0 + n) * Dd + k0 + kk;
        bf16 h0, l0, h1, l1;
        split2(v0, h0, l0); split2(v1, h1, l1);
        *(__nv_bfloat162*)(Th + o) = mkbf2(h0, h1);
        *(__nv_bfloat162*)(Tl + o) = mkbf2(l0, l1);
    }
}
__global__ void k_ln_mod_split(const float* __restrict__ x, const float* __restrict__ em,
                               bf16* __restrict__ oh, bf16* __restrict__ ol,
                               int scaleRow, int shiftRow) {
    int row = blockIdx.x, t = threadIdx.x;      // per-batch
    const float* xr = x + (long long)row * Dd;
    const float* es = em + (long long)scaleRow * Dd;
    const float* eh = em + (long long)shiftRow * Dd;
    float v[8];
    float4 a0 = *(const float4*)(xr + t * 8);
    float4 a1 = *(const float4*)(xr + t * 8 + 4);
    v[0]=a0.x; v[1]=a0.y; v[2]=a0.z; v[3]=a0.w; v[4]=a1.x; v[5]=a1.y; v[6]=a1.z; v[7]=a1.w;
    float s = 0.f, s2 = 0.f;
#pragma unroll
    for (int i = 0; i < 8; i++) { s += v[i]; s2 += v[i] * v[i]; }
    __shared__ float sh[512];
    sh[t] = s; sh[256 + t] = s2;
    __syncthreads();
    for (int o = 128; o > 0; o >>= 1) {
        if (t < o) { sh[t] += sh[t + o]; sh[256 + t] += sh[256 + t + o]; }
        __syncthreads();
    }
    float m = sh[0] * (1.f / Dd);
    float var = sh[256] * (1.f / Dd) - m * m;
    float r = rsqrtf(var + EPSf);
    bf16 hh[8], ll[8];
#pragma unroll
    for (int i = 0; i < 8; i++) {
        int dI = t * 8 + i;
        float u = (v[i] - m) * r * (1.f + es[dI]) + eh[dI];
        split2(u, hh[i], ll[i]);
    }
    long long ob = (long long)row * Dd + t * 8;
#pragma unroll
    for (int i = 0; i < 8; i += 2) {
        *(__nv_bfloat162*)(oh + ob + i) = mkbf2(hh[i], hh[i + 1]);
        *(__nv_bfloat162*)(ol + ob + i) = mkbf2(ll[i], ll[i + 1]);
    }
}
__global__ void k_rms_rope_split(const float* __restrict__ in, int ldin, int off,
                                 const float* __restrict__ w, const float* __restrict__ freqs,
                                 bf16* __restrict__ oh, bf16* __restrict__ ol, int Sv) {
    int row = blockIdx.x, s = row % Sv, t = threadIdx.x;   // per-batch
    const float* xr = in + (long long)row * ldin + off;
    float v[8];
    float4 a0 = *(const float4*)(xr + t * 8);
    float4 a1 = *(const float4*)(xr + t * 8 + 4);
    v[0]=a0.x; v[1]=a0.y; v[2]=a0.z; v[3]=a0.w; v[4]=a1.x; v[5]=a1.y; v[6]=a1.z; v[7]=a1.w;
    float s2 = 0.f;
#pragma unroll
    for (int i = 0; i < 8; i++) s2 += v[i] * v[i];
    __shared__ float sh[256];
    sh[t] = s2;
    __syncthreads();
    for (int o = 128; o > 0; o >>= 1) {
        if (t < o) sh[t] += sh[t + o];
        __syncthreads();
    }
    float r = rsqrtf(sh[0] * (1.f / Dd) + EPSf);
    int dbase = t * 8, h = dbase >> 7, dd = dbase & 127;
    float u[8];
#pragma unroll
    for (int i = 0; i < 8; i++) u[i] = v[i] * r * w[dbase + i];
    if (freqs) {
#pragma unroll
        for (int pr = 0; pr < 4; pr++) {
            float sn, cs;
            __sincosf(freqs[s * 64 + (dd >> 1) + pr], &sn, &cs);
            float xr_ = u[2 * pr], xi = u[2 * pr + 1];
            u[2 * pr]     = xr_ * cs - xi * sn;
            u[2 * pr + 1] = xr_ * sn + xi * cs;
        }
    }
    long long ob = ((long long)h * Sv + s) * 128 + dd;
    bf16 hh[8], ll[8];
#pragma unroll
    for (int i = 0; i < 8; i++) split2(u[i], hh[i], ll[i]);
#pragma unroll
    for (int i = 0; i < 8; i += 2) {
        *(__nv_bfloat162*)(oh + ob + i) = mkbf2(hh[i], hh[i + 1]);
        *(__nv_bfloat162*)(ol + ob + i) = mkbf2(ll[i], ll[i + 1]);
    }
}
__global__ void k_vt_split(const float* __restrict__ in, int ldin, int off,
                           bf16* __restrict__ oh, bf16* __restrict__ ol, int Sv) {
    __shared__ float t[32][33];
    int h = blockIdx.z;                 // per-batch: z = head
    int s0 = blockIdx.x * 32, d0 = blockIdx.y * 32;
    int tx = threadIdx.x;
    for (int j = threadIdx.y; j < 32; j += 8)
        t[j][tx] = in[(long long)(s0 + j) * ldin + off + h * 128 + d0 + tx];
    __syncthreads();
    for (int j = threadIdx.y; j < 16; j += 8) {
        int d  = j * 2 + (tx >> 4);
        int ss = (tx & 15) * 2;
        float v0 = t[ss][d], v1 = t[ss + 1][d];
        long long o = (long long)(h * 128 + d0 + d) * Sv + s0 + ss;
        bf16 h0, l0, h1, l1;
        split2(v0, h0, l0); split2(v1, h1, l1);
        *(__nv_bfloat162*)(oh + o) = mkbf2(h0, h1);
        *(__nv_bfloat162*)(ol + o) = mkbf2(l0, l1);
    }
}

// ---------------------------------------------------------------------------
// Host orchestration — two per-batch streams (R16) + flash attention
// ---------------------------------------------------------------------------
static void gemm(cudaStream_t st, int epi,
                 const bf16* Ah, const bf16* Al, const bf16* Bh, const bf16* Bl,
                 int M, int N, int K, int lda, int ldb,
                 float* C, bf16* Ch, bf16* Cl, int ldc,
                 const float* b0, const float* b1, const float* b2,
                 const float* em, int gateRow)
{
    dim3 g(N / 128, M / 64, 1), bl(256);
    size_t sm = SMEM_TOTAL_G;
    if (epi == 0)
        mma_gemm<0><<<g, bl, sm, st>>>(Ah, Al, Bh, Bl, K, lda, ldb, C, Ch, Cl, ldc,
                                       b0, b1, b2, em, gateRow, 1, 0, 0, 0, 0, 0, 0);
    else if (epi == 1)
        mma_gemm<1><<<g, bl, sm, st>>>(Ah, Al, Bh, Bl, K, lda, ldb, C, Ch, Cl, ldc,
                                       b0, b1, b2, em, gateRow, 1, 0, 0, 0, 0, 0, 0);
    else
        mma_gemm<2><<<g, bl, sm, st>>>(Ah, Al, Bh, Bl, K, lda, ldb, C, Ch, Cl, ldc,
                                       b0, b1, b2, em, gateRow, 1, 0, 0, 0, 0, 0, 0);
}

#define SYM(p, s) cudaGetSymbolAddress((void**)&p, s)

extern "C" void kernel_launch(void* const* d_in, const int* in_sizes, int n_in,
                              void* d_out, int out_size)
{
    bool sig = (in_sizes[13] == Dd);
    int I_snq, I_snk, I_cq_w, I_cq_b, I_ck_w, I_ck_b, I_cv_w, I_cv_b;
    int I_co_w, I_co_b, I_cnq, I_cnk, I_f1_w, I_f1_b, I_f2_w, I_f2_b;
    if (sig) {
        I_snq=13; I_snk=14; I_cq_w=15; I_cq_b=16; I_ck_w=17; I_ck_b=18;
        I_cv_w=19; I_cv_b=20; I_co_w=21; I_co_b=22; I_cnq=23; I_cnk=24;
        I_f1_w=25; I_f1_b=26; I_f2_w=27; I_f2_b=28;
    } else {
        I_cq_w=13; I_cq_b=14; I_ck_w=15; I_ck_b=16; I_cv_w=17; I_cv_b=18;
        I_co_w=19; I_co_b=20; I_f1_w=21; I_f1_b=22; I_f2_w=23; I_f2_b=24;
        I_snq=25; I_snk=26; I_cnq=27; I_cnk=28;
    }
    const float* x    = (const float*)d_in[0];
    const float* e    = (const float*)d_in[1];
    const float* ctx  = (const float*)d_in[2];
    const float* fr   = (const float*)d_in[3];
    const float* mod  = (const float*)d_in[4];
    const float* sq_w = (const float*)d_in[5];  const float* sq_b = (const float*)d_in[6];
    const float* sk_w = (const float*)d_in[7];  const float* sk_b = (const float*)d_in[8];
    const float* sv_w = (const float*)d_in[9];  const float* sv_b = (const float*)d_in[10];
    const float* so_w = (const float*)d_in[11]; const float* so_b = (const float*)d_in[12];
    const float* snq  = (const float*)d_in[I_snq];  const float* snk  = (const float*)d_in[I_snk];
    const float* cq_w = (const float*)d_in[I_cq_w]; const float* cq_b = (const float*)d_in[I_cq_b];
    const float* ck_w = (const float*)d_in[I_ck_w]; const float* ck_b = (const float*)d_in[I_ck_b];
    const float* cv_w = (const float*)d_in[I_cv_w]; const float* cv_b = (const float*)d_in[I_cv_b];
    const float* co_w = (const float*)d_in[I_co_w]; const float* co_b = (const float*)d_in[I_co_b];
    const float* cnq  = (const float*)d_in[I_cnq];  const float* cnk  = (const float*)d_in[I_cnk];
    const float* f1_w = (const float*)d_in[I_f1_w]; const float* f1_b = (const float*)d_in[I_f1_b];
    const float* f2_w = (const float*)d_in[I_f2_w]; const float* f2_b = (const float*)d_in[I_f2_b];

    cudaFuncSetAttribute(mma_gemm<0>, cudaFuncAttributeMaxDynamicSharedMemorySize, SMEM_TOTAL_G);
    cudaFuncSetAttribute(mma_gemm<1>, cudaFuncAttributeMaxDynamicSharedMemorySize, SMEM_TOTAL_G);
    cudaFuncSetAttribute(mma_gemm<2>, cudaFuncAttributeMaxDynamicSharedMemorySize, SMEM_TOTAL_G);
    cudaFuncSetAttribute(flash_attn,  cudaFuncAttributeMaxDynamicSharedMemorySize, FA_SMEM);

    static cudaStream_t stm[2] = {nullptr, nullptr};
    static cudaEvent_t evF = nullptr, evJ0 = nullptr, evJ1 = nullptr;
    if (stm[0] == nullptr) {
        cudaStreamCreateWithFlags(&stm[0], cudaStreamNonBlocking);
        cudaStreamCreateWithFlags(&stm[1], cudaStreamNonBlocking);
        cudaEventCreateWithFlags(&evF,  cudaEventDisableTiming);
        cudaEventCreateWithFlags(&evJ0, cudaEventDisableTiming);
        cudaEventCreateWithFlags(&evJ1, cudaEventDisableTiming);
    }

    float *em_, *qkv;
    SYM(em_, g_em); SYM(qkv, g_qkv);
    bf16 *txh, *txl, *cxh, *cxl, *qh, *ql, *kh, *kl, *vth, *vtl;
    bf16 *ckh, *ckl, *cvth, *cvtl, *fh, *fl;
    SYM(txh, g_txh); SYM(txl, g_txl); SYM(cxh, g_cxh); SYM(cxl, g_cxl);
    SYM(qh, g_qh); SYM(ql, g_ql); SYM(kh, g_kh); SYM(kl, g_kl);
    SYM(vth, g_vth); SYM(vtl, g_vtl);
    SYM(ckh, g_ckh); SYM(ckl, g_ckl); SYM(cvth, g_cvth); SYM(cvtl, g_cvtl);
    SYM(fh, g_fh); SYM(fl, g_fl);
    bf16 *wqkvh, *wqkvl, *wckvh, *wckvl, *woh, *wol, *wcqh, *wcql, *wcoh, *wcol, *wf1h, *wf1l, *wf2h, *wf2l;
    SYM(wqkvh, g_wqkvh); SYM(wqkvl, g_wqkvl); SYM(wckvh, g_wckvh); SYM(wckvl, g_wckvl);
    SYM(woh, g_woh); SYM(wol, g_wol); SYM(wcqh, g_wcqh); SYM(wcql, g_wcql);
    SYM(wcoh, g_wcoh); SYM(wcol, g_wcol); SYM(wf1h, g_wf1h); SYM(wf1l, g_wf1l);
    SYM(wf2h, g_wf2h); SYM(wf2l, g_wf2l);

    float* xo = (float*)d_out;
    const long long DD = (long long)Dd * Dd;
    const long long SD = (long long)Ss * Dd;
    const long long LD = (long long)LCc * Dd;
    dim3 tb(32, 8);

    // ---------------- shared weight prep on root stream ----------------
    k_emadd<<<(Bb * 6 * Dd + 255) / 256, 256>>>(e, mod, em_);
    k_tsplit3<<<dim3(Dd/32, Dd/32, 3), tb>>>(sq_w, sk_w, sv_w, wqkvh, wqkvl);
    k_tsplit<<<dim3(Dd/32, Dd/32), tb>>>(so_w, woh,  wol,  Dd, Dd);
    k_tsplit<<<dim3(Dd/32, Dd/32), tb>>>(cq_w, wcqh, wcql, Dd, Dd);
    k_tsplit<<<dim3(Dd/32, Dd/32), tb>>>(ck_w, wckvh,      wckvl,      Dd, Dd);
    k_tsplit<<<dim3(Dd/32, Dd/32), tb>>>(cv_w, wckvh + DD, wckvl + DD, Dd, Dd);
    k_tsplit<<<dim3(Dd/32, Dd/32), tb>>>(co_w, wcoh, wcol, Dd, Dd);
    k_tsplit<<<dim3(Ff/32, Dd/32), tb>>>(f1_w, wf1h, wf1l, Dd, Ff);
    k_tsplit<<<dim3(Dd/32, Ff/32), tb>>>(f2_w, wf2h, wf2l, Ff, Dd);
    cudaEventRecord(evF, 0);

    for (int b = 0; b < Bb; b++) {
        cudaStream_t st = stm[b];
        cudaStreamWaitEvent(st, evF, 0);

        const float* xb  = x   + (long long)b * SD;
        float*       xob = xo  + (long long)b * SD;
        const float* emb = em_ + (long long)b * 6 * Dd;
        float* qkvb = qkv + (long long)b * Ss * 3 * Dd;
        bf16 *txhb = txh + b*SD,  *txlb = txl + b*SD;
        bf16 *qhb  = qh  + b*SD,  *qlb  = ql  + b*SD;
        bf16 *khb  = kh  + b*SD,  *klb  = kl  + b*SD;
        bf16 *vthb = vth + b*SD,  *vtlb = vtl + b*SD;
        bf16 *ckhb = ckh + b*LD,  *cklb = ckl + b*LD;
        bf16 *cvthb= cvth+ b*LD,  *cvtlb= cvtl+ b*LD;
        bf16 *cxhb = cxh + b*LD,  *cxlb = cxl + b*LD;
        bf16 *fhb = fh + (long long)b*Ss*Ff, *flb = fl + (long long)b*Ss*Ff;
        const float* ctxb = ctx + (long long)b * LD;

        // self attention
        k_copy<<<(int)((SD + 255) / 256), 256, 0, st>>>(xb, xob, SD);
        k_ln_mod_split<<<Ss, 256, 0, st>>>(xb, emb, txhb, txlb, 1, 0);
        gemm(st, 0, txhb, txlb, wqkvh, wqkvl, Ss, 3*Dd, Dd, Dd, Dd,
             qkvb, nullptr, nullptr, 3*Dd, sq_b, sk_b, sv_b, nullptr, -1);
        k_rms_rope_split<<<Ss, 256, 0, st>>>(qkvb, 3*Dd, 0,  snq, fr, qhb, qlb, Ss);
        k_rms_rope_split<<<Ss, 256, 0, st>>>(qkvb, 3*Dd, Dd, snk, fr, khb, klb, Ss);
        k_vt_split<<<dim3(Ss/32, 4, Hh), tb, 0, st>>>(qkvb, 3*Dd, 2*Dd, vthb, vtlb, Ss);
        flash_attn<<<dim3(Ss/64, Hh), 128, FA_SMEM, st>>>(
            qhb, qlb, khb, klb, vthb, vtlb, txhb, txlb, Ss, Ss);
        gemm(st, 2, txhb, txlb, woh, wol, Ss, Dd, Dd, Dd, Dd,
             xob, nullptr, nullptr, Dd, so_b, nullptr, nullptr, emb, 2);

        // cross attention
        k_split4<<<(int)(SD / 1024), 256, 0, st>>>(xob, txhb, txlb, SD);
        gemm(st, 0, txhb, txlb, wcqh, wcql, Ss, Dd, Dd, Dd, Dd,
             qkvb, nullptr, nullptr, Dd, cq_b, nullptr, nullptr, nullptr, -1);
        k_rms_rope_split<<<Ss, 256, 0, st>>>(qkvb, Dd, 0, cnq, nullptr, qhb, qlb, Ss);
        k_split4<<<(int)(LD / 1024), 256, 0, st>>>(ctxb, cxhb, cxlb, LD);
        gemm(st, 0, cxhb, cxlb, wckvh, wckvl, LCc, 2*Dd, Dd, Dd, Dd,
             qkvb, nullptr, nullptr, 2*Dd, ck_b, cv_b, nullptr, nullptr, -1);
        k_rms_rope_split<<<LCc, 256, 0, st>>>(qkvb, 2*Dd, 0, cnk, nullptr, ckhb, cklb, LCc);
        k_vt_split<<<dim3(LCc/32, 4, Hh), tb, 0, st>>>(qkvb, 2*Dd, Dd, cvthb, cvtlb, LCc);
        flash_attn<<<dim3(Ss/64, Hh), 128, FA_SMEM, st>>>(
            qhb, qlb, ckhb, cklb, cvthb, cvtlb, txhb, txlb, Ss, LCc);
        gemm(st, 2, txhb, txlb, wcoh, wcol, Ss, Dd, Dd, Dd, Dd,
             xob, nullptr, nullptr, Dd, co_b, nullptr, nullptr, emb, -1);

        // FFN
        k_ln_mod_split<<<Ss, 256, 0, st>>>(xob, emb, txhb, txlb, 4, 3);
        gemm(st, 1, txhb, txlb, wf1h, wf1l, Ss, Ff, Dd, Dd, Dd,
             nullptr, fhb, flb, Ff, f1_b, nullptr, nullptr, nullptr, -1);
        gemm(st, 2, fhb, flb, wf2h, wf2l, Ss, Dd, Ff, Ff, Ff,
             xob, nullptr, nullptr, Dd, f2_b, nullptr, nullptr, emb, 5);

        cudaEventRecord(b == 0 ? evJ0 : evJ1, st);
    }

    cudaStreamWaitEvent(0, evJ0, 0);
    cudaStreamWaitEvent(0, evJ1, 0);
}